// round 9
// baseline (speedup 1.0000x reference)
#include <cuda_runtime.h>
#include <math.h>

#define BB 8
#define SS 1024
#define DD 512
#define HD 64
#define NROWS (BB*SS)
#define EPSV 1e-5f
#define SCP 1036
#define KVW 4352     // words per KV buffer (64 rows x 68)

// ---------------- scratch ----------------
__device__ float g_Qp[NROWS*DD];   // tf32 bits, [s][d]
__device__ float g_Kp[NROWS*DD];   // tf32 bits, [s][d]
__device__ float g_Vt[NROWS*DD];   // tf32 bits, TRANSPOSED: [bh][d][s]
__device__ float g_ao[NROWS*DD];   // exact fp32
__device__ float g_Qn[NROWS*DD];   // normed Q, tf32 bits
__device__ float g_aon[NROWS*DD];  // normed ao, tf32 bits
__device__ float g_Wt[4*DD*DD];    // tf32 weights TRANSPOSED: [n][k]
__device__ float g_sum1[BB], g_sq1[BB], g_sum2[BB], g_sq2[BB];
__device__ int   g_cnt[BB];
__device__ int   g_mask[NROWS];

// ---------------- helpers ----------------
__device__ __forceinline__ unsigned f2tf(float x) {
    unsigned r; asm("cvt.rna.tf32.f32 %0, %1;" : "=r"(r) : "f"(x)); return r;
}
__device__ __forceinline__ void mma8(float* c, unsigned a0, unsigned a1, unsigned a2, unsigned a3,
                                     unsigned b0, unsigned b1) {
    asm volatile(
        "mma.sync.aligned.m16n8k8.row.col.f32.tf32.tf32.f32 "
        "{%0,%1,%2,%3},{%4,%5,%6,%7},{%8,%9},{%0,%1,%2,%3};"
        : "+f"(c[0]), "+f"(c[1]), "+f"(c[2]), "+f"(c[3])
        : "r"(a0), "r"(a1), "r"(a2), "r"(a3), "r"(b0), "r"(b1));
}
__device__ __forceinline__ void ldsm4(unsigned addr, unsigned& r0, unsigned& r1,
                                      unsigned& r2, unsigned& r3) {
    asm volatile("ldmatrix.sync.aligned.m8n8.x4.shared.b16 {%0,%1,%2,%3}, [%4];"
                 : "=r"(r0), "=r"(r1), "=r"(r2), "=r"(r3) : "r"(addr));
}
__device__ __forceinline__ unsigned cvta_s(const void* p) {
    return (unsigned)__cvta_generic_to_shared(p);
}
#define CP16(dst_u32, src_ptr) \
    asm volatile("cp.async.cg.shared.global [%0], [%1], 16;" :: "r"(dst_u32), "l"(src_ptr))
#define CP_COMMIT() asm volatile("cp.async.commit_group;")
#define CP_WAIT2()  asm volatile("cp.async.wait_group 2;")
#define CP_WAIT0()  asm volatile("cp.async.wait_group 0;")

// ---------------- tiny kernels ----------------
__global__ void k_cvtW(const float* __restrict__ Wq, const float* __restrict__ Wk,
                       const float* __restrict__ Wv, const float* __restrict__ Wo) {
    if (blockIdx.x == 0 && blockIdx.y == 0 && blockIdx.z == 0 && threadIdx.x < BB) {
        int t = threadIdx.x;
        g_sum1[t]=0.f; g_sq1[t]=0.f; g_sum2[t]=0.f; g_sq2[t]=0.f; g_cnt[t]=0;
    }
    __shared__ float t[32][33];
    const float* src = (blockIdx.z == 0) ? Wq : (blockIdx.z == 1) ? Wk :
                       (blockIdx.z == 2) ? Wv : Wo;
    float* dst = g_Wt + (size_t)blockIdx.z * DD * DD;
    int k0 = blockIdx.x * 32, n0 = blockIdx.y * 32;
    int c = threadIdx.x & 31, r0 = threadIdx.x >> 5;
    #pragma unroll
    for (int i = 0; i < 4; i++) {
        int r = r0 + 8 * i;
        t[r][c] = src[(size_t)(k0 + r) * DD + n0 + c];
    }
    __syncthreads();
    #pragma unroll
    for (int i = 0; i < 4; i++) {
        int r = r0 + 8 * i;
        ((unsigned*)dst)[(size_t)(n0 + r) * DD + k0 + c] = f2tf(t[c][r]);
    }
}

__global__ void k_maskstats(const float* __restrict__ Q) {
    int row = blockIdx.x;
    int t = threadIdx.x;
    float4 q = ((const float4*)(Q + (size_t)row * DD))[t];
    bool nz = (q.x != 0.f) || (q.y != 0.f) || (q.z != 0.f) || (q.w != 0.f);
    float s  = q.x + q.y + q.z + q.w;
    float s2 = q.x*q.x + q.y*q.y + q.z*q.z + q.w*q.w;
    int valid = __syncthreads_or(nz ? 1 : 0);
    #pragma unroll
    for (int o = 16; o > 0; o >>= 1) {
        s  += __shfl_xor_sync(0xffffffffu, s,  o);
        s2 += __shfl_xor_sync(0xffffffffu, s2, o);
    }
    __shared__ float rs[4], rs2[4];
    if ((t & 31) == 0) { rs[t >> 5] = s; rs2[t >> 5] = s2; }
    __syncthreads();
    if (t == 0) {
        g_mask[row] = valid;
        if (valid) {
            int b = row >> 10;
            atomicAdd(&g_cnt[b], 1);
            atomicAdd(&g_sum1[b], rs[0]+rs[1]+rs[2]+rs[3]);
            atomicAdd(&g_sq1[b],  rs2[0]+rs2[1]+rs2[2]+rs2[3]);
        }
    }
}

__global__ void k_norm(const float* __restrict__ src, float* __restrict__ dst, int which) {
    int row = blockIdx.x;
    int t = threadIdx.x;
    int b = row >> 10;
    float cntD = (float)g_cnt[b] * (float)DD;
    float sum = which ? g_sum2[b] : g_sum1[b];
    float sq  = which ? g_sq2[b]  : g_sq1[b];
    float mean = (cntD > 0.f) ? sum / cntD : 0.f;
    float var  = (cntD > 0.f) ? sq / cntD - mean * mean : 0.f;
    if (var < 0.f) var = 0.f;
    float rstd = rsqrtf(var + EPSV);
    float sc = g_mask[row] ? rstd : 0.f;
    float mm = mean * sc;
    float4 v = ((const float4*)(src + (size_t)row * DD))[t];
    uint4 u;
    u.x = f2tf(fmaf(v.x, sc, -mm)); u.y = f2tf(fmaf(v.y, sc, -mm));
    u.z = f2tf(fmaf(v.z, sc, -mm)); u.w = f2tf(fmaf(v.w, sc, -mm));
    ((uint4*)(dst + (size_t)row * DD))[t] = u;
}

// ============ tf32 GEMM body: BM=128, BN=128, BK=32; 8 warps (4m x 2n), warp 32x64 ============
struct GemmOut { float c[2][8][4]; };

__device__ __forceinline__ void gemm_body(
    const float* __restrict__ Asrc, const float* __restrict__ Bsrc,
    int m0, int n0, float* smq, GemmOut& R)
{
    float* As0 = smq;               // 128*36
    float* As1 = smq + 4608;
    float* Bs0 = smq + 9216;        // 128*36
    float* Bs1 = smq + 13824;

    int tid = threadIdx.x;
    int wid = tid >> 5, lane = tid & 31;
    int wm = wid >> 1, wn = wid & 1;
    int m2 = lane >> 3, r8 = lane & 7;

    unsigned uA0 = cvta_s(As0), uA1 = cvta_s(As1);
    unsigned uB0 = cvta_s(Bs0), uB1 = cvta_s(Bs1);

    int rowA0 = (wm * 32 +      (m2 & 1) * 8 + r8) * 36 + (m2 >> 1) * 4;
    int rowA1 = rowA0 + 16 * 36;
    int rowB[4];
    #pragma unroll
    for (int nq = 0; nq < 4; nq++)
        rowB[nq] = (wn * 64 + nq * 16 + (m2 >> 1) * 8 + r8) * 36 + (m2 & 1) * 4;

    int arow = tid >> 3, c8 = tid & 7;

    #pragma unroll
    for (int mi = 0; mi < 2; mi++)
        #pragma unroll
        for (int ni = 0; ni < 8; ni++)
            #pragma unroll
            for (int j = 0; j < 4; j++) R.c[mi][ni][j] = 0.f;

    // prologue: chunk 0
    #pragma unroll
    for (int i = 0; i < 4; i++) {
        int row = arow + 32 * i;
        CP16(uA0 + (row * 36 + c8 * 4) * 4, Asrc + (size_t)(m0 + row) * 512 + c8 * 4);
        CP16(uB0 + (row * 36 + c8 * 4) * 4, Bsrc + (size_t)(n0 + row) * 512 + c8 * 4);
    }
    CP_COMMIT();

    for (int kc = 0; kc < 16; kc++) {
        CP_WAIT0();
        __syncthreads();
        if (kc < 15) {
            unsigned nA = (kc & 1) ? uA0 : uA1;
            unsigned nB = (kc & 1) ? uB0 : uB1;
            int k0 = (kc + 1) * 32;
            #pragma unroll
            for (int i = 0; i < 4; i++) {
                int row = arow + 32 * i;
                CP16(nA + (row * 36 + c8 * 4) * 4, Asrc + (size_t)(m0 + row) * 512 + k0 + c8 * 4);
                CP16(nB + (row * 36 + c8 * 4) * 4, Bsrc + (size_t)(n0 + row) * 512 + k0 + c8 * 4);
            }
        }
        CP_COMMIT();

        unsigned uAf = (kc & 1) ? uA1 : uA0;
        unsigned uBf = (kc & 1) ? uB1 : uB0;
        #pragma unroll
        for (int s = 0; s < 4; s++) {
            unsigned a[2][4], bb[8][2];
            ldsm4(uAf + (rowA0 + s * 8) * 4, a[0][0], a[0][1], a[0][2], a[0][3]);
            ldsm4(uAf + (rowA1 + s * 8) * 4, a[1][0], a[1][1], a[1][2], a[1][3]);
            #pragma unroll
            for (int nq = 0; nq < 4; nq++)
                ldsm4(uBf + (rowB[nq] + s * 8) * 4,
                      bb[nq*2][0], bb[nq*2][1], bb[nq*2+1][0], bb[nq*2+1][1]);
            #pragma unroll
            for (int mi = 0; mi < 2; mi++)
                #pragma unroll
                for (int ni = 0; ni < 8; ni++)
                    mma8(R.c[mi][ni], a[mi][0], a[mi][1], a[mi][2], a[mi][3],
                         bb[ni][0], bb[ni][1]);
        }
    }
}

// ---------------- QKV ----------------
__global__ __launch_bounds__(256, 2)
void k_qkv(const float* __restrict__ bq, const float* __restrict__ bk,
           const float* __restrict__ bv) {
    extern __shared__ float smq[];
    int z = blockIdx.z;
    const float* bias = (z == 0) ? bq : (z == 1) ? bk : bv;
    const float* Bsrc = g_Wt + (size_t)z * DD * DD;

    int n0 = blockIdx.x * 128, m0 = blockIdx.y * 128;
    int tid = threadIdx.x;
    int wid = tid >> 5, lane = tid & 31, g = lane >> 2, tig = lane & 3;
    int wm = wid >> 1, wn = wid & 1;

    GemmOut R;
    gemm_body(g_Qn, Bsrc, m0, n0, smq, R);

    if (z < 2) {
        float* outp = (z == 0) ? g_Qp : g_Kp;
        #pragma unroll
        for (int mi = 0; mi < 2; mi++) {
            int r0 = m0 + wm * 32 + mi * 16 + g;
            float mk0 = g_mask[r0]     ? 1.f : 0.f;
            float mk1 = g_mask[r0 + 8] ? 1.f : 0.f;
            #pragma unroll
            for (int ni = 0; ni < 8; ni++) {
                int col = n0 + wn * 64 + ni * 8 + tig * 2;
                float b0v = bias[col], b1v = bias[col + 1];
                uint2 o0 = make_uint2(f2tf((R.c[mi][ni][0] + b0v) * mk0),
                                      f2tf((R.c[mi][ni][1] + b1v) * mk0));
                uint2 o1 = make_uint2(f2tf((R.c[mi][ni][2] + b0v) * mk1),
                                      f2tf((R.c[mi][ni][3] + b1v) * mk1));
                *(uint2*)(outp + (size_t)r0 * 512 + col)       = o0;
                *(uint2*)(outp + (size_t)(r0 + 8) * 512 + col) = o1;
            }
        }
    } else {
        #pragma unroll
        for (int mi = 0; mi < 2; mi++) {
            int r0 = m0 + wm * 32 + mi * 16 + g;
            int bidx = r0 >> 10, s_ = r0 & 1023;
            float mk0 = g_mask[r0]     ? 1.f : 0.f;
            float mk1 = g_mask[r0 + 8] ? 1.f : 0.f;
            #pragma unroll
            for (int ni = 0; ni < 8; ni++) {
                int col = n0 + wn * 64 + ni * 8 + tig * 2;
                int h_ = col >> 6, dl = col & 63;
                float b0v = bias[col], b1v = bias[col + 1];
                unsigned* vt0 = (unsigned*)g_Vt + (((size_t)(bidx * 8 + h_) * 64 + dl) << 10);
                unsigned* vt1 = vt0 + 1024;
                vt0[s_]     = f2tf((R.c[mi][ni][0] + b0v) * mk0);
                vt1[s_]     = f2tf((R.c[mi][ni][1] + b1v) * mk0);
                vt0[s_ + 8] = f2tf((R.c[mi][ni][2] + b0v) * mk1);
                vt1[s_ + 8] = f2tf((R.c[mi][ni][3] + b1v) * mk1);
            }
        }
    }
}

// ---------------- output GEMM ----------------
__global__ __launch_bounds__(256, 2)
void k_out(const float* __restrict__ bo, float* __restrict__ out) {
    extern __shared__ float smq[];
    int n0 = blockIdx.x * 128, m0 = blockIdx.y * 128;
    int tid = threadIdx.x;
    int wid = tid >> 5, lane = tid & 31, g = lane >> 2, tig = lane & 3;
    int wm = wid >> 1, wn = wid & 1;

    GemmOut R;
    gemm_body(g_aon, g_Wt + (size_t)3 * DD * DD, m0, n0, smq, R);

    #pragma unroll
    for (int mi = 0; mi < 2; mi++) {
        int r0 = m0 + wm * 32 + mi * 16 + g;
        #pragma unroll
        for (int ni = 0; ni < 8; ni++) {
            int col = n0 + wn * 64 + ni * 8 + tig * 2;
            float b0v = bo[col], b1v = bo[col + 1];
            float2 a0 = *(const float2*)(g_ao + (size_t)r0 * 512 + col);
            float2 a1 = *(const float2*)(g_ao + (size_t)(r0 + 8) * 512 + col);
            float2 o0 = make_float2(a0.x + fmaxf(R.c[mi][ni][0] + b0v, 0.f),
                                    a0.y + fmaxf(R.c[mi][ni][1] + b1v, 0.f));
            float2 o1 = make_float2(a1.x + fmaxf(R.c[mi][ni][2] + b0v, 0.f),
                                    a1.y + fmaxf(R.c[mi][ni][3] + b1v, 0.f));
            *(float2*)(out + (size_t)r0 * 512 + col)       = o0;
            *(float2*)(out + (size_t)(r0 + 8) * 512 + col) = o1;
        }
    }
}

// ---------------- attention: fused exp + register rowsums ----------------
__global__ __launch_bounds__(512)
void k_attn(const float* __restrict__ Q, float* __restrict__ w_out) {
    extern __shared__ float sm[];
    float*    sc   = sm;                            // 32*1036
    unsigned* scU  = (unsigned*)sc;
    float*    kvb  = sm + 32 * SCP;                 // 4 * KVW
    unsigned* qs   = (unsigned*)(kvb + 4 * KVW);    // 32*68
    float*    red  = (float*)(qs + 32 * 68);        // 32
    float*    part = red + 32;                      // 32*8 rowsum partials

    int tid = threadIdx.x;
    int wid = tid >> 5, lane = tid & 31, g = lane >> 2, tig = lane & 3;
    int m2 = lane >> 3, r8 = lane & 7;
    int bh = blockIdx.y, b = bh >> 3, h = bh & 7;
    int q0 = blockIdx.x * 32;
    size_t baseQ = ((size_t)b * SS + q0) * DD + h * HD;
    size_t baseK = ((size_t)b * SS) * DD + h * HD;
    size_t baseVt = (size_t)bh * HD * SS;
    const int bS = b * SS;

    unsigned uKV[4];
    #pragma unroll
    for (int i = 0; i < 4; i++) uKV[i] = cvta_s(kvb + i * KVW);
    unsigned uQS = cvta_s(qs), uSC = cvta_s(sc);

    int lc4 = tid & 15;

    // K prologue: chunks 0..2 (64 keys each)
    #pragma unroll
    for (int p = 0; p < 3; p++) {
        #pragma unroll
        for (int i = 0; i < 2; i++) {
            int f = tid + 512 * i;
            int row = f >> 4, c4 = f & 15;
            CP16(uKV[p] + (row * 68 + c4 * 4) * 4,
                 g_Kp + baseK + (size_t)(p * 64 + row) * DD + c4 * 4);
        }
        CP_COMMIT();
    }

    // q tile -> smem (already tf32 bits)
    {
        int r = tid >> 4, c4 = tid & 15;
        *(uint4*)&qs[r * 68 + c4 * 4] =
            *(const uint4*)(g_Qp + baseQ + (size_t)r * DD + c4 * 4);
    }
    __syncthreads();

    // preload Q fragments (per warp: m16 x k64)
    int nslot = wid >> 1, mh = wid & 1;
    unsigned areg[8][4];
    {
        int rowQ = (mh * 16 + (m2 & 1) * 8 + r8) * 68 + (m2 >> 1) * 4;
        #pragma unroll
        for (int s = 0; s < 8; s++)
            ldsm4(uQS + (rowQ + s * 8) * 4, areg[s][0], areg[s][1], areg[s][2], areg[s][3]);
    }

    // ---- scores: 16 chunks of 64 keys; warp = m16 x n8; fused exp + rowsums ----
    float rs0 = 0.f, rs1 = 0.f;    // softmax rowsum partials for rows (mh*16+g), +8
    int rowKB = (nslot * 8 + r8) * 68 + m2 * 4;
    for (int kt = 0; kt < 16; kt++) {
        CP_WAIT2();
        __syncthreads();
        if (kt + 3 < 16) {
            unsigned nxt = uKV[(kt + 3) & 3];
            #pragma unroll
            for (int i = 0; i < 2; i++) {
                int f = tid + 512 * i;
                int row = f >> 4, c4 = f & 15;
                CP16(nxt + (row * 68 + c4 * 4) * 4,
                     g_Kp + baseK + (size_t)((kt + 3) * 64 + row) * DD + c4 * 4);
            }
        }
        CP_COMMIT();

        unsigned uKVf = uKV[kt & 3];
        float cc[4] = {0.f, 0.f, 0.f, 0.f};
        #pragma unroll
        for (int s16 = 0; s16 < 4; s16++) {
            unsigned b0, b1, b2, b3;
            ldsm4(uKVf + (rowKB + s16 * 16) * 4, b0, b1, b2, b3);
            mma8(cc, areg[2*s16][0],   areg[2*s16][1],   areg[2*s16][2],   areg[2*s16][3],   b0, b1);
            mma8(cc, areg[2*s16+1][0], areg[2*s16+1][1], areg[2*s16+1][2], areg[2*s16+1][3], b2, b3);
        }
        int gc = kt * 64 + nslot * 8 + tig * 2;
        bool k0v = g_mask[bS + gc] != 0;
        bool k1v = g_mask[bS + gc + 1] != 0;
        float p0 = k0v ? __expf(cc[0] * 0.125f) : 0.f;
        float p1 = k1v ? __expf(cc[1] * 0.125f) : 0.f;
        float p2 = k0v ? __expf(cc[2] * 0.125f) : 0.f;
        float p3 = k1v ? __expf(cc[3] * 0.125f) : 0.f;
        rs0 += p0 + p1;
        rs1 += p2 + p3;
        int r = mh * 16 + g;
        *(float2*)&sc[r * SCP + gc]       = make_float2(p0, p1);
        *(float2*)&sc[(r + 8) * SCP + gc] = make_float2(p2, p3);
    }

    // reduce rowsums over tig (lanes g*4+tig) and publish partials
    rs0 += __shfl_xor_sync(0xffffffffu, rs0, 1);
    rs0 += __shfl_xor_sync(0xffffffffu, rs0, 2);
    rs1 += __shfl_xor_sync(0xffffffffu, rs1, 1);
    rs1 += __shfl_xor_sync(0xffffffffu, rs1, 2);
    if (tig == 0) {
        int r = mh * 16 + g;
        part[r * 8 + nslot]       = rs0;
        part[(r + 8) * 8 + nslot] = rs1;
    }

    // V^T prologue: chunks 0..2 (64 d-rows x 64 s-words each)
    #pragma unroll
    for (int p = 0; p < 3; p++) {
        #pragma unroll
        for (int i = 0; i < 2; i++) {
            int f = tid + 512 * i;
            int row = f >> 4, c4 = f & 15;
            CP16(uKV[p] + (row * 68 + c4 * 4) * 4,
                 g_Vt + baseVt + (size_t)row * SS + p * 64 + c4 * 4);
        }
        CP_COMMIT();
    }
    __syncthreads();   // panel p-values + part[] visible

    // ---- single softmax-scale pass: scale + w-write + tf32 convert ----
    {
        int row = tid >> 4, l = tid & 15;
        const float* pr = part + row * 8;
        float sum = pr[0] + pr[1] + pr[2] + pr[3] + pr[4] + pr[5] + pr[6] + pr[7];
        float inv = g_mask[bS + q0 + row] ? (1.0f / sum) : 0.f;

        float* srow = sc + row * SCP;
        float* wrow = w_out + ((size_t)bh * SS + q0 + row) * SS;
        unsigned* urow = scU + row * SCP;
        #pragma unroll
        for (int j = 0; j < 16; j++) {
            int c = (l + 16 * j) * 4;
            float4 v = *(float4*)&srow[c];
            v.x *= inv; v.y *= inv; v.z *= inv; v.w *= inv;
            *(float4*)(wrow + c) = v;
            uint4 u; u.x = f2tf(v.x); u.y = f2tf(v.y); u.z = f2tf(v.z); u.w = f2tf(v.w);
            *(uint4*)&urow[c] = u;
        }
    }
    __syncthreads();

    // ---- attnV: 16 chunks of 64 s; 16 warps = 8 k-splits x 2 n-slots ----
    int ksl = wid & 7, nsl = wid >> 3;
    int rowPA0 = (     (m2 & 1) * 8 + r8) * SCP + (m2 >> 1) * 4;
    int rowPA1 = (16 + (m2 & 1) * 8 + r8) * SCP + (m2 >> 1) * 4;
    int rowVB0 = (nsl * 32 +      (m2 >> 1) * 8 + r8) * 68 + (m2 & 1) * 4;
    int rowVB1 = (nsl * 32 + 16 + (m2 >> 1) * 8 + r8) * 68 + (m2 & 1) * 4;

    float acc[2][4][4];
    #pragma unroll
    for (int mi = 0; mi < 2; mi++)
        #pragma unroll
        for (int nf = 0; nf < 4; nf++)
            #pragma unroll
            for (int j = 0; j < 4; j++) acc[mi][nf][j] = 0.f;

    for (int vt = 0; vt < 16; vt++) {
        CP_WAIT2();
        __syncthreads();
        if (vt + 3 < 16) {
            unsigned nxt = uKV[(vt + 3) & 3];
            #pragma unroll
            for (int i = 0; i < 2; i++) {
                int f = tid + 512 * i;
                int row = f >> 4, c4 = f & 15;
                CP16(nxt + (row * 68 + c4 * 4) * 4,
                     g_Vt + baseVt + (size_t)row * SS + (vt + 3) * 64 + c4 * 4);
            }
        }
        CP_COMMIT();

        unsigned uKVf = uKV[vt & 3];
        int kk = vt * 64 + ksl * 8;
        int kl = ksl * 8;
        unsigned a[2][4], bb[4][2];
        ldsm4(uSC + (rowPA0 + kk) * 4, a[0][0], a[0][1], a[0][2], a[0][3]);
        ldsm4(uSC + (rowPA1 + kk) * 4, a[1][0], a[1][1], a[1][2], a[1][3]);
        ldsm4(uKVf + (rowVB0 + kl) * 4, bb[0][0], bb[0][1], bb[1][0], bb[1][1]);
        ldsm4(uKVf + (rowVB1 + kl) * 4, bb[2][0], bb[2][1], bb[3][0], bb[3][1]);
        #pragma unroll
        for (int nf = 0; nf < 4; nf++) {
            mma8(acc[0][nf], a[0][0], a[0][1], a[0][2], a[0][3], bb[nf][0], bb[nf][1]);
            mma8(acc[1][nf], a[1][0], a[1][1], a[1][2], a[1][3], bb[nf][0], bb[nf][1]);
        }
    }
    __syncthreads();

    // ---- reduce 8 k-splits via kvb (8 regions of 32x68) ----
    float* at = kvb;
    #pragma unroll
    for (int mi = 0; mi < 2; mi++) {
        int r = mi * 16 + g;
        #pragma unroll
        for (int nf = 0; nf < 4; nf++) {
            int col = nsl * 32 + nf * 8 + tig * 2;
            *(float2*)&at[ksl * 2176 + r * 68 + col]       = make_float2(acc[mi][nf][0], acc[mi][nf][1]);
            *(float2*)&at[ksl * 2176 + (r + 8) * 68 + col] = make_float2(acc[mi][nf][2], acc[mi][nf][3]);
        }
    }
    __syncthreads();

    // ---- epilogue: attn_out = attn + Q; stats2 ----
    {
        int lr = tid >> 4;
        float4 o = make_float4(0.f, 0.f, 0.f, 0.f);
        #pragma unroll
        for (int k = 0; k < 8; k++) {
            float4 p = *(const float4*)&at[k * 2176 + lr * 68 + lc4 * 4];
            o.x += p.x; o.y += p.y; o.z += p.z; o.w += p.w;
        }
        size_t gaddr = baseQ + (size_t)lr * DD + lc4 * 4;
        float4 q4 = *(const float4*)(Q + gaddr);
        o.x += q4.x; o.y += q4.y; o.z += q4.z; o.w += q4.w;
        *(float4*)(g_ao + gaddr) = o;
        float t1 = o.x + o.y + o.z + o.w;
        float t2 = o.x*o.x + o.y*o.y + o.z*o.z + o.w*o.w;
        #pragma unroll
        for (int off = 16; off > 0; off >>= 1) {
            t1 += __shfl_xor_sync(0xffffffffu, t1, off);
            t2 += __shfl_xor_sync(0xffffffffu, t2, off);
        }
        if (lane == 0) { red[wid] = t1; red[16 + wid] = t2; }
    }
    __syncthreads();
    if (tid == 0) {
        float S1 = 0.f, S2 = 0.f;
        #pragma unroll
        for (int i = 0; i < 16; i++) { S1 += red[i]; S2 += red[16 + i]; }
        atomicAdd(&g_sum2[b], S1);
        atomicAdd(&g_sq2[b], S2);
    }
}

// ---------------- launch ----------------
extern "C" void kernel_launch(void* const* d_in, const int* in_sizes, int n_in,
                              void* d_out, int out_size) {
    const float* Q  = (const float*)d_in[0];
    const float* Wq = (const float*)d_in[1];
    const float* bq = (const float*)d_in[2];
    const float* Wk = (const float*)d_in[3];
    const float* bk = (const float*)d_in[4];
    const float* Wv = (const float*)d_in[5];
    const float* bv = (const float*)d_in[6];
    const float* Wo = (const float*)d_in[7];
    const float* bo = (const float*)d_in[8];

    float* out = (float*)d_out;
    float* w   = out + (size_t)BB * SS * DD;

    float* g_ao_ptr;  cudaGetSymbolAddress((void**)&g_ao_ptr,  g_ao);
    float* g_Qn_ptr;  cudaGetSymbolAddress((void**)&g_Qn_ptr,  g_Qn);
    float* g_aon_ptr; cudaGetSymbolAddress((void**)&g_aon_ptr, g_aon);

    const int GEMM_SMEM = 4 * 4608 * 4;
    const int ATTN_SMEM = (32 * SCP + 4 * KVW + 32 * 68 + 32 + 256) * 4;
    cudaFuncSetAttribute(k_qkv,  cudaFuncAttributeMaxDynamicSharedMemorySize, GEMM_SMEM);
    cudaFuncSetAttribute(k_out,  cudaFuncAttributeMaxDynamicSharedMemorySize, GEMM_SMEM);
    cudaFuncSetAttribute(k_attn, cudaFuncAttributeMaxDynamicSharedMemorySize, ATTN_SMEM);

    k_cvtW<<<dim3(16, 16, 4), 256>>>(Wq, Wk, Wv, Wo);
    k_maskstats<<<NROWS, 128>>>(Q);
    k_norm<<<NROWS, 128>>>(Q, g_Qn_ptr, 0);
    k_qkv<<<dim3(4, 64, 3), 256, GEMM_SMEM>>>(bq, bk, bv);
    k_attn<<<dim3(32, 64), 512, ATTN_SMEM>>>(Q, w);
    k_norm<<<NROWS, 128>>>(g_ao_ptr, g_aon_ptr, 1);
    k_out<<<dim3(4, 64), 256, GEMM_SMEM>>>(bo, out);
}

// round 10
// speedup vs baseline: 1.0206x; 1.0206x over previous
#include <cuda_runtime.h>
#include <math.h>

#define BB 8
#define SS 1024
#define DD 512
#define HD 64
#define NROWS (BB*SS)
#define EPSV 1e-5f
#define SCP 1036
#define KVW 4352     // words per KV buffer (64 rows x 68)

// ---------------- scratch ----------------
__device__ float g_Qp[NROWS*DD];   // tf32 bits, [s][d]
__device__ float g_Kp[NROWS*DD];   // tf32 bits, [s][d]
__device__ float g_Vt[NROWS*DD];   // tf32 bits, TRANSPOSED: [bh][d][s]
__device__ float g_ao[NROWS*DD];   // exact fp32
__device__ float g_Qn[NROWS*DD];   // normed Q, tf32 bits
__device__ float g_aon[NROWS*DD];  // normed ao, tf32 bits
__device__ float g_Wt[4*DD*DD];    // tf32 weights TRANSPOSED: [n][k]
__device__ float g_sum1[BB], g_sq1[BB], g_sum2[BB], g_sq2[BB];
__device__ int   g_cnt[BB];
__device__ int   g_mask[NROWS];

// ---------------- helpers ----------------
__device__ __forceinline__ unsigned f2tf(float x) {
    unsigned r; asm("cvt.rna.tf32.f32 %0, %1;" : "=r"(r) : "f"(x)); return r;
}
__device__ __forceinline__ void mma8(float* c, unsigned a0, unsigned a1, unsigned a2, unsigned a3,
                                     unsigned b0, unsigned b1) {
    asm volatile(
        "mma.sync.aligned.m16n8k8.row.col.f32.tf32.tf32.f32 "
        "{%0,%1,%2,%3},{%4,%5,%6,%7},{%8,%9},{%0,%1,%2,%3};"
        : "+f"(c[0]), "+f"(c[1]), "+f"(c[2]), "+f"(c[3])
        : "r"(a0), "r"(a1), "r"(a2), "r"(a3), "r"(b0), "r"(b1));
}
__device__ __forceinline__ void ldsm4(unsigned addr, unsigned& r0, unsigned& r1,
                                      unsigned& r2, unsigned& r3) {
    asm volatile("ldmatrix.sync.aligned.m8n8.x4.shared.b16 {%0,%1,%2,%3}, [%4];"
                 : "=r"(r0), "=r"(r1), "=r"(r2), "=r"(r3) : "r"(addr));
}
__device__ __forceinline__ unsigned cvta_s(const void* p) {
    return (unsigned)__cvta_generic_to_shared(p);
}
#define CP16(dst_u32, src_ptr) \
    asm volatile("cp.async.cg.shared.global [%0], [%1], 16;" :: "r"(dst_u32), "l"(src_ptr))
#define CP_COMMIT() asm volatile("cp.async.commit_group;")
#define CP_WAIT2()  asm volatile("cp.async.wait_group 2;")
#define CP_WAIT0()  asm volatile("cp.async.wait_group 0;")

// ---------------- tiny kernels ----------------
__global__ void k_cvtW(const float* __restrict__ Wq, const float* __restrict__ Wk,
                       const float* __restrict__ Wv, const float* __restrict__ Wo) {
    if (blockIdx.x == 0 && blockIdx.y == 0 && blockIdx.z == 0 && threadIdx.x < BB) {
        int t = threadIdx.x;
        g_sum1[t]=0.f; g_sq1[t]=0.f; g_sum2[t]=0.f; g_sq2[t]=0.f; g_cnt[t]=0;
    }
    __shared__ float t[32][33];
    const float* src = (blockIdx.z == 0) ? Wq : (blockIdx.z == 1) ? Wk :
                       (blockIdx.z == 2) ? Wv : Wo;
    float* dst = g_Wt + (size_t)blockIdx.z * DD * DD;
    int k0 = blockIdx.x * 32, n0 = blockIdx.y * 32;
    int c = threadIdx.x & 31, r0 = threadIdx.x >> 5;
    #pragma unroll
    for (int i = 0; i < 4; i++) {
        int r = r0 + 8 * i;
        t[r][c] = src[(size_t)(k0 + r) * DD + n0 + c];
    }
    __syncthreads();
    #pragma unroll
    for (int i = 0; i < 4; i++) {
        int r = r0 + 8 * i;
        ((unsigned*)dst)[(size_t)(n0 + r) * DD + k0 + c] = f2tf(t[c][r]);
    }
}

__global__ void k_maskstats(const float* __restrict__ Q) {
    int row = blockIdx.x;
    int t = threadIdx.x;
    float4 q = ((const float4*)(Q + (size_t)row * DD))[t];
    bool nz = (q.x != 0.f) || (q.y != 0.f) || (q.z != 0.f) || (q.w != 0.f);
    float s  = q.x + q.y + q.z + q.w;
    float s2 = q.x*q.x + q.y*q.y + q.z*q.z + q.w*q.w;
    int valid = __syncthreads_or(nz ? 1 : 0);
    #pragma unroll
    for (int o = 16; o > 0; o >>= 1) {
        s  += __shfl_xor_sync(0xffffffffu, s,  o);
        s2 += __shfl_xor_sync(0xffffffffu, s2, o);
    }
    __shared__ float rs[4], rs2[4];
    if ((t & 31) == 0) { rs[t >> 5] = s; rs2[t >> 5] = s2; }
    __syncthreads();
    if (t == 0) {
        g_mask[row] = valid;
        if (valid) {
            int b = row >> 10;
            atomicAdd(&g_cnt[b], 1);
            atomicAdd(&g_sum1[b], rs[0]+rs[1]+rs[2]+rs[3]);
            atomicAdd(&g_sq1[b],  rs2[0]+rs2[1]+rs2[2]+rs2[3]);
        }
    }
}

__global__ void k_norm(const float* __restrict__ src, float* __restrict__ dst, int which) {
    int row = blockIdx.x;
    int t = threadIdx.x;
    int b = row >> 10;
    float cntD = (float)g_cnt[b] * (float)DD;
    float sum = which ? g_sum2[b] : g_sum1[b];
    float sq  = which ? g_sq2[b]  : g_sq1[b];
    float mean = (cntD > 0.f) ? sum / cntD : 0.f;
    float var  = (cntD > 0.f) ? sq / cntD - mean * mean : 0.f;
    if (var < 0.f) var = 0.f;
    float rstd = rsqrtf(var + EPSV);
    float sc = g_mask[row] ? rstd : 0.f;
    float mm = mean * sc;
    float4 v = ((const float4*)(src + (size_t)row * DD))[t];
    uint4 u;
    u.x = f2tf(fmaf(v.x, sc, -mm)); u.y = f2tf(fmaf(v.y, sc, -mm));
    u.z = f2tf(fmaf(v.z, sc, -mm)); u.w = f2tf(fmaf(v.w, sc, -mm));
    ((uint4*)(dst + (size_t)row * DD))[t] = u;
}

// ============ tf32 GEMM body: BM=128, BN=128, BK=32; 8 warps (4m x 2n), warp 32x64 ============
struct GemmOut { float c[2][8][4]; };

__device__ __forceinline__ void gemm_body(
    const float* __restrict__ Asrc, const float* __restrict__ Bsrc,
    int m0, int n0, float* smq, GemmOut& R)
{
    float* As0 = smq;               // 128*36
    float* As1 = smq + 4608;
    float* Bs0 = smq + 9216;        // 128*36
    float* Bs1 = smq + 13824;

    int tid = threadIdx.x;
    int wid = tid >> 5, lane = tid & 31;
    int wm = wid >> 1, wn = wid & 1;
    int m2 = lane >> 3, r8 = lane & 7;

    unsigned uA0 = cvta_s(As0), uA1 = cvta_s(As1);
    unsigned uB0 = cvta_s(Bs0), uB1 = cvta_s(Bs1);

    int rowA0 = (wm * 32 +      (m2 & 1) * 8 + r8) * 36 + (m2 >> 1) * 4;
    int rowA1 = rowA0 + 16 * 36;
    int rowB[4];
    #pragma unroll
    for (int nq = 0; nq < 4; nq++)
        rowB[nq] = (wn * 64 + nq * 16 + (m2 >> 1) * 8 + r8) * 36 + (m2 & 1) * 4;

    int arow = tid >> 3, c8 = tid & 7;

    #pragma unroll
    for (int mi = 0; mi < 2; mi++)
        #pragma unroll
        for (int ni = 0; ni < 8; ni++)
            #pragma unroll
            for (int j = 0; j < 4; j++) R.c[mi][ni][j] = 0.f;

    // prologue: chunk 0
    #pragma unroll
    for (int i = 0; i < 4; i++) {
        int row = arow + 32 * i;
        CP16(uA0 + (row * 36 + c8 * 4) * 4, Asrc + (size_t)(m0 + row) * 512 + c8 * 4);
        CP16(uB0 + (row * 36 + c8 * 4) * 4, Bsrc + (size_t)(n0 + row) * 512 + c8 * 4);
    }
    CP_COMMIT();

    for (int kc = 0; kc < 16; kc++) {
        CP_WAIT0();
        __syncthreads();
        if (kc < 15) {
            unsigned nA = (kc & 1) ? uA0 : uA1;
            unsigned nB = (kc & 1) ? uB0 : uB1;
            int k0 = (kc + 1) * 32;
            #pragma unroll
            for (int i = 0; i < 4; i++) {
                int row = arow + 32 * i;
                CP16(nA + (row * 36 + c8 * 4) * 4, Asrc + (size_t)(m0 + row) * 512 + k0 + c8 * 4);
                CP16(nB + (row * 36 + c8 * 4) * 4, Bsrc + (size_t)(n0 + row) * 512 + k0 + c8 * 4);
            }
        }
        CP_COMMIT();

        unsigned uAf = (kc & 1) ? uA1 : uA0;
        unsigned uBf = (kc & 1) ? uB1 : uB0;
        #pragma unroll
        for (int s = 0; s < 4; s++) {
            unsigned a[2][4], bb[8][2];
            ldsm4(uAf + (rowA0 + s * 8) * 4, a[0][0], a[0][1], a[0][2], a[0][3]);
            ldsm4(uAf + (rowA1 + s * 8) * 4, a[1][0], a[1][1], a[1][2], a[1][3]);
            #pragma unroll
            for (int nq = 0; nq < 4; nq++)
                ldsm4(uBf + (rowB[nq] + s * 8) * 4,
                      bb[nq*2][0], bb[nq*2][1], bb[nq*2+1][0], bb[nq*2+1][1]);
            #pragma unroll
            for (int mi = 0; mi < 2; mi++)
                #pragma unroll
                for (int ni = 0; ni < 8; ni++)
                    mma8(R.c[mi][ni], a[mi][0], a[mi][1], a[mi][2], a[mi][3],
                         bb[ni][0], bb[ni][1]);
        }
    }
}

// ---------------- QKV ----------------
__global__ __launch_bounds__(256, 2)
void k_qkv(const float* __restrict__ bq, const float* __restrict__ bk,
           const float* __restrict__ bv) {
    extern __shared__ float smq[];
    int z = blockIdx.z;
    const float* bias = (z == 0) ? bq : (z == 1) ? bk : bv;
    const float* Bsrc = g_Wt + (size_t)z * DD * DD;

    int n0 = blockIdx.x * 128, m0 = blockIdx.y * 128;
    int tid = threadIdx.x;
    int wid = tid >> 5, lane = tid & 31, g = lane >> 2, tig = lane & 3;
    int wm = wid >> 1, wn = wid & 1;

    GemmOut R;
    gemm_body(g_Qn, Bsrc, m0, n0, smq, R);

    if (z < 2) {
        float* outp = (z == 0) ? g_Qp : g_Kp;
        #pragma unroll
        for (int mi = 0; mi < 2; mi++) {
            int r0 = m0 + wm * 32 + mi * 16 + g;
            float mk0 = g_mask[r0]     ? 1.f : 0.f;
            float mk1 = g_mask[r0 + 8] ? 1.f : 0.f;
            #pragma unroll
            for (int ni = 0; ni < 8; ni++) {
                int col = n0 + wn * 64 + ni * 8 + tig * 2;
                float b0v = bias[col], b1v = bias[col + 1];
                uint2 o0 = make_uint2(f2tf((R.c[mi][ni][0] + b0v) * mk0),
                                      f2tf((R.c[mi][ni][1] + b1v) * mk0));
                uint2 o1 = make_uint2(f2tf((R.c[mi][ni][2] + b0v) * mk1),
                                      f2tf((R.c[mi][ni][3] + b1v) * mk1));
                *(uint2*)(outp + (size_t)r0 * 512 + col)       = o0;
                *(uint2*)(outp + (size_t)(r0 + 8) * 512 + col) = o1;
            }
        }
    } else {
        #pragma unroll
        for (int mi = 0; mi < 2; mi++) {
            int r0 = m0 + wm * 32 + mi * 16 + g;
            int bidx = r0 >> 10, s_ = r0 & 1023;
            float mk0 = g_mask[r0]     ? 1.f : 0.f;
            float mk1 = g_mask[r0 + 8] ? 1.f : 0.f;
            #pragma unroll
            for (int ni = 0; ni < 8; ni++) {
                int col = n0 + wn * 64 + ni * 8 + tig * 2;
                int h_ = col >> 6, dl = col & 63;
                float b0v = bias[col], b1v = bias[col + 1];
                unsigned* vt0 = (unsigned*)g_Vt + (((size_t)(bidx * 8 + h_) * 64 + dl) << 10);
                unsigned* vt1 = vt0 + 1024;
                vt0[s_]     = f2tf((R.c[mi][ni][0] + b0v) * mk0);
                vt1[s_]     = f2tf((R.c[mi][ni][1] + b1v) * mk0);
                vt0[s_ + 8] = f2tf((R.c[mi][ni][2] + b0v) * mk1);
                vt1[s_ + 8] = f2tf((R.c[mi][ni][3] + b1v) * mk1);
            }
        }
    }
}

// ---------------- output GEMM ----------------
__global__ __launch_bounds__(256, 2)
void k_out(const float* __restrict__ bo, float* __restrict__ out) {
    extern __shared__ float smq[];
    int n0 = blockIdx.x * 128, m0 = blockIdx.y * 128;
    int tid = threadIdx.x;
    int wid = tid >> 5, lane = tid & 31, g = lane >> 2, tig = lane & 3;
    int wm = wid >> 1, wn = wid & 1;

    GemmOut R;
    gemm_body(g_aon, g_Wt + (size_t)3 * DD * DD, m0, n0, smq, R);

    #pragma unroll
    for (int mi = 0; mi < 2; mi++) {
        int r0 = m0 + wm * 32 + mi * 16 + g;
        #pragma unroll
        for (int ni = 0; ni < 8; ni++) {
            int col = n0 + wn * 64 + ni * 8 + tig * 2;
            float b0v = bo[col], b1v = bo[col + 1];
            float2 a0 = *(const float2*)(g_ao + (size_t)r0 * 512 + col);
            float2 a1 = *(const float2*)(g_ao + (size_t)(r0 + 8) * 512 + col);
            float2 o0 = make_float2(a0.x + fmaxf(R.c[mi][ni][0] + b0v, 0.f),
                                    a0.y + fmaxf(R.c[mi][ni][1] + b1v, 0.f));
            float2 o1 = make_float2(a1.x + fmaxf(R.c[mi][ni][2] + b0v, 0.f),
                                    a1.y + fmaxf(R.c[mi][ni][3] + b1v, 0.f));
            *(float2*)(out + (size_t)r0 * 512 + col)       = o0;
            *(float2*)(out + (size_t)(r0 + 8) * 512 + col) = o1;
        }
    }
}

// ---------------- attention (R8 base; attnV consumes UNNORMALIZED tf32 p) ----------------
__global__ __launch_bounds__(512)
void k_attn(const float* __restrict__ Q, float* __restrict__ w_out) {
    extern __shared__ float sm[];
    float*    sc   = sm;                            // 32*1036
    unsigned* scU  = (unsigned*)sc;
    float*    kvb  = sm + 32 * SCP;                 // 4 * KVW
    unsigned* qs   = (unsigned*)(kvb + 4 * KVW);    // 32*68
    float*    red  = (float*)(qs + 32 * 68);        // 32
    float*    invS = red + 32;                      // 32 per-row 1/sum

    int tid = threadIdx.x;
    int wid = tid >> 5, lane = tid & 31, g = lane >> 2, tig = lane & 3;
    int m2 = lane >> 3, r8 = lane & 7;
    int bh = blockIdx.y, b = bh >> 3, h = bh & 7;
    int q0 = blockIdx.x * 32;
    size_t baseQ = ((size_t)b * SS + q0) * DD + h * HD;
    size_t baseK = ((size_t)b * SS) * DD + h * HD;
    size_t baseVt = (size_t)bh * HD * SS;
    const int bS = b * SS;

    unsigned uKV[4];
    #pragma unroll
    for (int i = 0; i < 4; i++) uKV[i] = cvta_s(kvb + i * KVW);
    unsigned uQS = cvta_s(qs), uSC = cvta_s(sc);

    int lc4 = tid & 15;

    // K prologue: chunks 0..2 (64 keys each)
    #pragma unroll
    for (int p = 0; p < 3; p++) {
        #pragma unroll
        for (int i = 0; i < 2; i++) {
            int f = tid + 512 * i;
            int row = f >> 4, c4 = f & 15;
            CP16(uKV[p] + (row * 68 + c4 * 4) * 4,
                 g_Kp + baseK + (size_t)(p * 64 + row) * DD + c4 * 4);
        }
        CP_COMMIT();
    }

    // q tile -> smem (already tf32 bits)
    {
        int r = tid >> 4, c4 = tid & 15;
        *(uint4*)&qs[r * 68 + c4 * 4] =
            *(const uint4*)(g_Qp + baseQ + (size_t)r * DD + c4 * 4);
    }
    __syncthreads();

    // preload Q fragments (per warp: m16 x k64)
    int nslot = wid >> 1, mh = wid & 1;
    unsigned areg[8][4];
    {
        int rowQ = (mh * 16 + (m2 & 1) * 8 + r8) * 68 + (m2 >> 1) * 4;
        #pragma unroll
        for (int s = 0; s < 8; s++)
            ldsm4(uQS + (rowQ + s * 8) * 4, areg[s][0], areg[s][1], areg[s][2], areg[s][3]);
    }

    // ---- scores: 16 chunks of 64 keys; warp = m16 x n8 (raw masked scores to panel) ----
    int rowKB = (nslot * 8 + r8) * 68 + m2 * 4;
    for (int kt = 0; kt < 16; kt++) {
        CP_WAIT2();
        __syncthreads();
        if (kt + 3 < 16) {
            unsigned nxt = uKV[(kt + 3) & 3];
            #pragma unroll
            for (int i = 0; i < 2; i++) {
                int f = tid + 512 * i;
                int row = f >> 4, c4 = f & 15;
                CP16(nxt + (row * 68 + c4 * 4) * 4,
                     g_Kp + baseK + (size_t)((kt + 3) * 64 + row) * DD + c4 * 4);
            }
        }
        CP_COMMIT();

        unsigned uKVf = uKV[kt & 3];
        float cc[4] = {0.f, 0.f, 0.f, 0.f};
        #pragma unroll
        for (int s16 = 0; s16 < 4; s16++) {
            unsigned b0, b1, b2, b3;
            ldsm4(uKVf + (rowKB + s16 * 16) * 4, b0, b1, b2, b3);
            mma8(cc, areg[2*s16][0],   areg[2*s16][1],   areg[2*s16][2],   areg[2*s16][3],   b0, b1);
            mma8(cc, areg[2*s16+1][0], areg[2*s16+1][1], areg[2*s16+1][2], areg[2*s16+1][3], b2, b3);
        }
        int gc = kt * 64 + nslot * 8 + tig * 2;
        bool k0v = g_mask[bS + gc] != 0;
        bool k1v = g_mask[bS + gc + 1] != 0;
        int r = mh * 16 + g;
        float2 v0 = make_float2(k0v ? cc[0] * 0.125f : -1e30f,
                                k1v ? cc[1] * 0.125f : -1e30f);
        float2 v1 = make_float2(k0v ? cc[2] * 0.125f : -1e30f,
                                k1v ? cc[3] * 0.125f : -1e30f);
        *(float2*)&sc[r * SCP + gc]       = v0;
        *(float2*)&sc[(r + 8) * SCP + gc] = v1;
    }

    // V^T prologue: chunks 0..2 (lands during softmax)
    #pragma unroll
    for (int p = 0; p < 3; p++) {
        #pragma unroll
        for (int i = 0; i < 2; i++) {
            int f = tid + 512 * i;
            int row = f >> 4, c4 = f & 15;
            CP16(uKV[p] + (row * 68 + c4 * 4) * 4,
                 g_Vt + baseVt + (size_t)row * SS + p * 64 + c4 * 4);
        }
        CP_COMMIT();
    }
    __syncthreads();   // all score-panel writes visible

    // ---- exp pass: panel <- tf32(exp(score)) bits (UNNORMALIZED); fp32 rowsums ----
    {
        int row = tid >> 4, l = tid & 15;
        float* srow = sc + row * SCP;
        unsigned* urow = scU + row * SCP;
        float sum = 0.f;
        #pragma unroll
        for (int j = 0; j < 16; j++) {
            int c = (l + 16 * j) * 4;
            float4 v = *(float4*)&srow[c];
            v.x = __expf(v.x); v.y = __expf(v.y); v.z = __expf(v.z); v.w = __expf(v.w);
            sum += v.x + v.y + v.z + v.w;
            uint4 u; u.x = f2tf(v.x); u.y = f2tf(v.y); u.z = f2tf(v.z); u.w = f2tf(v.w);
            *(uint4*)&urow[c] = u;
        }
        #pragma unroll
        for (int o = 8; o > 0; o >>= 1) sum += __shfl_xor_sync(0xffffffffu, sum, o);
        float inv = g_mask[bS + q0 + row] ? (1.0f / sum) : 0.f;
        if (l == 0) invS[row] = inv;

        // w write only (no smem write-back): w = tf32(p) * inv
        float* wrow = w_out + ((size_t)bh * SS + q0 + row) * SS;
        #pragma unroll
        for (int j = 0; j < 16; j++) {
            int c = (l + 16 * j) * 4;
            float4 v = *(const float4*)&srow[c];   // tf32-bit floats
            v.x *= inv; v.y *= inv; v.z *= inv; v.w *= inv;
            *(float4*)(wrow + c) = v;
        }
    }
    __syncthreads();

    // ---- attnV: 16 chunks of 64 s; 16 warps = 8 k-splits x 2 n-slots (unnormalized P) ----
    int ksl = wid & 7, nsl = wid >> 3;
    int rowPA0 = (     (m2 & 1) * 8 + r8) * SCP + (m2 >> 1) * 4;
    int rowPA1 = (16 + (m2 & 1) * 8 + r8) * SCP + (m2 >> 1) * 4;
    int rowVB0 = (nsl * 32 +      (m2 >> 1) * 8 + r8) * 68 + (m2 & 1) * 4;
    int rowVB1 = (nsl * 32 + 16 + (m2 >> 1) * 8 + r8) * 68 + (m2 & 1) * 4;

    float acc[2][4][4];
    #pragma unroll
    for (int mi = 0; mi < 2; mi++)
        #pragma unroll
        for (int nf = 0; nf < 4; nf++)
            #pragma unroll
            for (int j = 0; j < 4; j++) acc[mi][nf][j] = 0.f;

    for (int vt = 0; vt < 16; vt++) {
        CP_WAIT2();
        __syncthreads();
        if (vt + 3 < 16) {
            unsigned nxt = uKV[(vt + 3) & 3];
            #pragma unroll
            for (int i = 0; i < 2; i++) {
                int f = tid + 512 * i;
                int row = f >> 4, c4 = f & 15;
                CP16(nxt + (row * 68 + c4 * 4) * 4,
                     g_Vt + baseVt + (size_t)row * SS + (vt + 3) * 64 + c4 * 4);
            }
        }
        CP_COMMIT();

        unsigned uKVf = uKV[vt & 3];
        int kk = vt * 64 + ksl * 8;
        int kl = ksl * 8;
        unsigned a[2][4], bb[4][2];
        ldsm4(uSC + (rowPA0 + kk) * 4, a[0][0], a[0][1], a[0][2], a[0][3]);
        ldsm4(uSC + (rowPA1 + kk) * 4, a[1][0], a[1][1], a[1][2], a[1][3]);
        ldsm4(uKVf + (rowVB0 + kl) * 4, bb[0][0], bb[0][1], bb[1][0], bb[1][1]);
        ldsm4(uKVf + (rowVB1 + kl) * 4, bb[2][0], bb[2][1], bb[3][0], bb[3][1]);
        #pragma unroll
        for (int nf = 0; nf < 4; nf++) {
            mma8(acc[0][nf], a[0][0], a[0][1], a[0][2], a[0][3], bb[nf][0], bb[nf][1]);
            mma8(acc[1][nf], a[1][0], a[1][1], a[1][2], a[1][3], bb[nf][0], bb[nf][1]);
        }
    }
    __syncthreads();

    // ---- reduce 8 k-splits via kvb; scale by inv[row] at the store ----
    float* at = kvb;
    #pragma unroll
    for (int mi = 0; mi < 2; mi++) {
        int r = mi * 16 + g;
        float i0 = invS[r], i1 = invS[r + 8];
        #pragma unroll
        for (int nf = 0; nf < 4; nf++) {
            int col = nsl * 32 + nf * 8 + tig * 2;
            *(float2*)&at[ksl * 2176 + r * 68 + col] =
                make_float2(acc[mi][nf][0] * i0, acc[mi][nf][1] * i0);
            *(float2*)&at[ksl * 2176 + (r + 8) * 68 + col] =
                make_float2(acc[mi][nf][2] * i1, acc[mi][nf][3] * i1);
        }
    }
    __syncthreads();

    // ---- epilogue: attn_out = attn + Q; stats2 ----
    {
        int lr = tid >> 4;
        float4 o = make_float4(0.f, 0.f, 0.f, 0.f);
        #pragma unroll
        for (int k = 0; k < 8; k++) {
            float4 p = *(const float4*)&at[k * 2176 + lr * 68 + lc4 * 4];
            o.x += p.x; o.y += p.y; o.z += p.z; o.w += p.w;
        }
        size_t gaddr = baseQ + (size_t)lr * DD + lc4 * 4;
        float4 q4 = *(const float4*)(Q + gaddr);
        o.x += q4.x; o.y += q4.y; o.z += q4.z; o.w += q4.w;
        *(float4*)(g_ao + gaddr) = o;
        float t1 = o.x + o.y + o.z + o.w;
        float t2 = o.x*o.x + o.y*o.y + o.z*o.z + o.w*o.w;
        #pragma unroll
        for (int off = 16; off > 0; off >>= 1) {
            t1 += __shfl_xor_sync(0xffffffffu, t1, off);
            t2 += __shfl_xor_sync(0xffffffffu, t2, off);
        }
        if (lane == 0) { red[wid] = t1; red[16 + wid] = t2; }
    }
    __syncthreads();
    if (tid == 0) {
        float S1 = 0.f, S2 = 0.f;
        #pragma unroll
        for (int i = 0; i < 16; i++) { S1 += red[i]; S2 += red[16 + i]; }
        atomicAdd(&g_sum2[b], S1);
        atomicAdd(&g_sq2[b], S2);
    }
}

// ---------------- launch ----------------
extern "C" void kernel_launch(void* const* d_in, const int* in_sizes, int n_in,
                              void* d_out, int out_size) {
    const float* Q  = (const float*)d_in[0];
    const float* Wq = (const float*)d_in[1];
    const float* bq = (const float*)d_in[2];
    const float* Wk = (const float*)d_in[3];
    const float* bk = (const float*)d_in[4];
    const float* Wv = (const float*)d_in[5];
    const float* bv = (const float*)d_in[6];
    const float* Wo = (const float*)d_in[7];
    const float* bo = (const float*)d_in[8];

    float* out = (float*)d_out;
    float* w   = out + (size_t)BB * SS * DD;

    float* g_ao_ptr;  cudaGetSymbolAddress((void**)&g_ao_ptr,  g_ao);
    float* g_Qn_ptr;  cudaGetSymbolAddress((void**)&g_Qn_ptr,  g_Qn);
    float* g_aon_ptr; cudaGetSymbolAddress((void**)&g_aon_ptr, g_aon);

    const int GEMM_SMEM = 4 * 4608 * 4;
    const int ATTN_SMEM = (32 * SCP + 4 * KVW + 32 * 68 + 64) * 4;
    cudaFuncSetAttribute(k_qkv,  cudaFuncAttributeMaxDynamicSharedMemorySize, GEMM_SMEM);
    cudaFuncSetAttribute(k_out,  cudaFuncAttributeMaxDynamicSharedMemorySize, GEMM_SMEM);
    cudaFuncSetAttribute(k_attn, cudaFuncAttributeMaxDynamicSharedMemorySize, ATTN_SMEM);

    k_cvtW<<<dim3(16, 16, 4), 256>>>(Wq, Wk, Wv, Wo);
    k_maskstats<<<NROWS, 128>>>(Q);
    k_norm<<<NROWS, 128>>>(Q, g_Qn_ptr, 0);
    k_qkv<<<dim3(4, 64, 3), 256, GEMM_SMEM>>>(bq, bk, bv);
    k_attn<<<dim3(32, 64), 512, ATTN_SMEM>>>(Q, w);
    k_norm<<<NROWS, 128>>>(g_ao_ptr, g_aon_ptr, 1);
    k_out<<<dim3(4, 64), 256, GEMM_SMEM>>>(bo, out);
}

// round 12
// speedup vs baseline: 1.2214x; 1.1968x over previous
#include <cuda_runtime.h>
#include <cuda_fp16.h>
#include <math.h>

#define BB 8
#define SS 1024
#define DD 512
#define HD 64
#define NROWS (BB*SS)
#define EPSV 1e-5f
#define SCPH 1032    // fp16 panel stride (halves); 1032*2 B mod 128 = 16 -> ldsm conflict-free
#define KVW 4352     // words per KV buffer (64 rows x 68 fp32; V fp16 uses 64 x 144B)

// ---------------- scratch ----------------
__device__ float  g_Qp[NROWS*DD];   // tf32 bits, [s][d]
__device__ float  g_Kp[NROWS*DD];   // tf32 bits, [s][d]
__device__ __half g_Vh[NROWS*DD];   // fp16 V: [bh][s][d]
__device__ float  g_ao[NROWS*DD];   // exact fp32
__device__ float  g_Qn[NROWS*DD];   // normed Q, tf32 bits
__device__ float  g_aon[NROWS*DD];  // normed ao, tf32 bits
__device__ float  g_Wt[4*DD*DD];    // tf32 weights TRANSPOSED: [n][k]
__device__ float  g_sum1[BB], g_sq1[BB], g_sum2[BB], g_sq2[BB];
__device__ int    g_cnt[BB];
__device__ int    g_mask[NROWS];

// ---------------- helpers ----------------
__device__ __forceinline__ unsigned f2tf(float x) {
    unsigned r; asm("cvt.rna.tf32.f32 %0, %1;" : "=r"(r) : "f"(x)); return r;
}
__device__ __forceinline__ void mma8(float* c, unsigned a0, unsigned a1, unsigned a2, unsigned a3,
                                     unsigned b0, unsigned b1) {
    asm volatile(
        "mma.sync.aligned.m16n8k8.row.col.f32.tf32.tf32.f32 "
        "{%0,%1,%2,%3},{%4,%5,%6,%7},{%8,%9},{%0,%1,%2,%3};"
        : "+f"(c[0]), "+f"(c[1]), "+f"(c[2]), "+f"(c[3])
        : "r"(a0), "r"(a1), "r"(a2), "r"(a3), "r"(b0), "r"(b1));
}
__device__ __forceinline__ void mma_h(float* c, unsigned a0, unsigned a1, unsigned b0) {
    asm volatile(
        "mma.sync.aligned.m16n8k8.row.col.f32.f16.f16.f32 "
        "{%0,%1,%2,%3},{%4,%5},{%6},{%0,%1,%2,%3};"
        : "+f"(c[0]), "+f"(c[1]), "+f"(c[2]), "+f"(c[3])
        : "r"(a0), "r"(a1), "r"(b0));
}
__device__ __forceinline__ void ldsm4(unsigned addr, unsigned& r0, unsigned& r1,
                                      unsigned& r2, unsigned& r3) {
    asm volatile("ldmatrix.sync.aligned.m8n8.x4.shared.b16 {%0,%1,%2,%3}, [%4];"
                 : "=r"(r0), "=r"(r1), "=r"(r2), "=r"(r3) : "r"(addr));
}
__device__ __forceinline__ void ldsm4t(unsigned addr, unsigned& r0, unsigned& r1,
                                       unsigned& r2, unsigned& r3) {
    asm volatile("ldmatrix.sync.aligned.m8n8.x4.trans.shared.b16 {%0,%1,%2,%3}, [%4];"
                 : "=r"(r0), "=r"(r1), "=r"(r2), "=r"(r3) : "r"(addr));
}
__device__ __forceinline__ unsigned cvta_s(const void* p) {
    return (unsigned)__cvta_generic_to_shared(p);
}
#define CP16(dst_u32, src_ptr) \
    asm volatile("cp.async.cg.shared.global [%0], [%1], 16;" :: "r"(dst_u32), "l"(src_ptr))
#define CP_COMMIT() asm volatile("cp.async.commit_group;")
#define CP_WAIT2()  asm volatile("cp.async.wait_group 2;")
#define CP_WAIT0()  asm volatile("cp.async.wait_group 0;")

// ---------------- tiny kernels ----------------
__global__ void k_cvtW(const float* __restrict__ Wq, const float* __restrict__ Wk,
                       const float* __restrict__ Wv, const float* __restrict__ Wo) {
    if (blockIdx.x == 0 && blockIdx.y == 0 && blockIdx.z == 0 && threadIdx.x < BB) {
        int t = threadIdx.x;
        g_sum1[t]=0.f; g_sq1[t]=0.f; g_sum2[t]=0.f; g_sq2[t]=0.f; g_cnt[t]=0;
    }
    __shared__ float t[32][33];
    const float* src = (blockIdx.z == 0) ? Wq : (blockIdx.z == 1) ? Wk :
                       (blockIdx.z == 2) ? Wv : Wo;
    float* dst = g_Wt + (size_t)blockIdx.z * DD * DD;
    int k0 = blockIdx.x * 32, n0 = blockIdx.y * 32;
    int c = threadIdx.x & 31, r0 = threadIdx.x >> 5;
    #pragma unroll
    for (int i = 0; i < 4; i++) {
        int r = r0 + 8 * i;
        t[r][c] = src[(size_t)(k0 + r) * DD + n0 + c];
    }
    __syncthreads();
    #pragma unroll
    for (int i = 0; i < 4; i++) {
        int r = r0 + 8 * i;
        ((unsigned*)dst)[(size_t)(n0 + r) * DD + k0 + c] = f2tf(t[c][r]);
    }
}

__global__ void k_maskstats(const float* __restrict__ Q) {
    int row = blockIdx.x;
    int t = threadIdx.x;
    float4 q = ((const float4*)(Q + (size_t)row * DD))[t];
    bool nz = (q.x != 0.f) || (q.y != 0.f) || (q.z != 0.f) || (q.w != 0.f);
    float s  = q.x + q.y + q.z + q.w;
    float s2 = q.x*q.x + q.y*q.y + q.z*q.z + q.w*q.w;
    int valid = __syncthreads_or(nz ? 1 : 0);
    #pragma unroll
    for (int o = 16; o > 0; o >>= 1) {
        s  += __shfl_xor_sync(0xffffffffu, s,  o);
        s2 += __shfl_xor_sync(0xffffffffu, s2, o);
    }
    __shared__ float rs[4], rs2[4];
    if ((t & 31) == 0) { rs[t >> 5] = s; rs2[t >> 5] = s2; }
    __syncthreads();
    if (t == 0) {
        g_mask[row] = valid;
        if (valid) {
            int b = row >> 10;
            atomicAdd(&g_cnt[b], 1);
            atomicAdd(&g_sum1[b], rs[0]+rs[1]+rs[2]+rs[3]);
            atomicAdd(&g_sq1[b],  rs2[0]+rs2[1]+rs2[2]+rs2[3]);
        }
    }
}

__global__ void k_norm(const float* __restrict__ src, float* __restrict__ dst, int which) {
    int row = blockIdx.x;
    int t = threadIdx.x;
    int b = row >> 10;
    float cntD = (float)g_cnt[b] * (float)DD;
    float sum = which ? g_sum2[b] : g_sum1[b];
    float sq  = which ? g_sq2[b]  : g_sq1[b];
    float mean = (cntD > 0.f) ? sum / cntD : 0.f;
    float var  = (cntD > 0.f) ? sq / cntD - mean * mean : 0.f;
    if (var < 0.f) var = 0.f;
    float rstd = rsqrtf(var + EPSV);
    float sc = g_mask[row] ? rstd : 0.f;
    float mm = mean * sc;
    float4 v = ((const float4*)(src + (size_t)row * DD))[t];
    uint4 u;
    u.x = f2tf(fmaf(v.x, sc, -mm)); u.y = f2tf(fmaf(v.y, sc, -mm));
    u.z = f2tf(fmaf(v.z, sc, -mm)); u.w = f2tf(fmaf(v.w, sc, -mm));
    ((uint4*)(dst + (size_t)row * DD))[t] = u;
}

// ============ tf32 GEMM body (R8 verbatim): BM=128, BN=128, BK=32 ============
struct GemmOut { float c[2][8][4]; };

__device__ __forceinline__ void gemm_body(
    const float* __restrict__ Asrc, const float* __restrict__ Bsrc,
    int m0, int n0, float* smq, GemmOut& R)
{
    float* As0 = smq;
    float* As1 = smq + 4608;
    float* Bs0 = smq + 9216;
    float* Bs1 = smq + 13824;

    int tid = threadIdx.x;
    int wid = tid >> 5, lane = tid & 31;
    int wm = wid >> 1, wn = wid & 1;
    int m2 = lane >> 3, r8 = lane & 7;

    unsigned uA0 = cvta_s(As0), uA1 = cvta_s(As1);
    unsigned uB0 = cvta_s(Bs0), uB1 = cvta_s(Bs1);

    int rowA0 = (wm * 32 +      (m2 & 1) * 8 + r8) * 36 + (m2 >> 1) * 4;
    int rowA1 = rowA0 + 16 * 36;
    int rowB[4];
    #pragma unroll
    for (int nq = 0; nq < 4; nq++)
        rowB[nq] = (wn * 64 + nq * 16 + (m2 >> 1) * 8 + r8) * 36 + (m2 & 1) * 4;

    int arow = tid >> 3, c8 = tid & 7;

    #pragma unroll
    for (int mi = 0; mi < 2; mi++)
        #pragma unroll
        for (int ni = 0; ni < 8; ni++)
            #pragma unroll
            for (int j = 0; j < 4; j++) R.c[mi][ni][j] = 0.f;

    #pragma unroll
    for (int i = 0; i < 4; i++) {
        int row = arow + 32 * i;
        CP16(uA0 + (row * 36 + c8 * 4) * 4, Asrc + (size_t)(m0 + row) * 512 + c8 * 4);
        CP16(uB0 + (row * 36 + c8 * 4) * 4, Bsrc + (size_t)(n0 + row) * 512 + c8 * 4);
    }
    CP_COMMIT();

    for (int kc = 0; kc < 16; kc++) {
        CP_WAIT0();
        __syncthreads();
        if (kc < 15) {
            unsigned nA = (kc & 1) ? uA0 : uA1;
            unsigned nB = (kc & 1) ? uB0 : uB1;
            int k0 = (kc + 1) * 32;
            #pragma unroll
            for (int i = 0; i < 4; i++) {
                int row = arow + 32 * i;
                CP16(nA + (row * 36 + c8 * 4) * 4, Asrc + (size_t)(m0 + row) * 512 + k0 + c8 * 4);
                CP16(nB + (row * 36 + c8 * 4) * 4, Bsrc + (size_t)(n0 + row) * 512 + k0 + c8 * 4);
            }
        }
        CP_COMMIT();

        unsigned uAf = (kc & 1) ? uA1 : uA0;
        unsigned uBf = (kc & 1) ? uB1 : uB0;
        #pragma unroll
        for (int s = 0; s < 4; s++) {
            unsigned a[2][4], bb[8][2];
            ldsm4(uAf + (rowA0 + s * 8) * 4, a[0][0], a[0][1], a[0][2], a[0][3]);
            ldsm4(uAf + (rowA1 + s * 8) * 4, a[1][0], a[1][1], a[1][2], a[1][3]);
            #pragma unroll
            for (int nq = 0; nq < 4; nq++)
                ldsm4(uBf + (rowB[nq] + s * 8) * 4,
                      bb[nq*2][0], bb[nq*2][1], bb[nq*2+1][0], bb[nq*2+1][1]);
            #pragma unroll
            for (int mi = 0; mi < 2; mi++)
                #pragma unroll
                for (int ni = 0; ni < 8; ni++)
                    mma8(R.c[mi][ni], a[mi][0], a[mi][1], a[mi][2], a[mi][3],
                         bb[ni][0], bb[ni][1]);
        }
    }
}

// ---------------- QKV ----------------
__global__ __launch_bounds__(256, 2)
void k_qkv(const float* __restrict__ bq, const float* __restrict__ bk,
           const float* __restrict__ bv) {
    extern __shared__ float smq[];
    int z = blockIdx.z;
    const float* bias = (z == 0) ? bq : (z == 1) ? bk : bv;
    const float* Bsrc = g_Wt + (size_t)z * DD * DD;

    int n0 = blockIdx.x * 128, m0 = blockIdx.y * 128;
    int tid = threadIdx.x;
    int wid = tid >> 5, lane = tid & 31, g = lane >> 2, tig = lane & 3;
    int wm = wid >> 1, wn = wid & 1;

    GemmOut R;
    gemm_body(g_Qn, Bsrc, m0, n0, smq, R);

    if (z < 2) {
        float* outp = (z == 0) ? g_Qp : g_Kp;
        #pragma unroll
        for (int mi = 0; mi < 2; mi++) {
            int r0 = m0 + wm * 32 + mi * 16 + g;
            float mk0 = g_mask[r0]     ? 1.f : 0.f;
            float mk1 = g_mask[r0 + 8] ? 1.f : 0.f;
            #pragma unroll
            for (int ni = 0; ni < 8; ni++) {
                int col = n0 + wn * 64 + ni * 8 + tig * 2;
                float b0v = bias[col], b1v = bias[col + 1];
                uint2 o0 = make_uint2(f2tf((R.c[mi][ni][0] + b0v) * mk0),
                                      f2tf((R.c[mi][ni][1] + b1v) * mk0));
                uint2 o1 = make_uint2(f2tf((R.c[mi][ni][2] + b0v) * mk1),
                                      f2tf((R.c[mi][ni][3] + b1v) * mk1));
                *(uint2*)(outp + (size_t)r0 * 512 + col)       = o0;
                *(uint2*)(outp + (size_t)(r0 + 8) * 512 + col) = o1;
            }
        }
    } else {
        // V: fp16 into g_Vh[bh][s][d]
        #pragma unroll
        for (int mi = 0; mi < 2; mi++) {
            int r0 = m0 + wm * 32 + mi * 16 + g;
            int bidx = r0 >> 10, s_ = r0 & 1023;
            float mk0 = g_mask[r0]     ? 1.f : 0.f;
            float mk1 = g_mask[r0 + 8] ? 1.f : 0.f;
            #pragma unroll
            for (int ni = 0; ni < 8; ni++) {
                int col = n0 + wn * 64 + ni * 8 + tig * 2;
                int h_ = col >> 6, dl = col & 63;
                float b0v = bias[col], b1v = bias[col + 1];
                __half* base = g_Vh + ((size_t)(bidx * 8 + h_) * 1024 + s_) * 64 + dl;
                *(__half2*)base = __floats2half2_rn((R.c[mi][ni][0] + b0v) * mk0,
                                                    (R.c[mi][ni][1] + b1v) * mk0);
                *(__half2*)(base + 8 * 64) = __floats2half2_rn((R.c[mi][ni][2] + b0v) * mk1,
                                                               (R.c[mi][ni][3] + b1v) * mk1);
            }
        }
    }
}

// ---------------- output GEMM ----------------
__global__ __launch_bounds__(256, 2)
void k_out(const float* __restrict__ bo, float* __restrict__ out) {
    extern __shared__ float smq[];
    int n0 = blockIdx.x * 128, m0 = blockIdx.y * 128;
    int tid = threadIdx.x;
    int wid = tid >> 5, lane = tid & 31, g = lane >> 2, tig = lane & 3;
    int wm = wid >> 1, wn = wid & 1;

    GemmOut R;
    gemm_body(g_aon, g_Wt + (size_t)3 * DD * DD, m0, n0, smq, R);

    #pragma unroll
    for (int mi = 0; mi < 2; mi++) {
        int r0 = m0 + wm * 32 + mi * 16 + g;
        #pragma unroll
        for (int ni = 0; ni < 8; ni++) {
            int col = n0 + wn * 64 + ni * 8 + tig * 2;
            float b0v = bo[col], b1v = bo[col + 1];
            float2 a0 = *(const float2*)(g_ao + (size_t)r0 * 512 + col);
            float2 a1 = *(const float2*)(g_ao + (size_t)(r0 + 8) * 512 + col);
            float2 o0 = make_float2(a0.x + fmaxf(R.c[mi][ni][0] + b0v, 0.f),
                                    a0.y + fmaxf(R.c[mi][ni][1] + b1v, 0.f));
            float2 o1 = make_float2(a1.x + fmaxf(R.c[mi][ni][2] + b0v, 0.f),
                                    a1.y + fmaxf(R.c[mi][ni][3] + b1v, 0.f));
            *(float2*)(out + (size_t)r0 * 512 + col)       = o0;
            *(float2*)(out + (size_t)(r0 + 8) * 512 + col) = o1;
        }
    }
}

// ---------------- attention: 64 q-rows, fp16 panel, fp16 attnV ----------------
// smem (words): scH 33024 | kvb 4*4352 | qs 4352 | red 32 | part 256 | invS 64
__global__ __launch_bounds__(512)
void k_attn(const float* __restrict__ Q, float* __restrict__ w_out) {
    extern __shared__ float sm[];
    __half* scH  = (__half*)sm;                 // 64 x 1032 fp16 (exp values)
    float*  kvb  = sm + 33024;
    float*  qs   = kvb + 4 * KVW;               // 64*68 tf32 Q tile; later: attn accum
    float*  red  = qs + 4352;                   // 32
    float*  part = red + 32;                    // 64*4 rowsum partials
    float*  invS = part + 256;                  // 64

    int tid = threadIdx.x;
    int wid = tid >> 5, lane = tid & 31, g = lane >> 2, tig = lane & 3;
    int m2 = lane >> 3, r8 = lane & 7;
    int bh = blockIdx.y, b = bh >> 3, h = bh & 7;
    int q0 = blockIdx.x * 64;
    size_t baseQ = ((size_t)b * SS + q0) * DD + h * HD;
    size_t baseK = ((size_t)b * SS) * DD + h * HD;
    const __half* Vh = g_Vh + (size_t)bh * SS * HD;
    const int bS = b * SS;

    unsigned uKV[4];
    #pragma unroll
    for (int i = 0; i < 4; i++) uKV[i] = cvta_s(kvb + i * KVW);
    unsigned uQS = cvta_s(qs), uSC = cvta_s(scH);

    // K prologue: chunks 0..2 (64 keys x 64 d, stride 68)
    #pragma unroll
    for (int p = 0; p < 3; p++) {
        #pragma unroll
        for (int i = 0; i < 2; i++) {
            int f = tid + 512 * i;
            int row = f >> 4, c4 = f & 15;
            CP16(uKV[p] + (row * 68 + c4 * 4) * 4,
                 g_Kp + baseK + (size_t)(p * 64 + row) * DD + c4 * 4);
        }
        CP_COMMIT();
    }

    // q tile 64x64 -> smem (tf32 bits)
    #pragma unroll
    for (int i = 0; i < 2; i++) {
        int f = tid + 512 * i;
        int r = f >> 4, c4 = f & 15;
        *(uint4*)&qs[r * 68 + c4 * 4] =
            *(const uint4*)(g_Qp + baseQ + (size_t)r * DD + c4 * 4);
    }
    __syncthreads();

    // warp layout: 16 warps = 4 m-groups x 4 n-slots
    int nslot = wid & 3, mw = wid >> 2;
    unsigned areg[8][4];
    {
        int rowQ = (mw * 16 + (m2 & 1) * 8 + r8) * 68 + (m2 >> 1) * 4;
        #pragma unroll
        for (int s = 0; s < 8; s++)
            ldsm4(uQS + (rowQ + s * 8) * 4, areg[s][0], areg[s][1], areg[s][2], areg[s][3]);
    }

    // ---- scores: 16 chunks of 64 keys; per warp m16 x n16; exp fused into epilogue ----
    float rs0 = 0.f, rs1 = 0.f;
    int rowKB0 = (nslot * 16 + r8) * 68 + m2 * 4;
    int rowKB1 = (nslot * 16 + 8 + r8) * 68 + m2 * 4;
    for (int kt = 0; kt < 16; kt++) {
        CP_WAIT2();
        __syncthreads();
        if (kt + 3 < 16) {
            unsigned nxt = uKV[(kt + 3) & 3];
            #pragma unroll
            for (int i = 0; i < 2; i++) {
                int f = tid + 512 * i;
                int row = f >> 4, c4 = f & 15;
                CP16(nxt + (row * 68 + c4 * 4) * 4,
                     g_Kp + baseK + (size_t)((kt + 3) * 64 + row) * DD + c4 * 4);
            }
        }
        CP_COMMIT();

        unsigned uKVf = uKV[kt & 3];
        float cc[2][4];
        #pragma unroll
        for (int nf = 0; nf < 2; nf++)
            #pragma unroll
            for (int j = 0; j < 4; j++) cc[nf][j] = 0.f;

        #pragma unroll
        for (int s16 = 0; s16 < 4; s16++) {
            unsigned b0, b1, b2, b3;
            ldsm4(uKVf + (rowKB0 + s16 * 16) * 4, b0, b1, b2, b3);
            mma8(cc[0], areg[2*s16][0],   areg[2*s16][1],   areg[2*s16][2],   areg[2*s16][3],   b0, b1);
            mma8(cc[0], areg[2*s16+1][0], areg[2*s16+1][1], areg[2*s16+1][2], areg[2*s16+1][3], b2, b3);
            ldsm4(uKVf + (rowKB1 + s16 * 16) * 4, b0, b1, b2, b3);
            mma8(cc[1], areg[2*s16][0],   areg[2*s16][1],   areg[2*s16][2],   areg[2*s16][3],   b0, b1);
            mma8(cc[1], areg[2*s16+1][0], areg[2*s16+1][1], areg[2*s16+1][2], areg[2*s16+1][3], b2, b3);
        }
        #pragma unroll
        for (int nf = 0; nf < 2; nf++) {
            int gc = kt * 64 + nslot * 16 + nf * 8 + tig * 2;
            bool k0v = g_mask[bS + gc] != 0;
            bool k1v = g_mask[bS + gc + 1] != 0;
            float p0 = k0v ? __expf(cc[nf][0] * 0.125f) : 0.f;
            float p1 = k1v ? __expf(cc[nf][1] * 0.125f) : 0.f;
            float p2 = k0v ? __expf(cc[nf][2] * 0.125f) : 0.f;
            float p3 = k1v ? __expf(cc[nf][3] * 0.125f) : 0.f;
            rs0 += p0 + p1;
            rs1 += p2 + p3;
            int r = mw * 16 + g;
            *(__half2*)&scH[r * SCPH + gc]       = __floats2half2_rn(p0, p1);
            *(__half2*)&scH[(r + 8) * SCPH + gc] = __floats2half2_rn(p2, p3);
        }
    }
    // rowsum partials: reduce over tig, publish per (row, nslot)
    rs0 += __shfl_xor_sync(0xffffffffu, rs0, 1);
    rs0 += __shfl_xor_sync(0xffffffffu, rs0, 2);
    rs1 += __shfl_xor_sync(0xffffffffu, rs1, 1);
    rs1 += __shfl_xor_sync(0xffffffffu, rs1, 2);
    if (tig == 0) {
        part[(mw * 16 + g) * 4 + nslot]     = rs0;
        part[(mw * 16 + g + 8) * 4 + nslot] = rs1;
    }

    // V prologue: chunks 0..2 (64 s-rows x 64 d fp16, stride 144B)
    #pragma unroll
    for (int p = 0; p < 3; p++) {
        int row = tid >> 3, c8 = tid & 7;
        CP16(uKV[p] + row * 144 + c8 * 16,
             (const float*)(Vh + ((size_t)(p * 64 + row)) * 64 + c8 * 8));
        CP_COMMIT();
    }
    __syncthreads();   // panel + part visible

    // ---- w pass: w = fp16(p) * inv (fp32 out); compute invS ----
    {
        int row = tid >> 3, l = tid & 7;
        const float* pr = part + row * 4;
        float sum = pr[0] + pr[1] + pr[2] + pr[3];
        float inv = g_mask[bS + q0 + row] ? (1.0f / sum) : 0.f;
        if (l == 0) invS[row] = inv;
        float* wrow = w_out + ((size_t)bh * SS + q0 + row) * SS;
        const char* prow = (const char*)scH + row * (SCPH * 2);
        #pragma unroll
        for (int j = 0; j < 16; j++) {
            int e = l + 8 * j;                 // 16B unit, 0..127
            uint4 u = *(const uint4*)(prow + e * 16);
            const __half2* hp = (const __half2*)&u;
            float2 f0 = __half22float2(hp[0]);
            float2 f1 = __half22float2(hp[1]);
            float2 f2 = __half22float2(hp[2]);
            float2 f3 = __half22float2(hp[3]);
            float4 o0 = make_float4(f0.x * inv, f0.y * inv, f1.x * inv, f1.y * inv);
            float4 o1 = make_float4(f2.x * inv, f2.y * inv, f3.x * inv, f3.y * inv);
            *(float4*)(wrow + e * 8)     = o0;
            *(float4*)(wrow + e * 8 + 4) = o1;
        }
    }

    // ---- attnV: fp16 mma; 16 chunks of 64 s; warps 4m x 4n; no k-split ----
    int nsl2 = wid & 3, mw2 = wid >> 2;
    unsigned paA = uSC + (unsigned)((mw2 * 16 + r8 + ((lane >> 3) & 1) * 8) * (SCPH * 2)
                                    + ((lane >> 4) & 1) * 16);
    unsigned pbN = (unsigned)((nsl2 * 16 + ((lane >> 4) & 1) * 8) * 2);
    int rowVk = (lane & 7) + ((lane >> 3) & 1) * 8;

    float acc[2][4];
    #pragma unroll
    for (int nf = 0; nf < 2; nf++)
        #pragma unroll
        for (int j = 0; j < 4; j++) acc[nf][j] = 0.f;

    for (int vt = 0; vt < 16; vt++) {
        CP_WAIT2();
        __syncthreads();
        if (vt + 3 < 16) {
            unsigned nxt = uKV[(vt + 3) & 3];
            int row = tid >> 3, c8 = tid & 7;
            CP16(nxt + row * 144 + c8 * 16,
                 (const float*)(Vh + ((size_t)((vt + 3) * 64 + row)) * 64 + c8 * 8));
        }
        CP_COMMIT();

        unsigned uKVf = uKV[vt & 3];
        #pragma unroll
        for (int ks = 0; ks < 4; ks++) {
            unsigned a0, a1, a2, a3, b0, b1, b2, b3;
            ldsm4(paA + vt * 128 + ks * 32, a0, a1, a2, a3);
            ldsm4t(uKVf + (ks * 16 + rowVk) * 144 + pbN, b0, b1, b2, b3);
            mma_h(acc[0], a0, a1, b0);
            mma_h(acc[0], a2, a3, b1);
            mma_h(acc[1], a0, a1, b2);
            mma_h(acc[1], a2, a3, b3);
        }
    }

    // ---- store scaled attn to smem (reuse qs), then epilogue ----
    {
        float* at = qs;
        int r = mw2 * 16 + g;
        float i0 = invS[r], i1 = invS[r + 8];
        #pragma unroll
        for (int nf = 0; nf < 2; nf++) {
            int col = nsl2 * 16 + nf * 8 + tig * 2;
            *(float2*)&at[r * 68 + col]       = make_float2(acc[nf][0] * i0, acc[nf][1] * i0);
            *(float2*)&at[(r + 8) * 68 + col] = make_float2(acc[nf][2] * i1, acc[nf][3] * i1);
        }
    }
    __syncthreads();

    // ---- epilogue: attn_out = attn + Q; stats2 ----
    {
        float* at = qs;
        float t1 = 0.f, t2 = 0.f;
        #pragma unroll
        for (int i = 0; i < 2; i++) {
            int f = tid + 512 * i;
            int r = f >> 4, c4 = f & 15;
            float4 a = *(const float4*)&at[r * 68 + c4 * 4];
            size_t gaddr = baseQ + (size_t)r * DD + c4 * 4;
            float4 q4 = *(const float4*)(Q + gaddr);
            float4 o = make_float4(a.x + q4.x, a.y + q4.y, a.z + q4.z, a.w + q4.w);
            *(float4*)(g_ao + gaddr) = o;
            t1 += o.x + o.y + o.z + o.w;
            t2 += o.x*o.x + o.y*o.y + o.z*o.z + o.w*o.w;
        }
        #pragma unroll
        for (int off = 16; off > 0; off >>= 1) {
            t1 += __shfl_xor_sync(0xffffffffu, t1, off);
            t2 += __shfl_xor_sync(0xffffffffu, t2, off);
        }
        if (lane == 0) { red[wid] = t1; red[16 + wid] = t2; }
    }
    __syncthreads();
    if (tid == 0) {
        float S1 = 0.f, S2 = 0.f;
        #pragma unroll
        for (int i = 0; i < 16; i++) { S1 += red[i]; S2 += red[16 + i]; }
        atomicAdd(&g_sum2[b], S1);
        atomicAdd(&g_sq2[b], S2);
    }
}

// ---------------- launch ----------------
extern "C" void kernel_launch(void* const* d_in, const int* in_sizes, int n_in,
                              void* d_out, int out_size) {
    const float* Q  = (const float*)d_in[0];
    const float* Wq = (const float*)d_in[1];
    const float* bq = (const float*)d_in[2];
    const float* Wk = (const float*)d_in[3];
    const float* bk = (const float*)d_in[4];
    const float* Wv = (const float*)d_in[5];
    const float* bv = (const float*)d_in[6];
    const float* Wo = (const float*)d_in[7];
    const float* bo = (const float*)d_in[8];

    float* out = (float*)d_out;
    float* w   = out + (size_t)BB * SS * DD;

    float* g_ao_ptr;  cudaGetSymbolAddress((void**)&g_ao_ptr,  g_ao);
    float* g_Qn_ptr;  cudaGetSymbolAddress((void**)&g_Qn_ptr,  g_Qn);
    float* g_aon_ptr; cudaGetSymbolAddress((void**)&g_aon_ptr, g_aon);

    const int GEMM_SMEM = 4 * 4608 * 4;
    const int ATTN_SMEM = (33024 + 4 * KVW + 4352 + 32 + 256 + 64) * 4;  // 220544 B
    cudaFuncSetAttribute(k_qkv,  cudaFuncAttributeMaxDynamicSharedMemorySize, GEMM_SMEM);
    cudaFuncSetAttribute(k_out,  cudaFuncAttributeMaxDynamicSharedMemorySize, GEMM_SMEM);
    cudaFuncSetAttribute(k_attn, cudaFuncAttributeMaxDynamicSharedMemorySize, ATTN_SMEM);

    k_cvtW<<<dim3(16, 16, 4), 256>>>(Wq, Wk, Wv, Wo);
    k_maskstats<<<NROWS, 128>>>(Q);
    k_norm<<<NROWS, 128>>>(Q, g_Qn_ptr, 0);
    k_qkv<<<dim3(4, 64, 3), 256, GEMM_SMEM>>>(bq, bk, bv);
    k_attn<<<dim3(16, 64), 512, ATTN_SMEM>>>(Q, w);
    k_norm<<<NROWS, 128>>>(g_ao_ptr, g_aon_ptr, 1);
    k_out<<<dim3(4, 64), 256, GEMM_SMEM>>>(bo, out);
}

// round 13
// speedup vs baseline: 1.4755x; 1.2080x over previous
#include <cuda_runtime.h>
#include <cuda_fp16.h>
#include <math.h>

#define BB 8
#define SS 1024
#define DD 512
#define HD 64
#define NROWS (BB*SS)
#define EPSV 1e-5f
#define SCPH 1032    // fp16 panel stride (halves); 1032*2 mod 128 = 16 -> ldsm conflict-free
#define KVW 2304     // words per KV buffer (64 rows x 72 halves = 9216 B)

// ---------------- scratch ----------------
__device__ __half g_Qp[NROWS*DD];   // fp16 Q-proj [s][d]
__device__ __half g_Kp[NROWS*DD];   // fp16 K-proj [s][d]
__device__ __half g_Vh[NROWS*DD];   // fp16 V: [bh][s][d]
__device__ float  g_ao[NROWS*DD];   // exact fp32
__device__ __half g_Qn[NROWS*DD];   // normed Q fp16
__device__ __half g_aon[NROWS*DD];  // normed ao fp16
__device__ __half g_Wt[4*DD*DD];    // fp16 weights TRANSPOSED: [n][k]
__device__ float  g_sum1[BB], g_sq1[BB], g_sum2[BB], g_sq2[BB];
__device__ int    g_cnt[BB];
__device__ int    g_mask[NROWS];

// ---------------- helpers ----------------
__device__ __forceinline__ void mma_h16(float* c, unsigned a0, unsigned a1, unsigned a2,
                                        unsigned a3, unsigned b0, unsigned b1) {
    asm volatile(
        "mma.sync.aligned.m16n8k16.row.col.f32.f16.f16.f32 "
        "{%0,%1,%2,%3},{%4,%5,%6,%7},{%8,%9},{%0,%1,%2,%3};"
        : "+f"(c[0]), "+f"(c[1]), "+f"(c[2]), "+f"(c[3])
        : "r"(a0), "r"(a1), "r"(a2), "r"(a3), "r"(b0), "r"(b1));
}
__device__ __forceinline__ void ldsm4(unsigned addr, unsigned& r0, unsigned& r1,
                                      unsigned& r2, unsigned& r3) {
    asm volatile("ldmatrix.sync.aligned.m8n8.x4.shared.b16 {%0,%1,%2,%3}, [%4];"
                 : "=r"(r0), "=r"(r1), "=r"(r2), "=r"(r3) : "r"(addr));
}
__device__ __forceinline__ void ldsm4t(unsigned addr, unsigned& r0, unsigned& r1,
                                       unsigned& r2, unsigned& r3) {
    asm volatile("ldmatrix.sync.aligned.m8n8.x4.trans.shared.b16 {%0,%1,%2,%3}, [%4];"
                 : "=r"(r0), "=r"(r1), "=r"(r2), "=r"(r3) : "r"(addr));
}
__device__ __forceinline__ unsigned cvta_s(const void* p) {
    return (unsigned)__cvta_generic_to_shared(p);
}
#define CP16(dst_u32, src_ptr) \
    asm volatile("cp.async.cg.shared.global [%0], [%1], 16;" :: "r"(dst_u32), "l"(src_ptr))
#define CP_COMMIT() asm volatile("cp.async.commit_group;")
#define CP_WAIT2()  asm volatile("cp.async.wait_group 2;")
#define CP_WAIT0()  asm volatile("cp.async.wait_group 0;")

// ---------------- tiny kernels ----------------
__global__ void k_cvtW(const float* __restrict__ Wq, const float* __restrict__ Wk,
                       const float* __restrict__ Wv, const float* __restrict__ Wo) {
    if (blockIdx.x == 0 && blockIdx.y == 0 && blockIdx.z == 0 && threadIdx.x < BB) {
        int t = threadIdx.x;
        g_sum1[t]=0.f; g_sq1[t]=0.f; g_sum2[t]=0.f; g_sq2[t]=0.f; g_cnt[t]=0;
    }
    __shared__ float t[32][33];
    const float* src = (blockIdx.z == 0) ? Wq : (blockIdx.z == 1) ? Wk :
                       (blockIdx.z == 2) ? Wv : Wo;
    __half* dst = g_Wt + (size_t)blockIdx.z * DD * DD;
    int k0 = blockIdx.x * 32, n0 = blockIdx.y * 32;
    int c = threadIdx.x & 31, r0 = threadIdx.x >> 5;
    #pragma unroll
    for (int i = 0; i < 4; i++) {
        int r = r0 + 8 * i;
        t[r][c] = src[(size_t)(k0 + r) * DD + n0 + c];
    }
    __syncthreads();
    #pragma unroll
    for (int i = 0; i < 4; i++) {
        int r = r0 + 8 * i;
        dst[(size_t)(n0 + r) * DD + k0 + c] = __float2half_rn(t[c][r]);
    }
}

__global__ void k_maskstats(const float* __restrict__ Q) {
    int row = blockIdx.x;
    int t = threadIdx.x;
    float4 q = ((const float4*)(Q + (size_t)row * DD))[t];
    bool nz = (q.x != 0.f) || (q.y != 0.f) || (q.z != 0.f) || (q.w != 0.f);
    float s  = q.x + q.y + q.z + q.w;
    float s2 = q.x*q.x + q.y*q.y + q.z*q.z + q.w*q.w;
    int valid = __syncthreads_or(nz ? 1 : 0);
    #pragma unroll
    for (int o = 16; o > 0; o >>= 1) {
        s  += __shfl_xor_sync(0xffffffffu, s,  o);
        s2 += __shfl_xor_sync(0xffffffffu, s2, o);
    }
    __shared__ float rs[4], rs2[4];
    if ((t & 31) == 0) { rs[t >> 5] = s; rs2[t >> 5] = s2; }
    __syncthreads();
    if (t == 0) {
        g_mask[row] = valid;
        if (valid) {
            int b = row >> 10;
            atomicAdd(&g_cnt[b], 1);
            atomicAdd(&g_sum1[b], rs[0]+rs[1]+rs[2]+rs[3]);
            atomicAdd(&g_sq1[b],  rs2[0]+rs2[1]+rs2[2]+rs2[3]);
        }
    }
}

// normalize + fp16 convert
__global__ void k_norm(const float* __restrict__ src, __half* __restrict__ dst, int which) {
    int row = blockIdx.x;
    int t = threadIdx.x;
    int b = row >> 10;
    float cntD = (float)g_cnt[b] * (float)DD;
    float sum = which ? g_sum2[b] : g_sum1[b];
    float sq  = which ? g_sq2[b]  : g_sq1[b];
    float mean = (cntD > 0.f) ? sum / cntD : 0.f;
    float var  = (cntD > 0.f) ? sq / cntD - mean * mean : 0.f;
    if (var < 0.f) var = 0.f;
    float rstd = rsqrtf(var + EPSV);
    float sc = g_mask[row] ? rstd : 0.f;
    float mm = mean * sc;
    float4 v = ((const float4*)(src + (size_t)row * DD))[t];
    __half2 h0 = __floats2half2_rn(fmaf(v.x, sc, -mm), fmaf(v.y, sc, -mm));
    __half2 h1 = __floats2half2_rn(fmaf(v.z, sc, -mm), fmaf(v.w, sc, -mm));
    uint2 u = make_uint2(*(unsigned*)&h0, *(unsigned*)&h1);
    *(uint2*)(dst + (size_t)row * DD + t * 4) = u;
}

// ============ fp16 GEMM body: BM=128, BN=128, BK=32; 8 warps (4m x 2n), warp 32x64 ============
// A [m][k] fp16 stride 40 halves; B [n][k] fp16 stride 40 halves.
struct GemmOut { float c[2][8][4]; };

__device__ __forceinline__ void gemm_body(
    const __half* __restrict__ Asrc, const __half* __restrict__ Bsrc,
    int m0, int n0, __half* smq, GemmOut& R)
{
    unsigned uA0 = cvta_s(smq);
    unsigned uA1 = uA0 + 10240;
    unsigned uB0 = uA0 + 20480;
    unsigned uB1 = uA0 + 30720;

    int tid = threadIdx.x;
    int wid = tid >> 5, lane = tid & 31;
    int wm = wid >> 1, wn = wid & 1;
    int r8 = lane & 7, kh2 = (lane >> 3) & 1, kh4 = (lane >> 4) & 1;

    // ldsm byte offsets (within buffer), add s*32 per k16-step
    unsigned offA0 = (unsigned)((wm * 32 +      r8 + kh2 * 8) * 80 + kh4 * 16);
    unsigned offA1 = offA0 + 16 * 80;
    unsigned offB[4];
    #pragma unroll
    for (int nq = 0; nq < 4; nq++)
        offB[nq] = (unsigned)((wn * 64 + nq * 16 + r8 + kh4 * 8) * 80 + kh2 * 16);

    int lrow = tid >> 2, lc4 = tid & 3;   // loader: 128 rows x 4x16B, 2 iters per matrix

    #pragma unroll
    for (int mi = 0; mi < 2; mi++)
        #pragma unroll
        for (int ni = 0; ni < 8; ni++)
            #pragma unroll
            for (int j = 0; j < 4; j++) R.c[mi][ni][j] = 0.f;

    #pragma unroll
    for (int i = 0; i < 2; i++) {
        int f = tid + 256 * i;
        int row = f >> 2, c4 = f & 3;
        CP16(uA0 + row * 80 + c4 * 16, Asrc + (size_t)(m0 + row) * 512 + c4 * 8);
        CP16(uB0 + row * 80 + c4 * 16, Bsrc + (size_t)(n0 + row) * 512 + c4 * 8);
    }
    CP_COMMIT();

    for (int kc = 0; kc < 16; kc++) {
        CP_WAIT0();
        __syncthreads();
        if (kc < 15) {
            unsigned nA = (kc & 1) ? uA0 : uA1;
            unsigned nB = (kc & 1) ? uB0 : uB1;
            int k0 = (kc + 1) * 32;
            #pragma unroll
            for (int i = 0; i < 2; i++) {
                int f = tid + 256 * i;
                int row = f >> 2, c4 = f & 3;
                CP16(nA + row * 80 + c4 * 16, Asrc + (size_t)(m0 + row) * 512 + k0 + c4 * 8);
                CP16(nB + row * 80 + c4 * 16, Bsrc + (size_t)(n0 + row) * 512 + k0 + c4 * 8);
            }
        }
        CP_COMMIT();

        unsigned uAf = (kc & 1) ? uA1 : uA0;
        unsigned uBf = (kc & 1) ? uB1 : uB0;
        #pragma unroll
        for (int s = 0; s < 2; s++) {
            unsigned a[2][4], bb[8][2];
            ldsm4(uAf + offA0 + s * 32, a[0][0], a[0][1], a[0][2], a[0][3]);
            ldsm4(uAf + offA1 + s * 32, a[1][0], a[1][1], a[1][2], a[1][3]);
            #pragma unroll
            for (int nq = 0; nq < 4; nq++)
                ldsm4(uBf + offB[nq] + s * 32,
                      bb[nq*2][0], bb[nq*2][1], bb[nq*2+1][0], bb[nq*2+1][1]);
            #pragma unroll
            for (int mi = 0; mi < 2; mi++)
                #pragma unroll
                for (int ni = 0; ni < 8; ni++)
                    mma_h16(R.c[mi][ni], a[mi][0], a[mi][1], a[mi][2], a[mi][3],
                            bb[ni][0], bb[ni][1]);
        }
    }
}

// ---------------- QKV ----------------
__global__ __launch_bounds__(256, 2)
void k_qkv(const float* __restrict__ bq, const float* __restrict__ bk,
           const float* __restrict__ bv) {
    extern __shared__ __half smh[];
    int z = blockIdx.z;
    const float* bias = (z == 0) ? bq : (z == 1) ? bk : bv;
    const __half* Bsrc = g_Wt + (size_t)z * DD * DD;

    int n0 = blockIdx.x * 128, m0 = blockIdx.y * 128;
    int tid = threadIdx.x;
    int wid = tid >> 5, lane = tid & 31, g = lane >> 2, tig = lane & 3;
    int wm = wid >> 1, wn = wid & 1;

    GemmOut R;
    gemm_body(g_Qn, Bsrc, m0, n0, smh, R);

    if (z < 2) {
        __half* outp = (z == 0) ? g_Qp : g_Kp;
        #pragma unroll
        for (int mi = 0; mi < 2; mi++) {
            int r0 = m0 + wm * 32 + mi * 16 + g;
            float mk0 = g_mask[r0]     ? 1.f : 0.f;
            float mk1 = g_mask[r0 + 8] ? 1.f : 0.f;
            #pragma unroll
            for (int ni = 0; ni < 8; ni++) {
                int col = n0 + wn * 64 + ni * 8 + tig * 2;
                float b0v = bias[col], b1v = bias[col + 1];
                *(__half2*)(outp + (size_t)r0 * 512 + col) =
                    __floats2half2_rn((R.c[mi][ni][0] + b0v) * mk0,
                                      (R.c[mi][ni][1] + b1v) * mk0);
                *(__half2*)(outp + (size_t)(r0 + 8) * 512 + col) =
                    __floats2half2_rn((R.c[mi][ni][2] + b0v) * mk1,
                                      (R.c[mi][ni][3] + b1v) * mk1);
            }
        }
    } else {
        #pragma unroll
        for (int mi = 0; mi < 2; mi++) {
            int r0 = m0 + wm * 32 + mi * 16 + g;
            int bidx = r0 >> 10, s_ = r0 & 1023;
            float mk0 = g_mask[r0]     ? 1.f : 0.f;
            float mk1 = g_mask[r0 + 8] ? 1.f : 0.f;
            #pragma unroll
            for (int ni = 0; ni < 8; ni++) {
                int col = n0 + wn * 64 + ni * 8 + tig * 2;
                int h_ = col >> 6, dl = col & 63;
                float b0v = bias[col], b1v = bias[col + 1];
                __half* base = g_Vh + ((size_t)(bidx * 8 + h_) * 1024 + s_) * 64 + dl;
                *(__half2*)base = __floats2half2_rn((R.c[mi][ni][0] + b0v) * mk0,
                                                    (R.c[mi][ni][1] + b1v) * mk0);
                *(__half2*)(base + 8 * 64) = __floats2half2_rn((R.c[mi][ni][2] + b0v) * mk1,
                                                               (R.c[mi][ni][3] + b1v) * mk1);
            }
        }
    }
}

// ---------------- output GEMM ----------------
__global__ __launch_bounds__(256, 2)
void k_out(const float* __restrict__ bo, float* __restrict__ out) {
    extern __shared__ __half smh[];
    int n0 = blockIdx.x * 128, m0 = blockIdx.y * 128;
    int tid = threadIdx.x;
    int wid = tid >> 5, lane = tid & 31, g = lane >> 2, tig = lane & 3;
    int wm = wid >> 1, wn = wid & 1;

    GemmOut R;
    gemm_body(g_aon, g_Wt + (size_t)3 * DD * DD, m0, n0, smh, R);

    #pragma unroll
    for (int mi = 0; mi < 2; mi++) {
        int r0 = m0 + wm * 32 + mi * 16 + g;
        #pragma unroll
        for (int ni = 0; ni < 8; ni++) {
            int col = n0 + wn * 64 + ni * 8 + tig * 2;
            float b0v = bo[col], b1v = bo[col + 1];
            float2 a0 = *(const float2*)(g_ao + (size_t)r0 * 512 + col);
            float2 a1 = *(const float2*)(g_ao + (size_t)(r0 + 8) * 512 + col);
            float2 o0 = make_float2(a0.x + fmaxf(R.c[mi][ni][0] + b0v, 0.f),
                                    a0.y + fmaxf(R.c[mi][ni][1] + b1v, 0.f));
            float2 o1 = make_float2(a1.x + fmaxf(R.c[mi][ni][2] + b0v, 0.f),
                                    a1.y + fmaxf(R.c[mi][ni][3] + b1v, 0.f));
            *(float2*)(out + (size_t)r0 * 512 + col)       = o0;
            *(float2*)(out + (size_t)(r0 + 8) * 512 + col) = o1;
        }
    }
}

// ---------------- attention: all-fp16, 64 q-rows ----------------
// smem (words): scH 33024 | kvb 4*2304 | qsH 2304 | red 32 | part 256 | invS 64
__global__ __launch_bounds__(512)
void k_attn(const float* __restrict__ Q, float* __restrict__ w_out) {
    extern __shared__ float sm[];
    __half* scH  = (__half*)sm;                 // 64 x 1032 fp16 exp values
    float*  kvb  = sm + 33024;                  // 4 x 2304 (64 rows x 72 halves each)
    __half* qsH  = (__half*)(kvb + 4 * KVW);    // 64 x 72 fp16 Q tile
    float*  red  = kvb + 4 * KVW + 2304;        // 32
    float*  part = red + 32;                    // 64*4
    float*  invS = part + 256;                  // 64

    int tid = threadIdx.x;
    int wid = tid >> 5, lane = tid & 31, g = lane >> 2, tig = lane & 3;
    int r8 = lane & 7, kh2 = (lane >> 3) & 1, kh4 = (lane >> 4) & 1;
    int bh = blockIdx.y, b = bh >> 3, h = bh & 7;
    int q0 = blockIdx.x * 64;
    size_t baseQ = ((size_t)b * SS + q0) * DD + h * HD;   // halves into g_Qp
    size_t baseK = ((size_t)b * SS) * DD + h * HD;        // halves into g_Kp
    size_t baseQf = baseQ;                                 // same indexing for fp32 Q/g_ao
    const __half* Vh = g_Vh + (size_t)bh * SS * HD;
    const int bS = b * SS;

    unsigned uKV[4];
    #pragma unroll
    for (int i = 0; i < 4; i++) uKV[i] = cvta_s(kvb + i * KVW);
    unsigned uQS = cvta_s(qsH), uSC = cvta_s(scH);

    // K prologue: chunks 0..2 (64 keys x 64 d fp16, stride 144 B)
    #pragma unroll
    for (int p = 0; p < 3; p++) {
        int row = tid >> 3, c8 = tid & 7;
        CP16(uKV[p] + row * 144 + c8 * 16,
             g_Kp + baseK + (size_t)(p * 64 + row) * 512 + c8 * 8);
        CP_COMMIT();
    }

    // q tile 64x64 fp16 -> smem
    {
        int r = tid >> 3, c8 = tid & 7;
        *(uint4*)(qsH + r * 72 + c8 * 8) =
            *(const uint4*)(g_Qp + baseQ + (size_t)r * 512 + c8 * 8);
    }
    __syncthreads();

    // warp layout: 16 warps = 4 m-groups x 4 n-slots
    int nslot = wid & 3, mw = wid >> 2;
    unsigned areg[4][4];   // 4 k16-steps
    {
        unsigned base = uQS + (unsigned)((mw * 16 + r8 + kh2 * 8) * 144 + kh4 * 16);
        #pragma unroll
        for (int ks = 0; ks < 4; ks++)
            ldsm4(base + ks * 32, areg[ks][0], areg[ks][1], areg[ks][2], areg[ks][3]);
    }

    // ---- scores: 16 chunks of 64 keys; per warp m16 x n16; fp16 mma; exp fused ----
    float rs0 = 0.f, rs1 = 0.f;
    unsigned offKB = (unsigned)((nslot * 16 + r8 + kh4 * 8) * 144 + kh2 * 16);
    for (int kt = 0; kt < 16; kt++) {
        CP_WAIT2();
        __syncthreads();
        if (kt + 3 < 16) {
            unsigned nxt = uKV[(kt + 3) & 3];
            int row = tid >> 3, c8 = tid & 7;
            CP16(nxt + row * 144 + c8 * 16,
                 g_Kp + baseK + (size_t)((kt + 3) * 64 + row) * 512 + c8 * 8);
        }
        CP_COMMIT();

        unsigned uKVf = uKV[kt & 3];
        float cc[2][4];
        #pragma unroll
        for (int nf = 0; nf < 2; nf++)
            #pragma unroll
            for (int j = 0; j < 4; j++) cc[nf][j] = 0.f;

        #pragma unroll
        for (int ks = 0; ks < 4; ks++) {
            unsigned b0, b1, b2, b3;
            ldsm4(uKVf + offKB + ks * 32, b0, b1, b2, b3);
            mma_h16(cc[0], areg[ks][0], areg[ks][1], areg[ks][2], areg[ks][3], b0, b1);
            mma_h16(cc[1], areg[ks][0], areg[ks][1], areg[ks][2], areg[ks][3], b2, b3);
        }
        #pragma unroll
        for (int nf = 0; nf < 2; nf++) {
            int gc = kt * 64 + nslot * 16 + nf * 8 + tig * 2;
            bool k0v = g_mask[bS + gc] != 0;
            bool k1v = g_mask[bS + gc + 1] != 0;
            float p0 = k0v ? __expf(cc[nf][0] * 0.125f) : 0.f;
            float p1 = k1v ? __expf(cc[nf][1] * 0.125f) : 0.f;
            float p2 = k0v ? __expf(cc[nf][2] * 0.125f) : 0.f;
            float p3 = k1v ? __expf(cc[nf][3] * 0.125f) : 0.f;
            rs0 += p0 + p1;
            rs1 += p2 + p3;
            int r = mw * 16 + g;
            *(__half2*)&scH[r * SCPH + gc]       = __floats2half2_rn(p0, p1);
            *(__half2*)&scH[(r + 8) * SCPH + gc] = __floats2half2_rn(p2, p3);
        }
    }
    rs0 += __shfl_xor_sync(0xffffffffu, rs0, 1);
    rs0 += __shfl_xor_sync(0xffffffffu, rs0, 2);
    rs1 += __shfl_xor_sync(0xffffffffu, rs1, 1);
    rs1 += __shfl_xor_sync(0xffffffffu, rs1, 2);
    if (tig == 0) {
        part[(mw * 16 + g) * 4 + nslot]     = rs0;
        part[(mw * 16 + g + 8) * 4 + nslot] = rs1;
    }

    // V prologue: chunks 0..2 (64 s-rows x 64 d fp16, stride 144 B)
    #pragma unroll
    for (int p = 0; p < 3; p++) {
        int row = tid >> 3, c8 = tid & 7;
        CP16(uKV[p] + row * 144 + c8 * 16,
             Vh + ((size_t)(p * 64 + row)) * 64 + c8 * 8);
        CP_COMMIT();
    }
    __syncthreads();   // panel + part visible

    // ---- w pass: w = fp16(p) * inv; compute invS ----
    {
        int row = tid >> 3, l = tid & 7;
        const float* pr = part + row * 4;
        float sum = pr[0] + pr[1] + pr[2] + pr[3];
        float inv = g_mask[bS + q0 + row] ? (1.0f / sum) : 0.f;
        if (l == 0) invS[row] = inv;
        float* wrow = w_out + ((size_t)bh * SS + q0 + row) * SS;
        const char* prow = (const char*)scH + row * (SCPH * 2);
        #pragma unroll
        for (int j = 0; j < 16; j++) {
            int e = l + 8 * j;
            uint4 u = *(const uint4*)(prow + e * 16);
            const __half2* hp = (const __half2*)&u;
            float2 f0 = __half22float2(hp[0]);
            float2 f1 = __half22float2(hp[1]);
            float2 f2 = __half22float2(hp[2]);
            float2 f3 = __half22float2(hp[3]);
            float4 o0 = make_float4(f0.x * inv, f0.y * inv, f1.x * inv, f1.y * inv);
            float4 o1 = make_float4(f2.x * inv, f2.y * inv, f3.x * inv, f3.y * inv);
            *(float4*)(wrow + e * 8)     = o0;
            *(float4*)(wrow + e * 8 + 4) = o1;
        }
    }

    // ---- attnV: fp16 m16n8k16; 16 chunks; warps 4m x 4n; no k-split ----
    int nsl2 = wid & 3, mw2 = wid >> 2;
    unsigned paA = uSC + (unsigned)((mw2 * 16 + r8 + kh2 * 8) * (SCPH * 2) + kh4 * 16);
    unsigned pbN = (unsigned)((nsl2 * 16 + kh4 * 8) * 2);
    int rowVk = r8 + kh2 * 8;

    float acc[2][4];
    #pragma unroll
    for (int nf = 0; nf < 2; nf++)
        #pragma unroll
        for (int j = 0; j < 4; j++) acc[nf][j] = 0.f;

    for (int vt = 0; vt < 16; vt++) {
        CP_WAIT2();
        __syncthreads();
        if (vt + 3 < 16) {
            unsigned nxt = uKV[(vt + 3) & 3];
            int row = tid >> 3, c8 = tid & 7;
            CP16(nxt + row * 144 + c8 * 16,
                 Vh + ((size_t)((vt + 3) * 64 + row)) * 64 + c8 * 8);
        }
        CP_COMMIT();

        unsigned uKVf = uKV[vt & 3];
        #pragma unroll
        for (int ks = 0; ks < 4; ks++) {
            unsigned a0, a1, a2, a3, b0, b1, b2, b3;
            ldsm4(paA + vt * 128 + ks * 32, a0, a1, a2, a3);
            ldsm4t(uKVf + (ks * 16 + rowVk) * 144 + pbN, b0, b1, b2, b3);
            mma_h16(acc[0], a0, a1, a2, a3, b0, b1);
            mma_h16(acc[1], a0, a1, a2, a3, b2, b3);
        }
    }
    __syncthreads();

    // ---- store scaled attn into kvb (free), then epilogue ----
    {
        float* at = kvb;   // 64 x 68 fp32
        int r = mw2 * 16 + g;
        float i0 = invS[r], i1 = invS[r + 8];
        #pragma unroll
        for (int nf = 0; nf < 2; nf++) {
            int col = nsl2 * 16 + nf * 8 + tig * 2;
            *(float2*)&at[r * 68 + col]       = make_float2(acc[nf][0] * i0, acc[nf][1] * i0);
            *(float2*)&at[(r + 8) * 68 + col] = make_float2(acc[nf][2] * i1, acc[nf][3] * i1);
        }
    }
    __syncthreads();

    // ---- epilogue: attn_out = attn + Q; stats2 ----
    {
        float* at = kvb;
        float t1 = 0.f, t2 = 0.f;
        #pragma unroll
        for (int i = 0; i < 2; i++) {
            int f = tid + 512 * i;
            int r = f >> 4, c4 = f & 15;
            float4 a = *(const float4*)&at[r * 68 + c4 * 4];
            size_t gaddr = baseQf + (size_t)r * DD + c4 * 4;
            float4 q4 = *(const float4*)(Q + gaddr);
            float4 o = make_float4(a.x + q4.x, a.y + q4.y, a.z + q4.z, a.w + q4.w);
            *(float4*)(g_ao + gaddr) = o;
            t1 += o.x + o.y + o.z + o.w;
            t2 += o.x*o.x + o.y*o.y + o.z*o.z + o.w*o.w;
        }
        #pragma unroll
        for (int off = 16; off > 0; off >>= 1) {
            t1 += __shfl_xor_sync(0xffffffffu, t1, off);
            t2 += __shfl_xor_sync(0xffffffffu, t2, off);
        }
        if (lane == 0) { red[wid] = t1; red[16 + wid] = t2; }
    }
    __syncthreads();
    if (tid == 0) {
        float S1 = 0.f, S2 = 0.f;
        #pragma unroll
        for (int i = 0; i < 16; i++) { S1 += red[i]; S2 += red[16 + i]; }
        atomicAdd(&g_sum2[b], S1);
        atomicAdd(&g_sq2[b], S2);
    }
}

// ---------------- launch ----------------
extern "C" void kernel_launch(void* const* d_in, const int* in_sizes, int n_in,
                              void* d_out, int out_size) {
    const float* Q  = (const float*)d_in[0];
    const float* Wq = (const float*)d_in[1];
    const float* bq = (const float*)d_in[2];
    const float* Wk = (const float*)d_in[3];
    const float* bk = (const float*)d_in[4];
    const float* Wv = (const float*)d_in[5];
    const float* bv = (const float*)d_in[6];
    const float* Wo = (const float*)d_in[7];
    const float* bo = (const float*)d_in[8];

    float* out = (float*)d_out;
    float* w   = out + (size_t)BB * SS * DD;

    float*  g_ao_ptr;  cudaGetSymbolAddress((void**)&g_ao_ptr,  g_ao);
    __half* g_Qn_ptr;  cudaGetSymbolAddress((void**)&g_Qn_ptr,  g_Qn);
    __half* g_aon_ptr; cudaGetSymbolAddress((void**)&g_aon_ptr, g_aon);

    const int GEMM_SMEM = 4 * 10240;                                  // 40960 B
    const int ATTN_SMEM = (33024 + 4 * KVW + 2304 + 32 + 256 + 64) * 4;  // ~179.5 KB
    cudaFuncSetAttribute(k_qkv,  cudaFuncAttributeMaxDynamicSharedMemorySize, GEMM_SMEM);
    cudaFuncSetAttribute(k_out,  cudaFuncAttributeMaxDynamicSharedMemorySize, GEMM_SMEM);
    cudaFuncSetAttribute(k_attn, cudaFuncAttributeMaxDynamicSharedMemorySize, ATTN_SMEM);

    k_cvtW<<<dim3(16, 16, 4), 256>>>(Wq, Wk, Wv, Wo);
    k_maskstats<<<NROWS, 128>>>(Q);
    k_norm<<<NROWS, 128>>>(Q, g_Qn_ptr, 0);
    k_qkv<<<dim3(4, 64, 3), 256, GEMM_SMEM>>>(bq, bk, bv);
    k_attn<<<dim3(16, 64), 512, ATTN_SMEM>>>(Q, w);
    k_norm<<<NROWS, 128>>>(g_ao_ptr, g_aon_ptr, 1);
    k_out<<<dim3(4, 64), 256, GEMM_SMEM>>>(bo, out);
}

// round 14
// speedup vs baseline: 1.4862x; 1.0073x over previous
#include <cuda_runtime.h>
#include <cuda_fp16.h>
#include <math.h>

#define BB 8
#define SS 1024
#define DD 512
#define HD 64
#define NROWS (BB*SS)
#define EPSV 1e-5f
#define SCPH 1032    // fp16 panel stride (halves); 1032*2 mod 128 = 16 -> ldsm conflict-free
#define KVW 2304     // words per KV buffer (64 rows x 72 halves = 9216 B)

// ---------------- scratch ----------------
__device__ __half g_Qp[NROWS*DD];   // fp16 Q-proj [s][d]
__device__ __half g_Kp[NROWS*DD];   // fp16 K-proj [s][d]
__device__ __half g_Vh[NROWS*DD];   // fp16 V: [bh][s][d]
__device__ float  g_ao[NROWS*DD];   // exact fp32
__device__ __half g_Qn[NROWS*DD];   // normed Q fp16
__device__ __half g_aon[NROWS*DD];  // normed ao fp16
__device__ __half g_Wt[4*DD*DD];    // fp16 weights TRANSPOSED: [n][k]
__device__ float  g_sum1[BB], g_sq1[BB], g_sum2[BB], g_sq2[BB];
__device__ int    g_cnt[BB];
__device__ int    g_mask[NROWS];

// ---------------- helpers ----------------
__device__ __forceinline__ void mma_h16(float* c, unsigned a0, unsigned a1, unsigned a2,
                                        unsigned a3, unsigned b0, unsigned b1) {
    asm volatile(
        "mma.sync.aligned.m16n8k16.row.col.f32.f16.f16.f32 "
        "{%0,%1,%2,%3},{%4,%5,%6,%7},{%8,%9},{%0,%1,%2,%3};"
        : "+f"(c[0]), "+f"(c[1]), "+f"(c[2]), "+f"(c[3])
        : "r"(a0), "r"(a1), "r"(a2), "r"(a3), "r"(b0), "r"(b1));
}
__device__ __forceinline__ void ldsm4(unsigned addr, unsigned& r0, unsigned& r1,
                                      unsigned& r2, unsigned& r3) {
    asm volatile("ldmatrix.sync.aligned.m8n8.x4.shared.b16 {%0,%1,%2,%3}, [%4];"
                 : "=r"(r0), "=r"(r1), "=r"(r2), "=r"(r3) : "r"(addr));
}
__device__ __forceinline__ void ldsm4t(unsigned addr, unsigned& r0, unsigned& r1,
                                       unsigned& r2, unsigned& r3) {
    asm volatile("ldmatrix.sync.aligned.m8n8.x4.trans.shared.b16 {%0,%1,%2,%3}, [%4];"
                 : "=r"(r0), "=r"(r1), "=r"(r2), "=r"(r3) : "r"(addr));
}
__device__ __forceinline__ unsigned cvta_s(const void* p) {
    return (unsigned)__cvta_generic_to_shared(p);
}
#define CP16(dst_u32, src_ptr) \
    asm volatile("cp.async.cg.shared.global [%0], [%1], 16;" :: "r"(dst_u32), "l"(src_ptr))
#define CP_COMMIT() asm volatile("cp.async.commit_group;")
#define CP_WAIT2()  asm volatile("cp.async.wait_group 2;")
#define CP_WAIT0()  asm volatile("cp.async.wait_group 0;")

// ---------------- tiny kernels ----------------
__global__ void k_cvtW(const float* __restrict__ Wq, const float* __restrict__ Wk,
                       const float* __restrict__ Wv, const float* __restrict__ Wo) {
    if (blockIdx.x == 0 && blockIdx.y == 0 && blockIdx.z == 0 && threadIdx.x < BB) {
        int t = threadIdx.x;
        g_sum1[t]=0.f; g_sq1[t]=0.f; g_sum2[t]=0.f; g_sq2[t]=0.f; g_cnt[t]=0;
    }
    __shared__ float t[32][33];
    const float* src = (blockIdx.z == 0) ? Wq : (blockIdx.z == 1) ? Wk :
                       (blockIdx.z == 2) ? Wv : Wo;
    __half* dst = g_Wt + (size_t)blockIdx.z * DD * DD;
    int k0 = blockIdx.x * 32, n0 = blockIdx.y * 32;
    int c = threadIdx.x & 31, r0 = threadIdx.x >> 5;
    #pragma unroll
    for (int i = 0; i < 4; i++) {
        int r = r0 + 8 * i;
        t[r][c] = src[(size_t)(k0 + r) * DD + n0 + c];
    }
    __syncthreads();
    #pragma unroll
    for (int i = 0; i < 4; i++) {
        int r = r0 + 8 * i;
        dst[(size_t)(n0 + r) * DD + k0 + c] = __float2half_rn(t[c][r]);
    }
}

__global__ void k_maskstats(const float* __restrict__ Q) {
    int row = blockIdx.x;
    int t = threadIdx.x;
    float4 q = ((const float4*)(Q + (size_t)row * DD))[t];
    bool nz = (q.x != 0.f) || (q.y != 0.f) || (q.z != 0.f) || (q.w != 0.f);
    float s  = q.x + q.y + q.z + q.w;
    float s2 = q.x*q.x + q.y*q.y + q.z*q.z + q.w*q.w;
    int valid = __syncthreads_or(nz ? 1 : 0);
    #pragma unroll
    for (int o = 16; o > 0; o >>= 1) {
        s  += __shfl_xor_sync(0xffffffffu, s,  o);
        s2 += __shfl_xor_sync(0xffffffffu, s2, o);
    }
    __shared__ float rs[4], rs2[4];
    if ((t & 31) == 0) { rs[t >> 5] = s; rs2[t >> 5] = s2; }
    __syncthreads();
    if (t == 0) {
        g_mask[row] = valid;
        if (valid) {
            int b = row >> 10;
            atomicAdd(&g_cnt[b], 1);
            atomicAdd(&g_sum1[b], rs[0]+rs[1]+rs[2]+rs[3]);
            atomicAdd(&g_sq1[b],  rs2[0]+rs2[1]+rs2[2]+rs2[3]);
        }
    }
}

// normalize + fp16 convert
__global__ void k_norm(const float* __restrict__ src, __half* __restrict__ dst, int which) {
    int row = blockIdx.x;
    int t = threadIdx.x;
    int b = row >> 10;
    float cntD = (float)g_cnt[b] * (float)DD;
    float sum = which ? g_sum2[b] : g_sum1[b];
    float sq  = which ? g_sq2[b]  : g_sq1[b];
    float mean = (cntD > 0.f) ? sum / cntD : 0.f;
    float var  = (cntD > 0.f) ? sq / cntD - mean * mean : 0.f;
    if (var < 0.f) var = 0.f;
    float rstd = rsqrtf(var + EPSV);
    float sc = g_mask[row] ? rstd : 0.f;
    float mm = mean * sc;
    float4 v = ((const float4*)(src + (size_t)row * DD))[t];
    __half2 h0 = __floats2half2_rn(fmaf(v.x, sc, -mm), fmaf(v.y, sc, -mm));
    __half2 h1 = __floats2half2_rn(fmaf(v.z, sc, -mm), fmaf(v.w, sc, -mm));
    uint2 u = make_uint2(*(unsigned*)&h0, *(unsigned*)&h1);
    *(uint2*)(dst + (size_t)row * DD + t * 4) = u;
}

// ============ fp16 GEMM body: BM=128, BN=128, BK=32; 4-stage pipeline ============
// A [m][k] fp16 stride 40 halves; B [n][k] fp16 stride 40 halves. 4 buffers each.
struct GemmOut { float c[2][8][4]; };

__device__ __forceinline__ void gemm_body(
    const __half* __restrict__ Asrc, const __half* __restrict__ Bsrc,
    int m0, int n0, __half* smq, GemmOut& R)
{
    unsigned uA[4], uB[4];
    unsigned base = cvta_s(smq);
    #pragma unroll
    for (int i = 0; i < 4; i++) {
        uA[i] = base + (unsigned)i * 10240u;
        uB[i] = base + 40960u + (unsigned)i * 10240u;
    }

    int tid = threadIdx.x;
    int wid = tid >> 5, lane = tid & 31;
    int wm = wid >> 1, wn = wid & 1;
    int r8 = lane & 7, kh2 = (lane >> 3) & 1, kh4 = (lane >> 4) & 1;

    unsigned offA0 = (unsigned)((wm * 32 +      r8 + kh2 * 8) * 80 + kh4 * 16);
    unsigned offA1 = offA0 + 16 * 80;
    unsigned offB[4];
    #pragma unroll
    for (int nq = 0; nq < 4; nq++)
        offB[nq] = (unsigned)((wn * 64 + nq * 16 + r8 + kh4 * 8) * 80 + kh2 * 16);

    #pragma unroll
    for (int mi = 0; mi < 2; mi++)
        #pragma unroll
        for (int ni = 0; ni < 8; ni++)
            #pragma unroll
            for (int j = 0; j < 4; j++) R.c[mi][ni][j] = 0.f;

    // prologue: chunks 0..2
    #pragma unroll
    for (int p = 0; p < 3; p++) {
        #pragma unroll
        for (int i = 0; i < 2; i++) {
            int f = tid + 256 * i;
            int row = f >> 2, c4 = f & 3;
            CP16(uA[p] + row * 80 + c4 * 16, Asrc + (size_t)(m0 + row) * 512 + p * 32 + c4 * 8);
            CP16(uB[p] + row * 80 + c4 * 16, Bsrc + (size_t)(n0 + row) * 512 + p * 32 + c4 * 8);
        }
        CP_COMMIT();
    }

    for (int kc = 0; kc < 16; kc++) {
        CP_WAIT2();
        __syncthreads();
        if (kc + 3 < 16) {
            int j = (kc + 3) & 3;
            int k0 = (kc + 3) * 32;
            #pragma unroll
            for (int i = 0; i < 2; i++) {
                int f = tid + 256 * i;
                int row = f >> 2, c4 = f & 3;
                CP16(uA[j] + row * 80 + c4 * 16, Asrc + (size_t)(m0 + row) * 512 + k0 + c4 * 8);
                CP16(uB[j] + row * 80 + c4 * 16, Bsrc + (size_t)(n0 + row) * 512 + k0 + c4 * 8);
            }
        }
        CP_COMMIT();

        unsigned uAf = uA[kc & 3];
        unsigned uBf = uB[kc & 3];
        #pragma unroll
        for (int s = 0; s < 2; s++) {
            unsigned a[2][4], bb[8][2];
            ldsm4(uAf + offA0 + s * 32, a[0][0], a[0][1], a[0][2], a[0][3]);
            ldsm4(uAf + offA1 + s * 32, a[1][0], a[1][1], a[1][2], a[1][3]);
            #pragma unroll
            for (int nq = 0; nq < 4; nq++)
                ldsm4(uBf + offB[nq] + s * 32,
                      bb[nq*2][0], bb[nq*2][1], bb[nq*2+1][0], bb[nq*2+1][1]);
            #pragma unroll
            for (int mi = 0; mi < 2; mi++)
                #pragma unroll
                for (int ni = 0; ni < 8; ni++)
                    mma_h16(R.c[mi][ni], a[mi][0], a[mi][1], a[mi][2], a[mi][3],
                            bb[ni][0], bb[ni][1]);
        }
    }
}

// ---------------- QKV ----------------
__global__ __launch_bounds__(256, 2)
void k_qkv(const float* __restrict__ bq, const float* __restrict__ bk,
           const float* __restrict__ bv) {
    extern __shared__ __half smh[];
    int z = blockIdx.z;
    const float* bias = (z == 0) ? bq : (z == 1) ? bk : bv;
    const __half* Bsrc = g_Wt + (size_t)z * DD * DD;

    int n0 = blockIdx.x * 128, m0 = blockIdx.y * 128;
    int tid = threadIdx.x;
    int wid = tid >> 5, lane = tid & 31, g = lane >> 2, tig = lane & 3;
    int wm = wid >> 1, wn = wid & 1;

    GemmOut R;
    gemm_body(g_Qn, Bsrc, m0, n0, smh, R);

    if (z < 2) {
        __half* outp = (z == 0) ? g_Qp : g_Kp;
        #pragma unroll
        for (int mi = 0; mi < 2; mi++) {
            int r0 = m0 + wm * 32 + mi * 16 + g;
            float mk0 = g_mask[r0]     ? 1.f : 0.f;
            float mk1 = g_mask[r0 + 8] ? 1.f : 0.f;
            #pragma unroll
            for (int ni = 0; ni < 8; ni++) {
                int col = n0 + wn * 64 + ni * 8 + tig * 2;
                float b0v = bias[col], b1v = bias[col + 1];
                *(__half2*)(outp + (size_t)r0 * 512 + col) =
                    __floats2half2_rn((R.c[mi][ni][0] + b0v) * mk0,
                                      (R.c[mi][ni][1] + b1v) * mk0);
                *(__half2*)(outp + (size_t)(r0 + 8) * 512 + col) =
                    __floats2half2_rn((R.c[mi][ni][2] + b0v) * mk1,
                                      (R.c[mi][ni][3] + b1v) * mk1);
            }
        }
    } else {
        #pragma unroll
        for (int mi = 0; mi < 2; mi++) {
            int r0 = m0 + wm * 32 + mi * 16 + g;
            int bidx = r0 >> 10, s_ = r0 & 1023;
            float mk0 = g_mask[r0]     ? 1.f : 0.f;
            float mk1 = g_mask[r0 + 8] ? 1.f : 0.f;
            #pragma unroll
            for (int ni = 0; ni < 8; ni++) {
                int col = n0 + wn * 64 + ni * 8 + tig * 2;
                int h_ = col >> 6, dl = col & 63;
                float b0v = bias[col], b1v = bias[col + 1];
                __half* base = g_Vh + ((size_t)(bidx * 8 + h_) * 1024 + s_) * 64 + dl;
                *(__half2*)base = __floats2half2_rn((R.c[mi][ni][0] + b0v) * mk0,
                                                    (R.c[mi][ni][1] + b1v) * mk0);
                *(__half2*)(base + 8 * 64) = __floats2half2_rn((R.c[mi][ni][2] + b0v) * mk1,
                                                               (R.c[mi][ni][3] + b1v) * mk1);
            }
        }
    }
}

// ---------------- output GEMM ----------------
__global__ __launch_bounds__(256, 2)
void k_out(const float* __restrict__ bo, float* __restrict__ out) {
    extern __shared__ __half smh[];
    int n0 = blockIdx.x * 128, m0 = blockIdx.y * 128;
    int tid = threadIdx.x;
    int wid = tid >> 5, lane = tid & 31, g = lane >> 2, tig = lane & 3;
    int wm = wid >> 1, wn = wid & 1;

    GemmOut R;
    gemm_body(g_aon, g_Wt + (size_t)3 * DD * DD, m0, n0, smh, R);

    #pragma unroll
    for (int mi = 0; mi < 2; mi++) {
        int r0 = m0 + wm * 32 + mi * 16 + g;
        #pragma unroll
        for (int ni = 0; ni < 8; ni++) {
            int col = n0 + wn * 64 + ni * 8 + tig * 2;
            float b0v = bo[col], b1v = bo[col + 1];
            float2 a0 = *(const float2*)(g_ao + (size_t)r0 * 512 + col);
            float2 a1 = *(const float2*)(g_ao + (size_t)(r0 + 8) * 512 + col);
            float2 o0 = make_float2(a0.x + fmaxf(R.c[mi][ni][0] + b0v, 0.f),
                                    a0.y + fmaxf(R.c[mi][ni][1] + b1v, 0.f));
            float2 o1 = make_float2(a1.x + fmaxf(R.c[mi][ni][2] + b0v, 0.f),
                                    a1.y + fmaxf(R.c[mi][ni][3] + b1v, 0.f));
            *(float2*)(out + (size_t)r0 * 512 + col)       = o0;
            *(float2*)(out + (size_t)(r0 + 8) * 512 + col) = o1;
        }
    }
}

// ---------------- attention: all-fp16, 64 q-rows (R13 verbatim) ----------------
__global__ __launch_bounds__(512)
void k_attn(const float* __restrict__ Q, float* __restrict__ w_out) {
    extern __shared__ float sm[];
    __half* scH  = (__half*)sm;                 // 64 x 1032 fp16 exp values
    float*  kvb  = sm + 33024;                  // 4 x 2304 (64 rows x 72 halves each)
    __half* qsH  = (__half*)(kvb + 4 * KVW);    // 64 x 72 fp16 Q tile
    float*  red  = kvb + 4 * KVW + 2304;        // 32
    float*  part = red + 32;                    // 64*4
    float*  invS = part + 256;                  // 64

    int tid = threadIdx.x;
    int wid = tid >> 5, lane = tid & 31, g = lane >> 2, tig = lane & 3;
    int r8 = lane & 7, kh2 = (lane >> 3) & 1, kh4 = (lane >> 4) & 1;
    int bh = blockIdx.y, b = bh >> 3, h = bh & 7;
    int q0 = blockIdx.x * 64;
    size_t baseQ = ((size_t)b * SS + q0) * DD + h * HD;
    size_t baseK = ((size_t)b * SS) * DD + h * HD;
    const __half* Vh = g_Vh + (size_t)bh * SS * HD;
    const int bS = b * SS;

    unsigned uKV[4];
    #pragma unroll
    for (int i = 0; i < 4; i++) uKV[i] = cvta_s(kvb + i * KVW);
    unsigned uQS = cvta_s(qsH), uSC = cvta_s(scH);

    // K prologue: chunks 0..2 (64 keys x 64 d fp16, stride 144 B)
    #pragma unroll
    for (int p = 0; p < 3; p++) {
        int row = tid >> 3, c8 = tid & 7;
        CP16(uKV[p] + row * 144 + c8 * 16,
             g_Kp + baseK + (size_t)(p * 64 + row) * 512 + c8 * 8);
        CP_COMMIT();
    }

    // q tile 64x64 fp16 -> smem
    {
        int r = tid >> 3, c8 = tid & 7;
        *(uint4*)(qsH + r * 72 + c8 * 8) =
            *(const uint4*)(g_Qp + baseQ + (size_t)r * 512 + c8 * 8);
    }
    __syncthreads();

    // warp layout: 16 warps = 4 m-groups x 4 n-slots
    int nslot = wid & 3, mw = wid >> 2;
    unsigned areg[4][4];
    {
        unsigned base = uQS + (unsigned)((mw * 16 + r8 + kh2 * 8) * 144 + kh4 * 16);
        #pragma unroll
        for (int ks = 0; ks < 4; ks++)
            ldsm4(base + ks * 32, areg[ks][0], areg[ks][1], areg[ks][2], areg[ks][3]);
    }

    // ---- scores: 16 chunks of 64 keys; per warp m16 x n16; fp16 mma; exp fused ----
    float rs0 = 0.f, rs1 = 0.f;
    unsigned offKB = (unsigned)((nslot * 16 + r8 + kh4 * 8) * 144 + kh2 * 16);
    for (int kt = 0; kt < 16; kt++) {
        CP_WAIT2();
        __syncthreads();
        if (kt + 3 < 16) {
            unsigned nxt = uKV[(kt + 3) & 3];
            int row = tid >> 3, c8 = tid & 7;
            CP16(nxt + row * 144 + c8 * 16,
                 g_Kp + baseK + (size_t)((kt + 3) * 64 + row) * 512 + c8 * 8);
        }
        CP_COMMIT();

        unsigned uKVf = uKV[kt & 3];
        float cc[2][4];
        #pragma unroll
        for (int nf = 0; nf < 2; nf++)
            #pragma unroll
            for (int j = 0; j < 4; j++) cc[nf][j] = 0.f;

        #pragma unroll
        for (int ks = 0; ks < 4; ks++) {
            unsigned b0, b1, b2, b3;
            ldsm4(uKVf + offKB + ks * 32, b0, b1, b2, b3);
            mma_h16(cc[0], areg[ks][0], areg[ks][1], areg[ks][2], areg[ks][3], b0, b1);
            mma_h16(cc[1], areg[ks][0], areg[ks][1], areg[ks][2], areg[ks][3], b2, b3);
        }
        #pragma unroll
        for (int nf = 0; nf < 2; nf++) {
            int gc = kt * 64 + nslot * 16 + nf * 8 + tig * 2;
            bool k0v = g_mask[bS + gc] != 0;
            bool k1v = g_mask[bS + gc + 1] != 0;
            float p0 = k0v ? __expf(cc[nf][0] * 0.125f) : 0.f;
            float p1 = k1v ? __expf(cc[nf][1] * 0.125f) : 0.f;
            float p2 = k0v ? __expf(cc[nf][2] * 0.125f) : 0.f;
            float p3 = k1v ? __expf(cc[nf][3] * 0.125f) : 0.f;
            rs0 += p0 + p1;
            rs1 += p2 + p3;
            int r = mw * 16 + g;
            *(__half2*)&scH[r * SCPH + gc]       = __floats2half2_rn(p0, p1);
            *(__half2*)&scH[(r + 8) * SCPH + gc] = __floats2half2_rn(p2, p3);
        }
    }
    rs0 += __shfl_xor_sync(0xffffffffu, rs0, 1);
    rs0 += __shfl_xor_sync(0xffffffffu, rs0, 2);
    rs1 += __shfl_xor_sync(0xffffffffu, rs1, 1);
    rs1 += __shfl_xor_sync(0xffffffffu, rs1, 2);
    if (tig == 0) {
        part[(mw * 16 + g) * 4 + nslot]     = rs0;
        part[(mw * 16 + g + 8) * 4 + nslot] = rs1;
    }

    // V prologue: chunks 0..2
    #pragma unroll
    for (int p = 0; p < 3; p++) {
        int row = tid >> 3, c8 = tid & 7;
        CP16(uKV[p] + row * 144 + c8 * 16,
             Vh + ((size_t)(p * 64 + row)) * 64 + c8 * 8);
        CP_COMMIT();
    }
    __syncthreads();   // panel + part visible

    // ---- w pass: w = fp16(p) * inv; compute invS ----
    {
        int row = tid >> 3, l = tid & 7;
        const float* pr = part + row * 4;
        float sum = pr[0] + pr[1] + pr[2] + pr[3];
        float inv = g_mask[bS + q0 + row] ? (1.0f / sum) : 0.f;
        if (l == 0) invS[row] = inv;
        float* wrow = w_out + ((size_t)bh * SS + q0 + row) * SS;
        const char* prow = (const char*)scH + row * (SCPH * 2);
        #pragma unroll
        for (int j = 0; j < 16; j++) {
            int e = l + 8 * j;
            uint4 u = *(const uint4*)(prow + e * 16);
            const __half2* hp = (const __half2*)&u;
            float2 f0 = __half22float2(hp[0]);
            float2 f1 = __half22float2(hp[1]);
            float2 f2 = __half22float2(hp[2]);
            float2 f3 = __half22float2(hp[3]);
            float4 o0 = make_float4(f0.x * inv, f0.y * inv, f1.x * inv, f1.y * inv);
            float4 o1 = make_float4(f2.x * inv, f2.y * inv, f3.x * inv, f3.y * inv);
            *(float4*)(wrow + e * 8)     = o0;
            *(float4*)(wrow + e * 8 + 4) = o1;
        }
    }

    // ---- attnV: fp16 m16n8k16; 16 chunks; warps 4m x 4n; no k-split ----
    int nsl2 = wid & 3, mw2 = wid >> 2;
    unsigned paA = uSC + (unsigned)((mw2 * 16 + r8 + kh2 * 8) * (SCPH * 2) + kh4 * 16);
    unsigned pbN = (unsigned)((nsl2 * 16 + kh4 * 8) * 2);
    int rowVk = r8 + kh2 * 8;

    float acc[2][4];
    #pragma unroll
    for (int nf = 0; nf < 2; nf++)
        #pragma unroll
        for (int j = 0; j < 4; j++) acc[nf][j] = 0.f;

    for (int vt = 0; vt < 16; vt++) {
        CP_WAIT2();
        __syncthreads();
        if (vt + 3 < 16) {
            unsigned nxt = uKV[(vt + 3) & 3];
            int row = tid >> 3, c8 = tid & 7;
            CP16(nxt + row * 144 + c8 * 16,
                 Vh + ((size_t)((vt + 3) * 64 + row)) * 64 + c8 * 8);
        }
        CP_COMMIT();

        unsigned uKVf = uKV[vt & 3];
        #pragma unroll
        for (int ks = 0; ks < 4; ks++) {
            unsigned a0, a1, a2, a3, b0, b1, b2, b3;
            ldsm4(paA + vt * 128 + ks * 32, a0, a1, a2, a3);
            ldsm4t(uKVf + (ks * 16 + rowVk) * 144 + pbN, b0, b1, b2, b3);
            mma_h16(acc[0], a0, a1, a2, a3, b0, b1);
            mma_h16(acc[1], a0, a1, a2, a3, b2, b3);
        }
    }
    __syncthreads();

    // ---- store scaled attn into kvb (free), then epilogue ----
    {
        float* at = kvb;
        int r = mw2 * 16 + g;
        float i0 = invS[r], i1 = invS[r + 8];
        #pragma unroll
        for (int nf = 0; nf < 2; nf++) {
            int col = nsl2 * 16 + nf * 8 + tig * 2;
            *(float2*)&at[r * 68 + col]       = make_float2(acc[nf][0] * i0, acc[nf][1] * i0);
            *(float2*)&at[(r + 8) * 68 + col] = make_float2(acc[nf][2] * i1, acc[nf][3] * i1);
        }
    }
    __syncthreads();

    // ---- epilogue: attn_out = attn + Q; stats2 ----
    {
        float* at = kvb;
        float t1 = 0.f, t2 = 0.f;
        #pragma unroll
        for (int i = 0; i < 2; i++) {
            int f = tid + 512 * i;
            int r = f >> 4, c4 = f & 15;
            float4 a = *(const float4*)&at[r * 68 + c4 * 4];
            size_t gaddr = baseQ + (size_t)r * DD + c4 * 4;
            float4 q4 = *(const float4*)(Q + gaddr);
            float4 o = make_float4(a.x + q4.x, a.y + q4.y, a.z + q4.z, a.w + q4.w);
            *(float4*)(g_ao + gaddr) = o;
            t1 += o.x + o.y + o.z + o.w;
            t2 += o.x*o.x + o.y*o.y + o.z*o.z + o.w*o.w;
        }
        #pragma unroll
        for (int off = 16; off > 0; off >>= 1) {
            t1 += __shfl_xor_sync(0xffffffffu, t1, off);
            t2 += __shfl_xor_sync(0xffffffffu, t2, off);
        }
        if (lane == 0) { red[wid] = t1; red[16 + wid] = t2; }
    }
    __syncthreads();
    if (tid == 0) {
        float S1 = 0.f, S2 = 0.f;
        #pragma unroll
        for (int i = 0; i < 16; i++) { S1 += red[i]; S2 += red[16 + i]; }
        atomicAdd(&g_sum2[b], S1);
        atomicAdd(&g_sq2[b], S2);
    }
}

// ---------------- launch ----------------
extern "C" void kernel_launch(void* const* d_in, const int* in_sizes, int n_in,
                              void* d_out, int out_size) {
    const float* Q  = (const float*)d_in[0];
    const float* Wq = (const float*)d_in[1];
    const float* bq = (const float*)d_in[2];
    const float* Wk = (const float*)d_in[3];
    const float* bk = (const float*)d_in[4];
    const float* Wv = (const float*)d_in[5];
    const float* bv = (const float*)d_in[6];
    const float* Wo = (const float*)d_in[7];
    const float* bo = (const float*)d_in[8];

    float* out = (float*)d_out;
    float* w   = out + (size_t)BB * SS * DD;

    float*  g_ao_ptr;  cudaGetSymbolAddress((void**)&g_ao_ptr,  g_ao);
    __half* g_Qn_ptr;  cudaGetSymbolAddress((void**)&g_Qn_ptr,  g_Qn);
    __half* g_aon_ptr; cudaGetSymbolAddress((void**)&g_aon_ptr, g_aon);

    const int GEMM_SMEM = 8 * 10240;                                     // 81920 B
    const int ATTN_SMEM = (33024 + 4 * KVW + 2304 + 32 + 256 + 64) * 4;  // ~179.5 KB
    cudaFuncSetAttribute(k_qkv,  cudaFuncAttributeMaxDynamicSharedMemorySize, GEMM_SMEM);
    cudaFuncSetAttribute(k_out,  cudaFuncAttributeMaxDynamicSharedMemorySize, GEMM_SMEM);
    cudaFuncSetAttribute(k_attn, cudaFuncAttributeMaxDynamicSharedMemorySize, ATTN_SMEM);

    k_cvtW<<<dim3(16, 16, 4), 256>>>(Wq, Wk, Wv, Wo);
    k_maskstats<<<NROWS, 128>>>(Q);
    k_norm<<<NROWS, 128>>>(Q, g_Qn_ptr, 0);
    k_qkv<<<dim3(4, 64, 3), 256, GEMM_SMEM>>>(bq, bk, bv);
    k_attn<<<dim3(16, 64), 512, ATTN_SMEM>>>(Q, w);
    k_norm<<<NROWS, 128>>>(g_ao_ptr, g_aon_ptr, 1);
    k_out<<<dim3(4, 64), 256, GEMM_SMEM>>>(bo, out);
}

// round 15
// speedup vs baseline: 1.6137x; 1.0858x over previous
#include <cuda_runtime.h>
#include <cuda_fp16.h>
#include <math.h>

#define BB 8
#define SS 1024
#define DD 512
#define HD 64
#define NROWS (BB*SS)
#define EPSV 1e-5f
#define SCPH 1032    // fp16 panel stride (halves)
#define KVW 4608     // words per KV buffer (128 rows x 72 halves = 18432 B)

// ---------------- scratch ----------------
__device__ __half g_Qp[NROWS*DD];   // fp16 Q-proj [s][d]
__device__ __half g_Kp[NROWS*DD];   // fp16 K-proj [s][d]
__device__ __half g_Vh[NROWS*DD];   // fp16 V: [bh][s][d]
__device__ float  g_ao[NROWS*DD];   // exact fp32
__device__ __half g_Qn[NROWS*DD];   // normed Q fp16
__device__ __half g_aon[NROWS*DD];  // normed ao fp16
__device__ __half g_Wt[4*DD*DD];    // fp16 weights TRANSPOSED: [n][k]
__device__ float  g_sum1[BB], g_sq1[BB], g_sum2[BB], g_sq2[BB];
__device__ int    g_cnt[BB];
__device__ int    g_mask[NROWS];

// ---------------- helpers ----------------
__device__ __forceinline__ void mma_h16(float* c, unsigned a0, unsigned a1, unsigned a2,
                                        unsigned a3, unsigned b0, unsigned b1) {
    asm volatile(
        "mma.sync.aligned.m16n8k16.row.col.f32.f16.f16.f32 "
        "{%0,%1,%2,%3},{%4,%5,%6,%7},{%8,%9},{%0,%1,%2,%3};"
        : "+f"(c[0]), "+f"(c[1]), "+f"(c[2]), "+f"(c[3])
        : "r"(a0), "r"(a1), "r"(a2), "r"(a3), "r"(b0), "r"(b1));
}
__device__ __forceinline__ void ldsm4(unsigned addr, unsigned& r0, unsigned& r1,
                                      unsigned& r2, unsigned& r3) {
    asm volatile("ldmatrix.sync.aligned.m8n8.x4.shared.b16 {%0,%1,%2,%3}, [%4];"
                 : "=r"(r0), "=r"(r1), "=r"(r2), "=r"(r3) : "r"(addr));
}
__device__ __forceinline__ void ldsm4t(unsigned addr, unsigned& r0, unsigned& r1,
                                       unsigned& r2, unsigned& r3) {
    asm volatile("ldmatrix.sync.aligned.m8n8.x4.trans.shared.b16 {%0,%1,%2,%3}, [%4];"
                 : "=r"(r0), "=r"(r1), "=r"(r2), "=r"(r3) : "r"(addr));
}
__device__ __forceinline__ unsigned cvta_s(const void* p) {
    return (unsigned)__cvta_generic_to_shared(p);
}
#define CP16(dst_u32, src_ptr) \
    asm volatile("cp.async.cg.shared.global [%0], [%1], 16;" :: "r"(dst_u32), "l"(src_ptr))
#define CP_COMMIT() asm volatile("cp.async.commit_group;")
#define CP_WAIT2()  asm volatile("cp.async.wait_group 2;")
#define CP_WAIT0()  asm volatile("cp.async.wait_group 0;")

// ---------------- tiny kernels ----------------
__global__ void k_cvtW(const float* __restrict__ Wq, const float* __restrict__ Wk,
                       const float* __restrict__ Wv, const float* __restrict__ Wo) {
    if (blockIdx.x == 0 && blockIdx.y == 0 && blockIdx.z == 0 && threadIdx.x < BB) {
        int t = threadIdx.x;
        g_sum1[t]=0.f; g_sq1[t]=0.f; g_sum2[t]=0.f; g_sq2[t]=0.f; g_cnt[t]=0;
    }
    __shared__ float t[32][33];
    const float* src = (blockIdx.z == 0) ? Wq : (blockIdx.z == 1) ? Wk :
                       (blockIdx.z == 2) ? Wv : Wo;
    __half* dst = g_Wt + (size_t)blockIdx.z * DD * DD;
    int k0 = blockIdx.x * 32, n0 = blockIdx.y * 32;
    int c = threadIdx.x & 31, r0 = threadIdx.x >> 5;
    #pragma unroll
    for (int i = 0; i < 4; i++) {
        int r = r0 + 8 * i;
        t[r][c] = src[(size_t)(k0 + r) * DD + n0 + c];
    }
    __syncthreads();
    #pragma unroll
    for (int i = 0; i < 4; i++) {
        int r = r0 + 8 * i;
        dst[(size_t)(n0 + r) * DD + k0 + c] = __float2half_rn(t[c][r]);
    }
}

__global__ void k_maskstats(const float* __restrict__ Q) {
    int row = blockIdx.x;
    int t = threadIdx.x;
    float4 q = ((const float4*)(Q + (size_t)row * DD))[t];
    bool nz = (q.x != 0.f) || (q.y != 0.f) || (q.z != 0.f) || (q.w != 0.f);
    float s  = q.x + q.y + q.z + q.w;
    float s2 = q.x*q.x + q.y*q.y + q.z*q.z + q.w*q.w;
    int valid = __syncthreads_or(nz ? 1 : 0);
    #pragma unroll
    for (int o = 16; o > 0; o >>= 1) {
        s  += __shfl_xor_sync(0xffffffffu, s,  o);
        s2 += __shfl_xor_sync(0xffffffffu, s2, o);
    }
    __shared__ float rs[4], rs2[4];
    if ((t & 31) == 0) { rs[t >> 5] = s; rs2[t >> 5] = s2; }
    __syncthreads();
    if (t == 0) {
        g_mask[row] = valid;
        if (valid) {
            int b = row >> 10;
            atomicAdd(&g_cnt[b], 1);
            atomicAdd(&g_sum1[b], rs[0]+rs[1]+rs[2]+rs[3]);
            atomicAdd(&g_sq1[b],  rs2[0]+rs2[1]+rs2[2]+rs2[3]);
        }
    }
}

__global__ void k_norm(const float* __restrict__ src, __half* __restrict__ dst, int which) {
    int row = blockIdx.x;
    int t = threadIdx.x;
    int b = row >> 10;
    float cntD = (float)g_cnt[b] * (float)DD;
    float sum = which ? g_sum2[b] : g_sum1[b];
    float sq  = which ? g_sq2[b]  : g_sq1[b];
    float mean = (cntD > 0.f) ? sum / cntD : 0.f;
    float var  = (cntD > 0.f) ? sq / cntD - mean * mean : 0.f;
    if (var < 0.f) var = 0.f;
    float rstd = rsqrtf(var + EPSV);
    float sc = g_mask[row] ? rstd : 0.f;
    float mm = mean * sc;
    float4 v = ((const float4*)(src + (size_t)row * DD))[t];
    __half2 h0 = __floats2half2_rn(fmaf(v.x, sc, -mm), fmaf(v.y, sc, -mm));
    __half2 h1 = __floats2half2_rn(fmaf(v.z, sc, -mm), fmaf(v.w, sc, -mm));
    uint2 u = make_uint2(*(unsigned*)&h0, *(unsigned*)&h1);
    *(uint2*)(dst + (size_t)row * DD + t * 4) = u;
}

// ============ fp16 GEMM body (R14 verbatim): BM=128, BN=128, BK=32; 4-stage ============
struct GemmOut { float c[2][8][4]; };

__device__ __forceinline__ void gemm_body(
    const __half* __restrict__ Asrc, const __half* __restrict__ Bsrc,
    int m0, int n0, __half* smq, GemmOut& R)
{
    unsigned uA[4], uB[4];
    unsigned base = cvta_s(smq);
    #pragma unroll
    for (int i = 0; i < 4; i++) {
        uA[i] = base + (unsigned)i * 10240u;
        uB[i] = base + 40960u + (unsigned)i * 10240u;
    }

    int tid = threadIdx.x;
    int wid = tid >> 5, lane = tid & 31;
    int wm = wid >> 1, wn = wid & 1;
    int r8 = lane & 7, kh2 = (lane >> 3) & 1, kh4 = (lane >> 4) & 1;

    unsigned offA0 = (unsigned)((wm * 32 +      r8 + kh2 * 8) * 80 + kh4 * 16);
    unsigned offA1 = offA0 + 16 * 80;
    unsigned offB[4];
    #pragma unroll
    for (int nq = 0; nq < 4; nq++)
        offB[nq] = (unsigned)((wn * 64 + nq * 16 + r8 + kh4 * 8) * 80 + kh2 * 16);

    #pragma unroll
    for (int mi = 0; mi < 2; mi++)
        #pragma unroll
        for (int ni = 0; ni < 8; ni++)
            #pragma unroll
            for (int j = 0; j < 4; j++) R.c[mi][ni][j] = 0.f;

    #pragma unroll
    for (int p = 0; p < 3; p++) {
        #pragma unroll
        for (int i = 0; i < 2; i++) {
            int f = tid + 256 * i;
            int row = f >> 2, c4 = f & 3;
            CP16(uA[p] + row * 80 + c4 * 16, Asrc + (size_t)(m0 + row) * 512 + p * 32 + c4 * 8);
            CP16(uB[p] + row * 80 + c4 * 16, Bsrc + (size_t)(n0 + row) * 512 + p * 32 + c4 * 8);
        }
        CP_COMMIT();
    }

    for (int kc = 0; kc < 16; kc++) {
        CP_WAIT2();
        __syncthreads();
        if (kc + 3 < 16) {
            int j = (kc + 3) & 3;
            int k0 = (kc + 3) * 32;
            #pragma unroll
            for (int i = 0; i < 2; i++) {
                int f = tid + 256 * i;
                int row = f >> 2, c4 = f & 3;
                CP16(uA[j] + row * 80 + c4 * 16, Asrc + (size_t)(m0 + row) * 512 + k0 + c4 * 8);
                CP16(uB[j] + row * 80 + c4 * 16, Bsrc + (size_t)(n0 + row) * 512 + k0 + c4 * 8);
            }
        }
        CP_COMMIT();

        unsigned uAf = uA[kc & 3];
        unsigned uBf = uB[kc & 3];
        #pragma unroll
        for (int s = 0; s < 2; s++) {
            unsigned a[2][4], bb[8][2];
            ldsm4(uAf + offA0 + s * 32, a[0][0], a[0][1], a[0][2], a[0][3]);
            ldsm4(uAf + offA1 + s * 32, a[1][0], a[1][1], a[1][2], a[1][3]);
            #pragma unroll
            for (int nq = 0; nq < 4; nq++)
                ldsm4(uBf + offB[nq] + s * 32,
                      bb[nq*2][0], bb[nq*2][1], bb[nq*2+1][0], bb[nq*2+1][1]);
            #pragma unroll
            for (int mi = 0; mi < 2; mi++)
                #pragma unroll
                for (int ni = 0; ni < 8; ni++)
                    mma_h16(R.c[mi][ni], a[mi][0], a[mi][1], a[mi][2], a[mi][3],
                            bb[ni][0], bb[ni][1]);
        }
    }
}

// ---------------- QKV ----------------
__global__ __launch_bounds__(256, 2)
void k_qkv(const float* __restrict__ bq, const float* __restrict__ bk,
           const float* __restrict__ bv) {
    extern __shared__ __half smh[];
    int z = blockIdx.z;
    const float* bias = (z == 0) ? bq : (z == 1) ? bk : bv;
    const __half* Bsrc = g_Wt + (size_t)z * DD * DD;

    int n0 = blockIdx.x * 128, m0 = blockIdx.y * 128;
    int tid = threadIdx.x;
    int wid = tid >> 5, lane = tid & 31, g = lane >> 2, tig = lane & 3;
    int wm = wid >> 1, wn = wid & 1;

    GemmOut R;
    gemm_body(g_Qn, Bsrc, m0, n0, smh, R);

    if (z < 2) {
        __half* outp = (z == 0) ? g_Qp : g_Kp;
        #pragma unroll
        for (int mi = 0; mi < 2; mi++) {
            int r0 = m0 + wm * 32 + mi * 16 + g;
            float mk0 = g_mask[r0]     ? 1.f : 0.f;
            float mk1 = g_mask[r0 + 8] ? 1.f : 0.f;
            #pragma unroll
            for (int ni = 0; ni < 8; ni++) {
                int col = n0 + wn * 64 + ni * 8 + tig * 2;
                float b0v = bias[col], b1v = bias[col + 1];
                *(__half2*)(outp + (size_t)r0 * 512 + col) =
                    __floats2half2_rn((R.c[mi][ni][0] + b0v) * mk0,
                                      (R.c[mi][ni][1] + b1v) * mk0);
                *(__half2*)(outp + (size_t)(r0 + 8) * 512 + col) =
                    __floats2half2_rn((R.c[mi][ni][2] + b0v) * mk1,
                                      (R.c[mi][ni][3] + b1v) * mk1);
            }
        }
    } else {
        #pragma unroll
        for (int mi = 0; mi < 2; mi++) {
            int r0 = m0 + wm * 32 + mi * 16 + g;
            int bidx = r0 >> 10, s_ = r0 & 1023;
            float mk0 = g_mask[r0]     ? 1.f : 0.f;
            float mk1 = g_mask[r0 + 8] ? 1.f : 0.f;
            #pragma unroll
            for (int ni = 0; ni < 8; ni++) {
                int col = n0 + wn * 64 + ni * 8 + tig * 2;
                int h_ = col >> 6, dl = col & 63;
                float b0v = bias[col], b1v = bias[col + 1];
                __half* base = g_Vh + ((size_t)(bidx * 8 + h_) * 1024 + s_) * 64 + dl;
                *(__half2*)base = __floats2half2_rn((R.c[mi][ni][0] + b0v) * mk0,
                                                    (R.c[mi][ni][1] + b1v) * mk0);
                *(__half2*)(base + 8 * 64) = __floats2half2_rn((R.c[mi][ni][2] + b0v) * mk1,
                                                               (R.c[mi][ni][3] + b1v) * mk1);
            }
        }
    }
}

// ---------------- output GEMM ----------------
__global__ __launch_bounds__(256, 2)
void k_out(const float* __restrict__ bo, float* __restrict__ out) {
    extern __shared__ __half smh[];
    int n0 = blockIdx.x * 128, m0 = blockIdx.y * 128;
    int tid = threadIdx.x;
    int wid = tid >> 5, lane = tid & 31, g = lane >> 2, tig = lane & 3;
    int wm = wid >> 1, wn = wid & 1;

    GemmOut R;
    gemm_body(g_aon, g_Wt + (size_t)3 * DD * DD, m0, n0, smh, R);

    #pragma unroll
    for (int mi = 0; mi < 2; mi++) {
        int r0 = m0 + wm * 32 + mi * 16 + g;
        #pragma unroll
        for (int ni = 0; ni < 8; ni++) {
            int col = n0 + wn * 64 + ni * 8 + tig * 2;
            float b0v = bo[col], b1v = bo[col + 1];
            float2 a0 = *(const float2*)(g_ao + (size_t)r0 * 512 + col);
            float2 a1 = *(const float2*)(g_ao + (size_t)(r0 + 8) * 512 + col);
            float2 o0 = make_float2(a0.x + fmaxf(R.c[mi][ni][0] + b0v, 0.f),
                                    a0.y + fmaxf(R.c[mi][ni][1] + b1v, 0.f));
            float2 o1 = make_float2(a1.x + fmaxf(R.c[mi][ni][2] + b0v, 0.f),
                                    a1.y + fmaxf(R.c[mi][ni][3] + b1v, 0.f));
            *(float2*)(out + (size_t)r0 * 512 + col)       = o0;
            *(float2*)(out + (size_t)(r0 + 8) * 512 + col) = o1;
        }
    }
}

// ---------------- attention: 64 q-rows, 128-row K/V chunks (8 barrier iters/phase) ----------------
__global__ __launch_bounds__(512)
void k_attn(const float* __restrict__ Q, float* __restrict__ w_out) {
    extern __shared__ float sm[];
    __half* scH  = (__half*)sm;                 // 64 x 1032 fp16 exp values
    float*  kvb  = sm + 33024;                  // 4 x 4608 (128 rows x 72 halves each)
    __half* qsH  = (__half*)(kvb + 4 * KVW);    // 64 x 72 fp16 Q tile
    float*  red  = kvb + 4 * KVW + 2304;        // 32
    float*  part = red + 32;                    // 64*4
    float*  invS = part + 256;                  // 64

    int tid = threadIdx.x;
    int wid = tid >> 5, lane = tid & 31, g = lane >> 2, tig = lane & 3;
    int r8 = lane & 7, kh2 = (lane >> 3) & 1, kh4 = (lane >> 4) & 1;
    int bh = blockIdx.y, b = bh >> 3, h = bh & 7;
    int q0 = blockIdx.x * 64;
    size_t baseQ = ((size_t)b * SS + q0) * DD + h * HD;
    size_t baseK = ((size_t)b * SS) * DD + h * HD;
    const __half* Vh = g_Vh + (size_t)bh * SS * HD;
    const int bS = b * SS;

    unsigned uKV[4];
    #pragma unroll
    for (int i = 0; i < 4; i++) uKV[i] = cvta_s(kvb + i * KVW);
    unsigned uQS = cvta_s(qsH), uSC = cvta_s(scH);

    // K prologue: chunks 0..2 (128 keys x 64 d fp16 each; 2 CP16/thread/chunk)
    #pragma unroll
    for (int p = 0; p < 3; p++) {
        #pragma unroll
        for (int i = 0; i < 2; i++) {
            int f = tid + 512 * i;
            int row = f >> 3, c8 = f & 7;
            CP16(uKV[p] + row * 144 + c8 * 16,
                 g_Kp + baseK + (size_t)(p * 128 + row) * 512 + c8 * 8);
        }
        CP_COMMIT();
    }

    // q tile 64x64 fp16 -> smem
    {
        int r = tid >> 3, c8 = tid & 7;
        *(uint4*)(qsH + r * 72 + c8 * 8) =
            *(const uint4*)(g_Qp + baseQ + (size_t)r * 512 + c8 * 8);
    }
    __syncthreads();

    // warp layout: 16 warps = 4 m-groups x 4 n-slots (n32 per warp now)
    int nslot = wid & 3, mw = wid >> 2;
    unsigned areg[4][4];
    {
        unsigned base = uQS + (unsigned)((mw * 16 + r8 + kh2 * 8) * 144 + kh4 * 16);
        #pragma unroll
        for (int ks = 0; ks < 4; ks++)
            ldsm4(base + ks * 32, areg[ks][0], areg[ks][1], areg[ks][2], areg[ks][3]);
    }

    // ---- scores: 8 chunks of 128 keys; per warp m16 x n32; exp fused ----
    float rs0 = 0.f, rs1 = 0.f;
    unsigned offKB[2];
    #pragma unroll
    for (int nf16 = 0; nf16 < 2; nf16++)
        offKB[nf16] = (unsigned)((nslot * 32 + nf16 * 16 + r8 + kh4 * 8) * 144 + kh2 * 16);

    for (int kt = 0; kt < 8; kt++) {
        CP_WAIT2();
        __syncthreads();
        if (kt + 3 < 8) {
            unsigned nxt = uKV[(kt + 3) & 3];
            #pragma unroll
            for (int i = 0; i < 2; i++) {
                int f = tid + 512 * i;
                int row = f >> 3, c8 = f & 7;
                CP16(nxt + row * 144 + c8 * 16,
                     g_Kp + baseK + (size_t)((kt + 3) * 128 + row) * 512 + c8 * 8);
            }
        }
        CP_COMMIT();

        unsigned uKVf = uKV[kt & 3];
        float cc[4][4];
        #pragma unroll
        for (int nf = 0; nf < 4; nf++)
            #pragma unroll
            for (int j = 0; j < 4; j++) cc[nf][j] = 0.f;

        #pragma unroll
        for (int ks = 0; ks < 4; ks++) {
            #pragma unroll
            for (int nf16 = 0; nf16 < 2; nf16++) {
                unsigned b0, b1, b2, b3;
                ldsm4(uKVf + offKB[nf16] + ks * 32, b0, b1, b2, b3);
                mma_h16(cc[nf16*2],   areg[ks][0], areg[ks][1], areg[ks][2], areg[ks][3], b0, b1);
                mma_h16(cc[nf16*2+1], areg[ks][0], areg[ks][1], areg[ks][2], areg[ks][3], b2, b3);
            }
        }
        #pragma unroll
        for (int nf = 0; nf < 4; nf++) {
            int gc = kt * 128 + nslot * 32 + nf * 8 + tig * 2;
            bool k0v = g_mask[bS + gc] != 0;
            bool k1v = g_mask[bS + gc + 1] != 0;
            float p0 = k0v ? __expf(cc[nf][0] * 0.125f) : 0.f;
            float p1 = k1v ? __expf(cc[nf][1] * 0.125f) : 0.f;
            float p2 = k0v ? __expf(cc[nf][2] * 0.125f) : 0.f;
            float p3 = k1v ? __expf(cc[nf][3] * 0.125f) : 0.f;
            rs0 += p0 + p1;
            rs1 += p2 + p3;
            int r = mw * 16 + g;
            *(__half2*)&scH[r * SCPH + gc]       = __floats2half2_rn(p0, p1);
            *(__half2*)&scH[(r + 8) * SCPH + gc] = __floats2half2_rn(p2, p3);
        }
    }
    rs0 += __shfl_xor_sync(0xffffffffu, rs0, 1);
    rs0 += __shfl_xor_sync(0xffffffffu, rs0, 2);
    rs1 += __shfl_xor_sync(0xffffffffu, rs1, 1);
    rs1 += __shfl_xor_sync(0xffffffffu, rs1, 2);
    if (tig == 0) {
        part[(mw * 16 + g) * 4 + nslot]     = rs0;
        part[(mw * 16 + g + 8) * 4 + nslot] = rs1;
    }

    // V prologue: chunks 0..2 (128 s-rows x 64 d fp16)
    #pragma unroll
    for (int p = 0; p < 3; p++) {
        #pragma unroll
        for (int i = 0; i < 2; i++) {
            int f = tid + 512 * i;
            int row = f >> 3, c8 = f & 7;
            CP16(uKV[p] + row * 144 + c8 * 16,
                 Vh + ((size_t)(p * 128 + row)) * 64 + c8 * 8);
        }
        CP_COMMIT();
    }
    __syncthreads();   // panel + part visible

    // ---- w pass: w = fp16(p) * inv; compute invS ----
    {
        int row = tid >> 3, l = tid & 7;
        const float* pr = part + row * 4;
        float sum = pr[0] + pr[1] + pr[2] + pr[3];
        float inv = g_mask[bS + q0 + row] ? (1.0f / sum) : 0.f;
        if (l == 0) invS[row] = inv;
        float* wrow = w_out + ((size_t)bh * SS + q0 + row) * SS;
        const char* prow = (const char*)scH + row * (SCPH * 2);
        #pragma unroll
        for (int j = 0; j < 16; j++) {
            int e = l + 8 * j;
            uint4 u = *(const uint4*)(prow + e * 16);
            const __half2* hp = (const __half2*)&u;
            float2 f0 = __half22float2(hp[0]);
            float2 f1 = __half22float2(hp[1]);
            float2 f2 = __half22float2(hp[2]);
            float2 f3 = __half22float2(hp[3]);
            float4 o0 = make_float4(f0.x * inv, f0.y * inv, f1.x * inv, f1.y * inv);
            float4 o1 = make_float4(f2.x * inv, f2.y * inv, f3.x * inv, f3.y * inv);
            *(float4*)(wrow + e * 8)     = o0;
            *(float4*)(wrow + e * 8 + 4) = o1;
        }
    }

    // ---- attnV: fp16 m16n8k16; 8 chunks of 128 s; warps 4m x 4n ----
    int nsl2 = wid & 3, mw2 = wid >> 2;
    unsigned paA = uSC + (unsigned)((mw2 * 16 + r8 + kh2 * 8) * (SCPH * 2) + kh4 * 16);
    unsigned pbN = (unsigned)((nsl2 * 16 + kh4 * 8) * 2);
    int rowVk = r8 + kh2 * 8;

    float acc[2][4];
    #pragma unroll
    for (int nf = 0; nf < 2; nf++)
        #pragma unroll
        for (int j = 0; j < 4; j++) acc[nf][j] = 0.f;

    for (int vt = 0; vt < 8; vt++) {
        CP_WAIT2();
        __syncthreads();
        if (vt + 3 < 8) {
            unsigned nxt = uKV[(vt + 3) & 3];
            #pragma unroll
            for (int i = 0; i < 2; i++) {
                int f = tid + 512 * i;
                int row = f >> 3, c8 = f & 7;
                CP16(nxt + row * 144 + c8 * 16,
                     Vh + ((size_t)((vt + 3) * 128 + row)) * 64 + c8 * 8);
            }
        }
        CP_COMMIT();

        unsigned uKVf = uKV[vt & 3];
        #pragma unroll
        for (int ks = 0; ks < 8; ks++) {
            unsigned a0, a1, a2, a3, b0, b1, b2, b3;
            ldsm4(paA + vt * 256 + ks * 32, a0, a1, a2, a3);
            ldsm4t(uKVf + (ks * 16 + rowVk) * 144 + pbN, b0, b1, b2, b3);
            mma_h16(acc[0], a0, a1, a2, a3, b0, b1);
            mma_h16(acc[1], a0, a1, a2, a3, b2, b3);
        }
    }
    __syncthreads();

    // ---- store scaled attn into kvb (free), then epilogue ----
    {
        float* at = kvb;
        int r = mw2 * 16 + g;
        float i0 = invS[r], i1 = invS[r + 8];
        #pragma unroll
        for (int nf = 0; nf < 2; nf++) {
            int col = nsl2 * 16 + nf * 8 + tig * 2;
            *(float2*)&at[r * 68 + col]       = make_float2(acc[nf][0] * i0, acc[nf][1] * i0);
            *(float2*)&at[(r + 8) * 68 + col] = make_float2(acc[nf][2] * i1, acc[nf][3] * i1);
        }
    }
    __syncthreads();

    // ---- epilogue: attn_out = attn + Q; stats2 ----
    {
        float* at = kvb;
        float t1 = 0.f, t2 = 0.f;
        #pragma unroll
        for (int i = 0; i < 2; i++) {
            int f = tid + 512 * i;
            int r = f >> 4, c4 = f & 15;
            float4 a = *(const float4*)&at[r * 68 + c4 * 4];
            size_t gaddr = baseQ + (size_t)r * DD + c4 * 4;
            float4 q4 = *(const float4*)(Q + gaddr);
            float4 o = make_float4(a.x + q4.x, a.y + q4.y, a.z + q4.z, a.w + q4.w);
            *(float4*)(g_ao + gaddr) = o;
            t1 += o.x + o.y + o.z + o.w;
            t2 += o.x*o.x + o.y*o.y + o.z*o.z + o.w*o.w;
        }
        #pragma unroll
        for (int off = 16; off > 0; off >>= 1) {
            t1 += __shfl_xor_sync(0xffffffffu, t1, off);
            t2 += __shfl_xor_sync(0xffffffffu, t2, off);
        }
        if (lane == 0) { red[wid] = t1; red[16 + wid] = t2; }
    }
    __syncthreads();
    if (tid == 0) {
        float S1 = 0.f, S2 = 0.f;
        #pragma unroll
        for (int i = 0; i < 16; i++) { S1 += red[i]; S2 += red[16 + i]; }
        atomicAdd(&g_sum2[b], S1);
        atomicAdd(&g_sq2[b], S2);
    }
}

// ---------------- launch ----------------
extern "C" void kernel_launch(void* const* d_in, const int* in_sizes, int n_in,
                              void* d_out, int out_size) {
    const float* Q  = (const float*)d_in[0];
    const float* Wq = (const float*)d_in[1];
    const float* bq = (const float*)d_in[2];
    const float* Wk = (const float*)d_in[3];
    const float* bk = (const float*)d_in[4];
    const float* Wv = (const float*)d_in[5];
    const float* bv = (const float*)d_in[6];
    const float* Wo = (const float*)d_in[7];
    const float* bo = (const float*)d_in[8];

    float* out = (float*)d_out;
    float* w   = out + (size_t)BB * SS * DD;

    float*  g_ao_ptr;  cudaGetSymbolAddress((void**)&g_ao_ptr,  g_ao);
    __half* g_Qn_ptr;  cudaGetSymbolAddress((void**)&g_Qn_ptr,  g_Qn);
    __half* g_aon_ptr; cudaGetSymbolAddress((void**)&g_aon_ptr, g_aon);

    const int GEMM_SMEM = 8 * 10240;
    const int ATTN_SMEM = (33024 + 4 * KVW + 2304 + 32 + 256 + 64) * 4;  // 216448 B
    cudaFuncSetAttribute(k_qkv,  cudaFuncAttributeMaxDynamicSharedMemorySize, GEMM_SMEM);
    cudaFuncSetAttribute(k_out,  cudaFuncAttributeMaxDynamicSharedMemorySize, GEMM_SMEM);
    cudaFuncSetAttribute(k_attn, cudaFuncAttributeMaxDynamicSharedMemorySize, ATTN_SMEM);

    k_cvtW<<<dim3(16, 16, 4), 256>>>(Wq, Wk, Wv, Wo);
    k_maskstats<<<NROWS, 128>>>(Q);
    k_norm<<<NROWS, 128>>>(Q, g_Qn_ptr, 0);
    k_qkv<<<dim3(4, 64, 3), 256, GEMM_SMEM>>>(bq, bk, bv);
    k_attn<<<dim3(16, 64), 512, ATTN_SMEM>>>(Q, w);
    k_norm<<<NROWS, 128>>>(g_ao_ptr, g_aon_ptr, 1);
    k_out<<<dim3(4, 64), 256, GEMM_SMEM>>>(bo, out);
}

// round 16
// speedup vs baseline: 1.6928x; 1.0490x over previous
#include <cuda_runtime.h>
#include <cuda_fp16.h>
#include <math.h>

#define BB 8
#define SS 1024
#define DD 512
#define HD 64
#define NROWS (BB*SS)
#define EPSV 1e-5f
#define SCPH 1032    // fp16 panel stride (halves)
#define KVW 2304     // words per KV buffer (64 rows x 72 halves = 9216 B)

// ---------------- scratch ----------------
__device__ __half g_Qp[NROWS*DD];   // fp16 Q-proj [s][d]
__device__ __half g_Kp[NROWS*DD];   // fp16 K-proj [s][d]
__device__ __half g_Vh[NROWS*DD];   // fp16 V: [bh][s][d]
__device__ float  g_ao[NROWS*DD];   // exact fp32
__device__ __half g_Qn[NROWS*DD];   // normed Q fp16
__device__ __half g_aon[NROWS*DD];  // normed ao fp16
__device__ __half g_Wt[4*DD*DD];    // fp16 weights TRANSPOSED: [n][k]
__device__ float  g_sum1[BB], g_sq1[BB], g_sum2[BB], g_sq2[BB];
__device__ int    g_cnt[BB];
__device__ int    g_mask[NROWS];

// ---------------- helpers ----------------
__device__ __forceinline__ void mma_h16(float* c, unsigned a0, unsigned a1, unsigned a2,
                                        unsigned a3, unsigned b0, unsigned b1) {
    asm volatile(
        "mma.sync.aligned.m16n8k16.row.col.f32.f16.f16.f32 "
        "{%0,%1,%2,%3},{%4,%5,%6,%7},{%8,%9},{%0,%1,%2,%3};"
        : "+f"(c[0]), "+f"(c[1]), "+f"(c[2]), "+f"(c[3])
        : "r"(a0), "r"(a1), "r"(a2), "r"(a3), "r"(b0), "r"(b1));
}
__device__ __forceinline__ void ldsm4(unsigned addr, unsigned& r0, unsigned& r1,
                                      unsigned& r2, unsigned& r3) {
    asm volatile("ldmatrix.sync.aligned.m8n8.x4.shared.b16 {%0,%1,%2,%3}, [%4];"
                 : "=r"(r0), "=r"(r1), "=r"(r2), "=r"(r3) : "r"(addr));
}
__device__ __forceinline__ void ldsm4t(unsigned addr, unsigned& r0, unsigned& r1,
                                       unsigned& r2, unsigned& r3) {
    asm volatile("ldmatrix.sync.aligned.m8n8.x4.trans.shared.b16 {%0,%1,%2,%3}, [%4];"
                 : "=r"(r0), "=r"(r1), "=r"(r2), "=r"(r3) : "r"(addr));
}
__device__ __forceinline__ unsigned cvta_s(const void* p) {
    return (unsigned)__cvta_generic_to_shared(p);
}
#define CP16(dst_u32, src_ptr) \
    asm volatile("cp.async.cg.shared.global [%0], [%1], 16;" :: "r"(dst_u32), "l"(src_ptr))
#define CP_COMMIT() asm volatile("cp.async.commit_group;")
#define CP_WAIT2()  asm volatile("cp.async.wait_group 2;")
#define CP_WAIT0()  asm volatile("cp.async.wait_group 0;")

// ---------------- tiny kernels ----------------
__global__ void k_cvtW(const float* __restrict__ Wq, const float* __restrict__ Wk,
                       const float* __restrict__ Wv, const float* __restrict__ Wo) {
    if (blockIdx.x == 0 && blockIdx.y == 0 && blockIdx.z == 0 && threadIdx.x < BB) {
        int t = threadIdx.x;
        g_sum1[t]=0.f; g_sq1[t]=0.f; g_sum2[t]=0.f; g_sq2[t]=0.f; g_cnt[t]=0;
    }
    __shared__ float t[32][33];
    const float* src = (blockIdx.z == 0) ? Wq : (blockIdx.z == 1) ? Wk :
                       (blockIdx.z == 2) ? Wv : Wo;
    __half* dst = g_Wt + (size_t)blockIdx.z * DD * DD;
    int k0 = blockIdx.x * 32, n0 = blockIdx.y * 32;
    int c = threadIdx.x & 31, r0 = threadIdx.x >> 5;
    #pragma unroll
    for (int i = 0; i < 4; i++) {
        int r = r0 + 8 * i;
        t[r][c] = src[(size_t)(k0 + r) * DD + n0 + c];
    }
    __syncthreads();
    #pragma unroll
    for (int i = 0; i < 4; i++) {
        int r = r0 + 8 * i;
        dst[(size_t)(n0 + r) * DD + k0 + c] = __float2half_rn(t[c][r]);
    }
}

__global__ void k_maskstats(const float* __restrict__ Q) {
    int row = blockIdx.x;
    int t = threadIdx.x;
    float4 q = ((const float4*)(Q + (size_t)row * DD))[t];
    bool nz = (q.x != 0.f) || (q.y != 0.f) || (q.z != 0.f) || (q.w != 0.f);
    float s  = q.x + q.y + q.z + q.w;
    float s2 = q.x*q.x + q.y*q.y + q.z*q.z + q.w*q.w;
    int valid = __syncthreads_or(nz ? 1 : 0);
    #pragma unroll
    for (int o = 16; o > 0; o >>= 1) {
        s  += __shfl_xor_sync(0xffffffffu, s,  o);
        s2 += __shfl_xor_sync(0xffffffffu, s2, o);
    }
    __shared__ float rs[4], rs2[4];
    if ((t & 31) == 0) { rs[t >> 5] = s; rs2[t >> 5] = s2; }
    __syncthreads();
    if (t == 0) {
        g_mask[row] = valid;
        if (valid) {
            int b = row >> 10;
            atomicAdd(&g_cnt[b], 1);
            atomicAdd(&g_sum1[b], rs[0]+rs[1]+rs[2]+rs[3]);
            atomicAdd(&g_sq1[b],  rs2[0]+rs2[1]+rs2[2]+rs2[3]);
        }
    }
}

__global__ void k_norm(const float* __restrict__ src, __half* __restrict__ dst, int which) {
    int row = blockIdx.x;
    int t = threadIdx.x;
    int b = row >> 10;
    float cntD = (float)g_cnt[b] * (float)DD;
    float sum = which ? g_sum2[b] : g_sum1[b];
    float sq  = which ? g_sq2[b]  : g_sq1[b];
    float mean = (cntD > 0.f) ? sum / cntD : 0.f;
    float var  = (cntD > 0.f) ? sq / cntD - mean * mean : 0.f;
    if (var < 0.f) var = 0.f;
    float rstd = rsqrtf(var + EPSV);
    float sc = g_mask[row] ? rstd : 0.f;
    float mm = mean * sc;
    float4 v = ((const float4*)(src + (size_t)row * DD))[t];
    __half2 h0 = __floats2half2_rn(fmaf(v.x, sc, -mm), fmaf(v.y, sc, -mm));
    __half2 h1 = __floats2half2_rn(fmaf(v.z, sc, -mm), fmaf(v.w, sc, -mm));
    uint2 u = make_uint2(*(unsigned*)&h0, *(unsigned*)&h1);
    *(uint2*)(dst + (size_t)row * DD + t * 4) = u;
}

// ============ fp16 GEMM body (R14 verbatim): BM=128, BN=128, BK=32; 4-stage ============
struct GemmOut { float c[2][8][4]; };

__device__ __forceinline__ void gemm_body(
    const __half* __restrict__ Asrc, const __half* __restrict__ Bsrc,
    int m0, int n0, __half* smq, GemmOut& R)
{
    unsigned uA[4], uB[4];
    unsigned base = cvta_s(smq);
    #pragma unroll
    for (int i = 0; i < 4; i++) {
        uA[i] = base + (unsigned)i * 10240u;
        uB[i] = base + 40960u + (unsigned)i * 10240u;
    }

    int tid = threadIdx.x;
    int wid = tid >> 5, lane = tid & 31;
    int wm = wid >> 1, wn = wid & 1;
    int r8 = lane & 7, kh2 = (lane >> 3) & 1, kh4 = (lane >> 4) & 1;

    unsigned offA0 = (unsigned)((wm * 32 +      r8 + kh2 * 8) * 80 + kh4 * 16);
    unsigned offA1 = offA0 + 16 * 80;
    unsigned offB[4];
    #pragma unroll
    for (int nq = 0; nq < 4; nq++)
        offB[nq] = (unsigned)((wn * 64 + nq * 16 + r8 + kh4 * 8) * 80 + kh2 * 16);

    #pragma unroll
    for (int mi = 0; mi < 2; mi++)
        #pragma unroll
        for (int ni = 0; ni < 8; ni++)
            #pragma unroll
            for (int j = 0; j < 4; j++) R.c[mi][ni][j] = 0.f;

    #pragma unroll
    for (int p = 0; p < 3; p++) {
        #pragma unroll
        for (int i = 0; i < 2; i++) {
            int f = tid + 256 * i;
            int row = f >> 2, c4 = f & 3;
            CP16(uA[p] + row * 80 + c4 * 16, Asrc + (size_t)(m0 + row) * 512 + p * 32 + c4 * 8);
            CP16(uB[p] + row * 80 + c4 * 16, Bsrc + (size_t)(n0 + row) * 512 + p * 32 + c4 * 8);
        }
        CP_COMMIT();
    }

    for (int kc = 0; kc < 16; kc++) {
        CP_WAIT2();
        __syncthreads();
        if (kc + 3 < 16) {
            int j = (kc + 3) & 3;
            int k0 = (kc + 3) * 32;
            #pragma unroll
            for (int i = 0; i < 2; i++) {
                int f = tid + 256 * i;
                int row = f >> 2, c4 = f & 3;
                CP16(uA[j] + row * 80 + c4 * 16, Asrc + (size_t)(m0 + row) * 512 + k0 + c4 * 8);
                CP16(uB[j] + row * 80 + c4 * 16, Bsrc + (size_t)(n0 + row) * 512 + k0 + c4 * 8);
            }
        }
        CP_COMMIT();

        unsigned uAf = uA[kc & 3];
        unsigned uBf = uB[kc & 3];
        #pragma unroll
        for (int s = 0; s < 2; s++) {
            unsigned a[2][4], bb[8][2];
            ldsm4(uAf + offA0 + s * 32, a[0][0], a[0][1], a[0][2], a[0][3]);
            ldsm4(uAf + offA1 + s * 32, a[1][0], a[1][1], a[1][2], a[1][3]);
            #pragma unroll
            for (int nq = 0; nq < 4; nq++)
                ldsm4(uBf + offB[nq] + s * 32,
                      bb[nq*2][0], bb[nq*2][1], bb[nq*2+1][0], bb[nq*2+1][1]);
            #pragma unroll
            for (int mi = 0; mi < 2; mi++)
                #pragma unroll
                for (int ni = 0; ni < 8; ni++)
                    mma_h16(R.c[mi][ni], a[mi][0], a[mi][1], a[mi][2], a[mi][3],
                            bb[ni][0], bb[ni][1]);
        }
    }
}

// ---------------- QKV ----------------
__global__ __launch_bounds__(256, 2)
void k_qkv(const float* __restrict__ bq, const float* __restrict__ bk,
           const float* __restrict__ bv) {
    extern __shared__ __half smh[];
    int z = blockIdx.z;
    const float* bias = (z == 0) ? bq : (z == 1) ? bk : bv;
    const __half* Bsrc = g_Wt + (size_t)z * DD * DD;

    int n0 = blockIdx.x * 128, m0 = blockIdx.y * 128;
    int tid = threadIdx.x;
    int wid = tid >> 5, lane = tid & 31, g = lane >> 2, tig = lane & 3;
    int wm = wid >> 1, wn = wid & 1;

    GemmOut R;
    gemm_body(g_Qn, Bsrc, m0, n0, smh, R);

    if (z < 2) {
        __half* outp = (z == 0) ? g_Qp : g_Kp;
        #pragma unroll
        for (int mi = 0; mi < 2; mi++) {
            int r0 = m0 + wm * 32 + mi * 16 + g;
            float mk0 = g_mask[r0]     ? 1.f : 0.f;
            float mk1 = g_mask[r0 + 8] ? 1.f : 0.f;
            #pragma unroll
            for (int ni = 0; ni < 8; ni++) {
                int col = n0 + wn * 64 + ni * 8 + tig * 2;
                float b0v = bias[col], b1v = bias[col + 1];
                *(__half2*)(outp + (size_t)r0 * 512 + col) =
                    __floats2half2_rn((R.c[mi][ni][0] + b0v) * mk0,
                                      (R.c[mi][ni][1] + b1v) * mk0);
                *(__half2*)(outp + (size_t)(r0 + 8) * 512 + col) =
                    __floats2half2_rn((R.c[mi][ni][2] + b0v) * mk1,
                                      (R.c[mi][ni][3] + b1v) * mk1);
            }
        }
    } else {
        #pragma unroll
        for (int mi = 0; mi < 2; mi++) {
            int r0 = m0 + wm * 32 + mi * 16 + g;
            int bidx = r0 >> 10, s_ = r0 & 1023;
            float mk0 = g_mask[r0]     ? 1.f : 0.f;
            float mk1 = g_mask[r0 + 8] ? 1.f : 0.f;
            #pragma unroll
            for (int ni = 0; ni < 8; ni++) {
                int col = n0 + wn * 64 + ni * 8 + tig * 2;
                int h_ = col >> 6, dl = col & 63;
                float b0v = bias[col], b1v = bias[col + 1];
                __half* base = g_Vh + ((size_t)(bidx * 8 + h_) * 1024 + s_) * 64 + dl;
                *(__half2*)base = __floats2half2_rn((R.c[mi][ni][0] + b0v) * mk0,
                                                    (R.c[mi][ni][1] + b1v) * mk0);
                *(__half2*)(base + 8 * 64) = __floats2half2_rn((R.c[mi][ni][2] + b0v) * mk1,
                                                               (R.c[mi][ni][3] + b1v) * mk1);
            }
        }
    }
}

// ---------------- output GEMM ----------------
__global__ __launch_bounds__(256, 2)
void k_out(const float* __restrict__ bo, float* __restrict__ out) {
    extern __shared__ __half smh[];
    int n0 = blockIdx.x * 128, m0 = blockIdx.y * 128;
    int tid = threadIdx.x;
    int wid = tid >> 5, lane = tid & 31, g = lane >> 2, tig = lane & 3;
    int wm = wid >> 1, wn = wid & 1;

    GemmOut R;
    gemm_body(g_aon, g_Wt + (size_t)3 * DD * DD, m0, n0, smh, R);

    #pragma unroll
    for (int mi = 0; mi < 2; mi++) {
        int r0 = m0 + wm * 32 + mi * 16 + g;
        #pragma unroll
        for (int ni = 0; ni < 8; ni++) {
            int col = n0 + wn * 64 + ni * 8 + tig * 2;
            float b0v = bo[col], b1v = bo[col + 1];
            float2 a0 = *(const float2*)(g_ao + (size_t)r0 * 512 + col);
            float2 a1 = *(const float2*)(g_ao + (size_t)(r0 + 8) * 512 + col);
            float2 o0 = make_float2(a0.x + fmaxf(R.c[mi][ni][0] + b0v, 0.f),
                                    a0.y + fmaxf(R.c[mi][ni][1] + b1v, 0.f));
            float2 o1 = make_float2(a1.x + fmaxf(R.c[mi][ni][2] + b0v, 0.f),
                                    a1.y + fmaxf(R.c[mi][ni][3] + b1v, 0.f));
            *(float2*)(out + (size_t)r0 * 512 + col)       = o0;
            *(float2*)(out + (size_t)(r0 + 8) * 512 + col) = o1;
        }
    }
}

// ---------------- attention: 32 q-rows, 256 thr, 2 CTAs/SM ----------------
// smem (words): scH 8256 | kvb 4*2304 | qsH 1152 | red 16 | part 128 | invS 32  = 108 KB
__global__ __launch_bounds__(256, 2)
void k_attn(const float* __restrict__ Q, float* __restrict__ w_out) {
    extern __shared__ float sm[];
    __half* scH  = (__half*)sm;                 // 32 x 1032 fp16 exp values
    float*  kvb  = sm + 16512;                  // 4 x 2304
    __half* qsH  = (__half*)(kvb + 4 * KVW);    // 32 x 72 fp16 Q tile
    float*  red  = kvb + 4 * KVW + 1152;        // 16
    float*  part = red + 16;                    // 32*4
    float*  invS = part + 128;                  // 32

    int tid = threadIdx.x;
    int wid = tid >> 5, lane = tid & 31, g = lane >> 2, tig = lane & 3;
    int r8 = lane & 7, kh2 = (lane >> 3) & 1, kh4 = (lane >> 4) & 1;
    int bh = blockIdx.y, b = bh >> 3, h = bh & 7;
    int q0 = blockIdx.x * 32;
    size_t baseQ = ((size_t)b * SS + q0) * DD + h * HD;
    size_t baseK = ((size_t)b * SS) * DD + h * HD;
    const __half* Vh = g_Vh + (size_t)bh * SS * HD;
    const int bS = b * SS;

    unsigned uKV[4];
    #pragma unroll
    for (int i = 0; i < 4; i++) uKV[i] = cvta_s(kvb + i * KVW);
    unsigned uQS = cvta_s(qsH), uSC = cvta_s(scH);

    // K prologue: chunks 0..2 (64 keys x 64 d fp16; 2 CP16/thread/chunk)
    #pragma unroll
    for (int p = 0; p < 3; p++) {
        #pragma unroll
        for (int i = 0; i < 2; i++) {
            int f = tid + 256 * i;
            int row = f >> 3, c8 = f & 7;
            CP16(uKV[p] + row * 144 + c8 * 16,
                 g_Kp + baseK + (size_t)(p * 64 + row) * 512 + c8 * 8);
        }
        CP_COMMIT();
    }

    // q tile 32x64 fp16 -> smem (1 uint4 per thread)
    {
        int r = tid >> 3, c8 = tid & 7;
        *(uint4*)(qsH + r * 72 + c8 * 8) =
            *(const uint4*)(g_Qp + baseQ + (size_t)r * 512 + c8 * 8);
    }
    __syncthreads();

    // warp layout: 8 warps = 2 m-groups x 4 n-slots
    int nslot = wid & 3, mw = wid >> 2;
    unsigned areg[4][4];
    {
        unsigned base = uQS + (unsigned)((mw * 16 + r8 + kh2 * 8) * 144 + kh4 * 16);
        #pragma unroll
        for (int ks = 0; ks < 4; ks++)
            ldsm4(base + ks * 32, areg[ks][0], areg[ks][1], areg[ks][2], areg[ks][3]);
    }

    // ---- scores: 16 chunks of 64 keys; per warp m16 x n16; exp fused ----
    float rs0 = 0.f, rs1 = 0.f;
    unsigned offKB = (unsigned)((nslot * 16 + r8 + kh4 * 8) * 144 + kh2 * 16);
    for (int kt = 0; kt < 16; kt++) {
        CP_WAIT2();
        __syncthreads();
        if (kt + 3 < 16) {
            unsigned nxt = uKV[(kt + 3) & 3];
            #pragma unroll
            for (int i = 0; i < 2; i++) {
                int f = tid + 256 * i;
                int row = f >> 3, c8 = f & 7;
                CP16(nxt + row * 144 + c8 * 16,
                     g_Kp + baseK + (size_t)((kt + 3) * 64 + row) * 512 + c8 * 8);
            }
        }
        CP_COMMIT();

        unsigned uKVf = uKV[kt & 3];
        float cc[2][4];
        #pragma unroll
        for (int nf = 0; nf < 2; nf++)
            #pragma unroll
            for (int j = 0; j < 4; j++) cc[nf][j] = 0.f;

        #pragma unroll
        for (int ks = 0; ks < 4; ks++) {
            unsigned b0, b1, b2, b3;
            ldsm4(uKVf + offKB + ks * 32, b0, b1, b2, b3);
            mma_h16(cc[0], areg[ks][0], areg[ks][1], areg[ks][2], areg[ks][3], b0, b1);
            mma_h16(cc[1], areg[ks][0], areg[ks][1], areg[ks][2], areg[ks][3], b2, b3);
        }
        #pragma unroll
        for (int nf = 0; nf < 2; nf++) {
            int gc = kt * 64 + nslot * 16 + nf * 8 + tig * 2;
            bool k0v = g_mask[bS + gc] != 0;
            bool k1v = g_mask[bS + gc + 1] != 0;
            float p0 = k0v ? __expf(cc[nf][0] * 0.125f) : 0.f;
            float p1 = k1v ? __expf(cc[nf][1] * 0.125f) : 0.f;
            float p2 = k0v ? __expf(cc[nf][2] * 0.125f) : 0.f;
            float p3 = k1v ? __expf(cc[nf][3] * 0.125f) : 0.f;
            rs0 += p0 + p1;
            rs1 += p2 + p3;
            int r = mw * 16 + g;
            *(__half2*)&scH[r * SCPH + gc]       = __floats2half2_rn(p0, p1);
            *(__half2*)&scH[(r + 8) * SCPH + gc] = __floats2half2_rn(p2, p3);
        }
    }
    rs0 += __shfl_xor_sync(0xffffffffu, rs0, 1);
    rs0 += __shfl_xor_sync(0xffffffffu, rs0, 2);
    rs1 += __shfl_xor_sync(0xffffffffu, rs1, 1);
    rs1 += __shfl_xor_sync(0xffffffffu, rs1, 2);
    if (tig == 0) {
        part[(mw * 16 + g) * 4 + nslot]     = rs0;
        part[(mw * 16 + g + 8) * 4 + nslot] = rs1;
    }

    // V prologue: chunks 0..2
    #pragma unroll
    for (int p = 0; p < 3; p++) {
        #pragma unroll
        for (int i = 0; i < 2; i++) {
            int f = tid + 256 * i;
            int row = f >> 3, c8 = f & 7;
            CP16(uKV[p] + row * 144 + c8 * 16,
                 Vh + ((size_t)(p * 64 + row)) * 64 + c8 * 8);
        }
        CP_COMMIT();
    }
    __syncthreads();   // panel + part visible

    // ---- w pass: w = fp16(p) * inv; compute invS (32 rows x 8 lanes) ----
    {
        int row = tid >> 3, l = tid & 7;
        const float* pr = part + row * 4;
        float sum = pr[0] + pr[1] + pr[2] + pr[3];
        float inv = g_mask[bS + q0 + row] ? (1.0f / sum) : 0.f;
        if (l == 0) invS[row] = inv;
        float* wrow = w_out + ((size_t)bh * SS + q0 + row) * SS;
        const char* prow = (const char*)scH + row * (SCPH * 2);
        #pragma unroll
        for (int j = 0; j < 16; j++) {
            int e = l + 8 * j;
            uint4 u = *(const uint4*)(prow + e * 16);
            const __half2* hp = (const __half2*)&u;
            float2 f0 = __half22float2(hp[0]);
            float2 f1 = __half22float2(hp[1]);
            float2 f2 = __half22float2(hp[2]);
            float2 f3 = __half22float2(hp[3]);
            float4 o0 = make_float4(f0.x * inv, f0.y * inv, f1.x * inv, f1.y * inv);
            float4 o1 = make_float4(f2.x * inv, f2.y * inv, f3.x * inv, f3.y * inv);
            *(float4*)(wrow + e * 8)     = o0;
            *(float4*)(wrow + e * 8 + 4) = o1;
        }
    }

    // ---- attnV: fp16 m16n8k16; 16 chunks of 64 s; warps 2m x 4n ----
    int nsl2 = wid & 3, mw2 = wid >> 2;
    unsigned paA = uSC + (unsigned)((mw2 * 16 + r8 + kh2 * 8) * (SCPH * 2) + kh4 * 16);
    unsigned pbN = (unsigned)((nsl2 * 16 + kh4 * 8) * 2);
    int rowVk = r8 + kh2 * 8;

    float acc[2][4];
    #pragma unroll
    for (int nf = 0; nf < 2; nf++)
        #pragma unroll
        for (int j = 0; j < 4; j++) acc[nf][j] = 0.f;

    for (int vt = 0; vt < 16; vt++) {
        CP_WAIT2();
        __syncthreads();
        if (vt + 3 < 16) {
            unsigned nxt = uKV[(vt + 3) & 3];
            #pragma unroll
            for (int i = 0; i < 2; i++) {
                int f = tid + 256 * i;
                int row = f >> 3, c8 = f & 7;
                CP16(nxt + row * 144 + c8 * 16,
                     Vh + ((size_t)((vt + 3) * 64 + row)) * 64 + c8 * 8);
            }
        }
        CP_COMMIT();

        unsigned uKVf = uKV[vt & 3];
        #pragma unroll
        for (int ks = 0; ks < 4; ks++) {
            unsigned a0, a1, a2, a3, b0, b1, b2, b3;
            ldsm4(paA + vt * 128 + ks * 32, a0, a1, a2, a3);
            ldsm4t(uKVf + (ks * 16 + rowVk) * 144 + pbN, b0, b1, b2, b3);
            mma_h16(acc[0], a0, a1, a2, a3, b0, b1);
            mma_h16(acc[1], a0, a1, a2, a3, b2, b3);
        }
    }
    __syncthreads();

    // ---- store scaled attn into kvb (free), then epilogue ----
    {
        float* at = kvb;   // 32 x 68 fp32
        int r = mw2 * 16 + g;
        float i0 = invS[r], i1 = invS[r + 8];
        #pragma unroll
        for (int nf = 0; nf < 2; nf++) {
            int col = nsl2 * 16 + nf * 8 + tig * 2;
            *(float2*)&at[r * 68 + col]       = make_float2(acc[nf][0] * i0, acc[nf][1] * i0);
            *(float2*)&at[(r + 8) * 68 + col] = make_float2(acc[nf][2] * i1, acc[nf][3] * i1);
        }
    }
    __syncthreads();

    // ---- epilogue: attn_out = attn + Q; stats2 ----
    {
        float* at = kvb;
        float t1 = 0.f, t2 = 0.f;
        #pragma unroll
        for (int i = 0; i < 2; i++) {
            int f = tid + 256 * i;
            int r = f >> 4, c4 = f & 15;
            float4 a = *(const float4*)&at[r * 68 + c4 * 4];
            size_t gaddr = baseQ + (size_t)r * DD + c4 * 4;
            float4 q4 = *(const float4*)(Q + gaddr);
            float4 o = make_float4(a.x + q4.x, a.y + q4.y, a.z + q4.z, a.w + q4.w);
            *(float4*)(g_ao + gaddr) = o;
            t1 += o.x + o.y + o.z + o.w;
            t2 += o.x*o.x + o.y*o.y + o.z*o.z + o.w*o.w;
        }
        #pragma unroll
        for (int off = 16; off > 0; off >>= 1) {
            t1 += __shfl_xor_sync(0xffffffffu, t1, off);
            t2 += __shfl_xor_sync(0xffffffffu, t2, off);
        }
        if (lane == 0) { red[wid] = t1; red[8 + wid] = t2; }
    }
    __syncthreads();
    if (tid == 0) {
        float S1 = 0.f, S2 = 0.f;
        #pragma unroll
        for (int i = 0; i < 8; i++) { S1 += red[i]; S2 += red[8 + i]; }
        atomicAdd(&g_sum2[b], S1);
        atomicAdd(&g_sq2[b], S2);
    }
}

// ---------------- launch ----------------
extern "C" void kernel_launch(void* const* d_in, const int* in_sizes, int n_in,
                              void* d_out, int out_size) {
    const float* Q  = (const float*)d_in[0];
    const float* Wq = (const float*)d_in[1];
    const float* bq = (const float*)d_in[2];
    const float* Wk = (const float*)d_in[3];
    const float* bk = (const float*)d_in[4];
    const float* Wv = (const float*)d_in[5];
    const float* bv = (const float*)d_in[6];
    const float* Wo = (const float*)d_in[7];
    const float* bo = (const float*)d_in[8];

    float* out = (float*)d_out;
    float* w   = out + (size_t)BB * SS * DD;

    float*  g_ao_ptr;  cudaGetSymbolAddress((void**)&g_ao_ptr,  g_ao);
    __half* g_Qn_ptr;  cudaGetSymbolAddress((void**)&g_Qn_ptr,  g_Qn);
    __half* g_aon_ptr; cudaGetSymbolAddress((void**)&g_aon_ptr, g_aon);

    const int GEMM_SMEM = 8 * 10240;
    const int ATTN_SMEM = (16512 + 4 * KVW + 1152 + 16 + 128 + 32) * 4;  // 108160 B
    cudaFuncSetAttribute(k_qkv,  cudaFuncAttributeMaxDynamicSharedMemorySize, GEMM_SMEM);
    cudaFuncSetAttribute(k_out,  cudaFuncAttributeMaxDynamicSharedMemorySize, GEMM_SMEM);
    cudaFuncSetAttribute(k_attn, cudaFuncAttributeMaxDynamicSharedMemorySize, ATTN_SMEM);

    k_cvtW<<<dim3(16, 16, 4), 256>>>(Wq, Wk, Wv, Wo);
    k_maskstats<<<NROWS, 128>>>(Q);
    k_norm<<<NROWS, 128>>>(Q, g_Qn_ptr, 0);
    k_qkv<<<dim3(4, 64, 3), 256, GEMM_SMEM>>>(bq, bk, bv);
    k_attn<<<dim3(32, 64), 256, ATTN_SMEM>>>(Q, w);
    k_norm<<<NROWS, 128>>>(g_ao_ptr, g_aon_ptr, 1);
    k_out<<<dim3(4, 64), 256, GEMM_SMEM>>>(bo, out);
}

// round 17
// speedup vs baseline: 1.8181x; 1.0741x over previous
#include <cuda_runtime.h>
#include <cuda_fp16.h>
#include <math.h>

#define BB 8
#define SS 1024
#define DD 512
#define HD 64
#define NROWS (BB*SS)
#define EPSV 1e-5f
#define SCPH 1032    // fp16 panel stride (halves)
#define KVW 2304     // words per KV buffer (64 rows x 72 halves = 9216 B)

// ---------------- scratch ----------------
__device__ __half g_Qp[NROWS*DD];   // fp16 Q-proj [s][d]
__device__ __half g_Kp[NROWS*DD];   // fp16 K-proj [s][d]
__device__ __half g_Vh[NROWS*DD];   // fp16 V: [bh][s][d]
__device__ float  g_ao[NROWS*DD];   // exact fp32
__device__ __half g_Qn[NROWS*DD];   // normed Q fp16
__device__ __half g_aon[NROWS*DD];  // normed ao fp16
__device__ __half g_Wt[4*DD*DD];    // fp16 weights TRANSPOSED: [n][k]
__device__ float  g_sum1[BB], g_sq1[BB], g_sum2[BB], g_sq2[BB];
__device__ int    g_cnt[BB];
__device__ int    g_mask[NROWS];
__device__ int    g_ckv[128];       // per-64-key-chunk any-valid flags

// ---------------- helpers ----------------
__device__ __forceinline__ void mma_h16(float* c, unsigned a0, unsigned a1, unsigned a2,
                                        unsigned a3, unsigned b0, unsigned b1) {
    asm volatile(
        "mma.sync.aligned.m16n8k16.row.col.f32.f16.f16.f32 "
        "{%0,%1,%2,%3},{%4,%5,%6,%7},{%8,%9},{%0,%1,%2,%3};"
        : "+f"(c[0]), "+f"(c[1]), "+f"(c[2]), "+f"(c[3])
        : "r"(a0), "r"(a1), "r"(a2), "r"(a3), "r"(b0), "r"(b1));
}
__device__ __forceinline__ void ldsm4(unsigned addr, unsigned& r0, unsigned& r1,
                                      unsigned& r2, unsigned& r3) {
    asm volatile("ldmatrix.sync.aligned.m8n8.x4.shared.b16 {%0,%1,%2,%3}, [%4];"
                 : "=r"(r0), "=r"(r1), "=r"(r2), "=r"(r3) : "r"(addr));
}
__device__ __forceinline__ void ldsm4t(unsigned addr, unsigned& r0, unsigned& r1,
                                       unsigned& r2, unsigned& r3) {
    asm volatile("ldmatrix.sync.aligned.m8n8.x4.trans.shared.b16 {%0,%1,%2,%3}, [%4];"
                 : "=r"(r0), "=r"(r1), "=r"(r2), "=r"(r3) : "r"(addr));
}
__device__ __forceinline__ unsigned cvta_s(const void* p) {
    return (unsigned)__cvta_generic_to_shared(p);
}
#define CP16(dst_u32, src_ptr) \
    asm volatile("cp.async.cg.shared.global [%0], [%1], 16;" :: "r"(dst_u32), "l"(src_ptr))
#define CP_COMMIT() asm volatile("cp.async.commit_group;")
#define CP_WAIT2()  asm volatile("cp.async.wait_group 2;")
#define CP_WAIT0()  asm volatile("cp.async.wait_group 0;")

// ---------------- tiny kernels ----------------
__global__ void k_cvtW(const float* __restrict__ Wq, const float* __restrict__ Wk,
                       const float* __restrict__ Wv, const float* __restrict__ Wo) {
    if (blockIdx.x == 0 && blockIdx.y == 0 && blockIdx.z == 0) {
        int t = threadIdx.x;
        if (t < BB) { g_sum1[t]=0.f; g_sq1[t]=0.f; g_sum2[t]=0.f; g_sq2[t]=0.f; g_cnt[t]=0; }
        if (t < 128) g_ckv[t] = 0;
    }
    __shared__ float t[32][33];
    const float* src = (blockIdx.z == 0) ? Wq : (blockIdx.z == 1) ? Wk :
                       (blockIdx.z == 2) ? Wv : Wo;
    __half* dst = g_Wt + (size_t)blockIdx.z * DD * DD;
    int k0 = blockIdx.x * 32, n0 = blockIdx.y * 32;
    int c = threadIdx.x & 31, r0 = threadIdx.x >> 5;
    #pragma unroll
    for (int i = 0; i < 4; i++) {
        int r = r0 + 8 * i;
        t[r][c] = src[(size_t)(k0 + r) * DD + n0 + c];
    }
    __syncthreads();
    #pragma unroll
    for (int i = 0; i < 4; i++) {
        int r = r0 + 8 * i;
        dst[(size_t)(n0 + r) * DD + k0 + c] = __float2half_rn(t[c][r]);
    }
}

__global__ void k_maskstats(const float* __restrict__ Q) {
    int row = blockIdx.x;
    int t = threadIdx.x;
    float4 q = ((const float4*)(Q + (size_t)row * DD))[t];
    bool nz = (q.x != 0.f) || (q.y != 0.f) || (q.z != 0.f) || (q.w != 0.f);
    float s  = q.x + q.y + q.z + q.w;
    float s2 = q.x*q.x + q.y*q.y + q.z*q.z + q.w*q.w;
    int valid = __syncthreads_or(nz ? 1 : 0);
    #pragma unroll
    for (int o = 16; o > 0; o >>= 1) {
        s  += __shfl_xor_sync(0xffffffffu, s,  o);
        s2 += __shfl_xor_sync(0xffffffffu, s2, o);
    }
    __shared__ float rs[4], rs2[4];
    if ((t & 31) == 0) { rs[t >> 5] = s; rs2[t >> 5] = s2; }
    __syncthreads();
    if (t == 0) {
        g_mask[row] = valid;
        if (valid) {
            int b = row >> 10;
            atomicOr(&g_ckv[row >> 6], 1);
            atomicAdd(&g_cnt[b], 1);
            atomicAdd(&g_sum1[b], rs[0]+rs[1]+rs[2]+rs[3]);
            atomicAdd(&g_sq1[b],  rs2[0]+rs2[1]+rs2[2]+rs2[3]);
        }
    }
}

__global__ void k_norm(const float* __restrict__ src, __half* __restrict__ dst, int which) {
    int row = blockIdx.x;
    int t = threadIdx.x;
    int b = row >> 10;
    float cntD = (float)g_cnt[b] * (float)DD;
    float sum = which ? g_sum2[b] : g_sum1[b];
    float sq  = which ? g_sq2[b]  : g_sq1[b];
    float mean = (cntD > 0.f) ? sum / cntD : 0.f;
    float var  = (cntD > 0.f) ? sq / cntD - mean * mean : 0.f;
    if (var < 0.f) var = 0.f;
    float rstd = rsqrtf(var + EPSV);
    float sc = g_mask[row] ? rstd : 0.f;
    float mm = mean * sc;
    float4 v = ((const float4*)(src + (size_t)row * DD))[t];
    __half2 h0 = __floats2half2_rn(fmaf(v.x, sc, -mm), fmaf(v.y, sc, -mm));
    __half2 h1 = __floats2half2_rn(fmaf(v.z, sc, -mm), fmaf(v.w, sc, -mm));
    uint2 u = make_uint2(*(unsigned*)&h0, *(unsigned*)&h1);
    *(uint2*)(dst + (size_t)row * DD + t * 4) = u;
}

// ============ fp16 GEMM body: BM=128, BN=128, BK=32; 4-stage ============
struct GemmOut { float c[2][8][4]; };

__device__ __forceinline__ void gemm_body(
    const __half* __restrict__ Asrc, const __half* __restrict__ Bsrc,
    int m0, int n0, __half* smq, GemmOut& R)
{
    unsigned uA[4], uB[4];
    unsigned base = cvta_s(smq);
    #pragma unroll
    for (int i = 0; i < 4; i++) {
        uA[i] = base + (unsigned)i * 10240u;
        uB[i] = base + 40960u + (unsigned)i * 10240u;
    }

    int tid = threadIdx.x;
    int wid = tid >> 5, lane = tid & 31;
    int wm = wid >> 1, wn = wid & 1;
    int r8 = lane & 7, kh2 = (lane >> 3) & 1, kh4 = (lane >> 4) & 1;

    unsigned offA0 = (unsigned)((wm * 32 +      r8 + kh2 * 8) * 80 + kh4 * 16);
    unsigned offA1 = offA0 + 16 * 80;
    unsigned offB[4];
    #pragma unroll
    for (int nq = 0; nq < 4; nq++)
        offB[nq] = (unsigned)((wn * 64 + nq * 16 + r8 + kh4 * 8) * 80 + kh2 * 16);

    #pragma unroll
    for (int mi = 0; mi < 2; mi++)
        #pragma unroll
        for (int ni = 0; ni < 8; ni++)
            #pragma unroll
            for (int j = 0; j < 4; j++) R.c[mi][ni][j] = 0.f;

    #pragma unroll
    for (int p = 0; p < 3; p++) {
        #pragma unroll
        for (int i = 0; i < 2; i++) {
            int f = tid + 256 * i;
            int row = f >> 2, c4 = f & 3;
            CP16(uA[p] + row * 80 + c4 * 16, Asrc + (size_t)(m0 + row) * 512 + p * 32 + c4 * 8);
            CP16(uB[p] + row * 80 + c4 * 16, Bsrc + (size_t)(n0 + row) * 512 + p * 32 + c4 * 8);
        }
        CP_COMMIT();
    }

    for (int kc = 0; kc < 16; kc++) {
        CP_WAIT2();
        __syncthreads();
        if (kc + 3 < 16) {
            int j = (kc + 3) & 3;
            int k0 = (kc + 3) * 32;
            #pragma unroll
            for (int i = 0; i < 2; i++) {
                int f = tid + 256 * i;
                int row = f >> 2, c4 = f & 3;
                CP16(uA[j] + row * 80 + c4 * 16, Asrc + (size_t)(m0 + row) * 512 + k0 + c4 * 8);
                CP16(uB[j] + row * 80 + c4 * 16, Bsrc + (size_t)(n0 + row) * 512 + k0 + c4 * 8);
            }
        }
        CP_COMMIT();

        unsigned uAf = uA[kc & 3];
        unsigned uBf = uB[kc & 3];
        #pragma unroll
        for (int s = 0; s < 2; s++) {
            unsigned a[2][4], bb[8][2];
            ldsm4(uAf + offA0 + s * 32, a[0][0], a[0][1], a[0][2], a[0][3]);
            ldsm4(uAf + offA1 + s * 32, a[1][0], a[1][1], a[1][2], a[1][3]);
            #pragma unroll
            for (int nq = 0; nq < 4; nq++)
                ldsm4(uBf + offB[nq] + s * 32,
                      bb[nq*2][0], bb[nq*2][1], bb[nq*2+1][0], bb[nq*2+1][1]);
            #pragma unroll
            for (int mi = 0; mi < 2; mi++)
                #pragma unroll
                for (int ni = 0; ni < 8; ni++)
                    mma_h16(R.c[mi][ni], a[mi][0], a[mi][1], a[mi][2], a[mi][3],
                            bb[ni][0], bb[ni][1]);
        }
    }
}

// ---------------- QKV ----------------
__global__ __launch_bounds__(256, 2)
void k_qkv(const float* __restrict__ bq, const float* __restrict__ bk,
           const float* __restrict__ bv) {
    extern __shared__ __half smh[];
    int z = blockIdx.z;
    const float* bias = (z == 0) ? bq : (z == 1) ? bk : bv;
    const __half* Bsrc = g_Wt + (size_t)z * DD * DD;

    int n0 = blockIdx.x * 128, m0 = blockIdx.y * 128;
    int tid = threadIdx.x;
    int wid = tid >> 5, lane = tid & 31, g = lane >> 2, tig = lane & 3;
    int wm = wid >> 1, wn = wid & 1;

    GemmOut R;
    gemm_body(g_Qn, Bsrc, m0, n0, smh, R);

    if (z < 2) {
        __half* outp = (z == 0) ? g_Qp : g_Kp;
        #pragma unroll
        for (int mi = 0; mi < 2; mi++) {
            int r0 = m0 + wm * 32 + mi * 16 + g;
            float mk0 = g_mask[r0]     ? 1.f : 0.f;
            float mk1 = g_mask[r0 + 8] ? 1.f : 0.f;
            #pragma unroll
            for (int ni = 0; ni < 8; ni++) {
                int col = n0 + wn * 64 + ni * 8 + tig * 2;
                float b0v = bias[col], b1v = bias[col + 1];
                *(__half2*)(outp + (size_t)r0 * 512 + col) =
                    __floats2half2_rn((R.c[mi][ni][0] + b0v) * mk0,
                                      (R.c[mi][ni][1] + b1v) * mk0);
                *(__half2*)(outp + (size_t)(r0 + 8) * 512 + col) =
                    __floats2half2_rn((R.c[mi][ni][2] + b0v) * mk1,
                                      (R.c[mi][ni][3] + b1v) * mk1);
            }
        }
    } else {
        #pragma unroll
        for (int mi = 0; mi < 2; mi++) {
            int r0 = m0 + wm * 32 + mi * 16 + g;
            int bidx = r0 >> 10, s_ = r0 & 1023;
            float mk0 = g_mask[r0]     ? 1.f : 0.f;
            float mk1 = g_mask[r0 + 8] ? 1.f : 0.f;
            #pragma unroll
            for (int ni = 0; ni < 8; ni++) {
                int col = n0 + wn * 64 + ni * 8 + tig * 2;
                int h_ = col >> 6, dl = col & 63;
                float b0v = bias[col], b1v = bias[col + 1];
                __half* base = g_Vh + ((size_t)(bidx * 8 + h_) * 1024 + s_) * 64 + dl;
                *(__half2*)base = __floats2half2_rn((R.c[mi][ni][0] + b0v) * mk0,
                                                    (R.c[mi][ni][1] + b1v) * mk0);
                *(__half2*)(base + 8 * 64) = __floats2half2_rn((R.c[mi][ni][2] + b0v) * mk1,
                                                               (R.c[mi][ni][3] + b1v) * mk1);
            }
        }
    }
}

// ---------------- output GEMM ----------------
__global__ __launch_bounds__(256, 2)
void k_out(const float* __restrict__ bo, float* __restrict__ out) {
    extern __shared__ __half smh[];
    int n0 = blockIdx.x * 128, m0 = blockIdx.y * 128;
    int tid = threadIdx.x;
    int wid = tid >> 5, lane = tid & 31, g = lane >> 2, tig = lane & 3;
    int wm = wid >> 1, wn = wid & 1;

    GemmOut R;
    gemm_body(g_aon, g_Wt + (size_t)3 * DD * DD, m0, n0, smh, R);

    #pragma unroll
    for (int mi = 0; mi < 2; mi++) {
        int r0 = m0 + wm * 32 + mi * 16 + g;
        #pragma unroll
        for (int ni = 0; ni < 8; ni++) {
            int col = n0 + wn * 64 + ni * 8 + tig * 2;
            float b0v = bo[col], b1v = bo[col + 1];
            float2 a0 = *(const float2*)(g_ao + (size_t)r0 * 512 + col);
            float2 a1 = *(const float2*)(g_ao + (size_t)(r0 + 8) * 512 + col);
            float2 o0 = make_float2(a0.x + fmaxf(R.c[mi][ni][0] + b0v, 0.f),
                                    a0.y + fmaxf(R.c[mi][ni][1] + b1v, 0.f));
            float2 o1 = make_float2(a1.x + fmaxf(R.c[mi][ni][2] + b0v, 0.f),
                                    a1.y + fmaxf(R.c[mi][ni][3] + b1v, 0.f));
            *(float2*)(out + (size_t)r0 * 512 + col)       = o0;
            *(float2*)(out + (size_t)(r0 + 8) * 512 + col) = o1;
        }
    }
}

// ---------------- attention: 32 q-rows, 2 CTAs/SM, mask-aware tile skipping ----------------
__global__ __launch_bounds__(256, 2)
void k_attn(const float* __restrict__ Q, float* __restrict__ w_out) {
    extern __shared__ float sm[];
    __half* scH  = (__half*)sm;                 // 32 x 1032 fp16 exp values
    float*  kvb  = sm + 16512;                  // 4 x 2304
    __half* qsH  = (__half*)(kvb + 4 * KVW);    // 32 x 72 fp16 Q tile
    float*  red  = kvb + 4 * KVW + 1152;        // 16
    float*  part = red + 16;                    // 32*4
    float*  invS = part + 128;                  // 32
    int*    ckvS = (int*)(invS + 32);           // 16

    int tid = threadIdx.x;
    int wid = tid >> 5, lane = tid & 31, g = lane >> 2, tig = lane & 3;
    int r8 = lane & 7, kh2 = (lane >> 3) & 1, kh4 = (lane >> 4) & 1;
    int bh = blockIdx.y, b = bh >> 3, h = bh & 7;
    int q0 = blockIdx.x * 32;
    size_t baseQ = ((size_t)b * SS + q0) * DD + h * HD;
    size_t baseK = ((size_t)b * SS) * DD + h * HD;
    const __half* Vh = g_Vh + (size_t)bh * SS * HD;
    const int bS = b * SS;

    // ---- fully-invalid q-block early-out: w rows = 0, attn_out = Q ----
    {
        int v = (tid < 32) ? g_mask[bS + q0 + tid] : 0;
        if (!__syncthreads_or(v)) {
            float4 z = make_float4(0.f, 0.f, 0.f, 0.f);
            size_t wbase = ((size_t)bh * SS + q0) * SS;
            #pragma unroll
            for (int i = 0; i < 32; i++) {
                int f = tid + 256 * i;
                int r = f >> 8, c4 = f & 255;
                *(float4*)(w_out + wbase + (size_t)r * SS + c4 * 4) = z;
            }
            #pragma unroll
            for (int i = 0; i < 2; i++) {
                int f = tid + 256 * i;
                int r = f >> 4, c4 = f & 15;
                size_t gaddr = baseQ + (size_t)r * DD + c4 * 4;
                *(float4*)(g_ao + gaddr) = *(const float4*)(Q + gaddr);
            }
            return;
        }
    }

    unsigned uKV[4];
    #pragma unroll
    for (int i = 0; i < 4; i++) uKV[i] = cvta_s(kvb + i * KVW);
    unsigned uQS = cvta_s(qsH), uSC = cvta_s(scH);

    // K prologue: chunks 0..2
    #pragma unroll
    for (int p = 0; p < 3; p++) {
        #pragma unroll
        for (int i = 0; i < 2; i++) {
            int f = tid + 256 * i;
            int row = f >> 3, c8 = f & 7;
            CP16(uKV[p] + row * 144 + c8 * 16,
                 g_Kp + baseK + (size_t)(p * 64 + row) * 512 + c8 * 8);
        }
        CP_COMMIT();
    }

    // q tile + key-chunk validity flags
    {
        int r = tid >> 3, c8 = tid & 7;
        *(uint4*)(qsH + r * 72 + c8 * 8) =
            *(const uint4*)(g_Qp + baseQ + (size_t)r * 512 + c8 * 8);
    }
    if (tid < 16) ckvS[tid] = g_ckv[b * 16 + tid];
    __syncthreads();

    // warp layout: 8 warps = 2 m-groups x 4 n-slots
    int nslot = wid & 3, mw = wid >> 2;
    unsigned areg[4][4];
    {
        unsigned base = uQS + (unsigned)((mw * 16 + r8 + kh2 * 8) * 144 + kh4 * 16);
        #pragma unroll
        for (int ks = 0; ks < 4; ks++)
            ldsm4(base + ks * 32, areg[ks][0], areg[ks][1], areg[ks][2], areg[ks][3]);
    }

    // ---- scores: 16 chunks of 64 keys; dead chunks -> zero panel ----
    float rs0 = 0.f, rs1 = 0.f;
    unsigned offKB = (unsigned)((nslot * 16 + r8 + kh4 * 8) * 144 + kh2 * 16);
    for (int kt = 0; kt < 16; kt++) {
        CP_WAIT2();
        __syncthreads();
        if (kt + 3 < 16) {
            unsigned nxt = uKV[(kt + 3) & 3];
            #pragma unroll
            for (int i = 0; i < 2; i++) {
                int f = tid + 256 * i;
                int row = f >> 3, c8 = f & 7;
                CP16(nxt + row * 144 + c8 * 16,
                     g_Kp + baseK + (size_t)((kt + 3) * 64 + row) * 512 + c8 * 8);
            }
        }
        CP_COMMIT();

        int r = mw * 16 + g;
        if (ckvS[kt]) {
            unsigned uKVf = uKV[kt & 3];
            float cc[2][4];
            #pragma unroll
            for (int nf = 0; nf < 2; nf++)
                #pragma unroll
                for (int j = 0; j < 4; j++) cc[nf][j] = 0.f;

            #pragma unroll
            for (int ks = 0; ks < 4; ks++) {
                unsigned b0, b1, b2, b3;
                ldsm4(uKVf + offKB + ks * 32, b0, b1, b2, b3);
                mma_h16(cc[0], areg[ks][0], areg[ks][1], areg[ks][2], areg[ks][3], b0, b1);
                mma_h16(cc[1], areg[ks][0], areg[ks][1], areg[ks][2], areg[ks][3], b2, b3);
            }
            #pragma unroll
            for (int nf = 0; nf < 2; nf++) {
                int gc = kt * 64 + nslot * 16 + nf * 8 + tig * 2;
                bool k0v = g_mask[bS + gc] != 0;
                bool k1v = g_mask[bS + gc + 1] != 0;
                float p0 = k0v ? __expf(cc[nf][0] * 0.125f) : 0.f;
                float p1 = k1v ? __expf(cc[nf][1] * 0.125f) : 0.f;
                float p2 = k0v ? __expf(cc[nf][2] * 0.125f) : 0.f;
                float p3 = k1v ? __expf(cc[nf][3] * 0.125f) : 0.f;
                rs0 += p0 + p1;
                rs1 += p2 + p3;
                *(__half2*)&scH[r * SCPH + gc]       = __floats2half2_rn(p0, p1);
                *(__half2*)&scH[(r + 8) * SCPH + gc] = __floats2half2_rn(p2, p3);
            }
        } else {
            __half2 z = __floats2half2_rn(0.f, 0.f);
            #pragma unroll
            for (int nf = 0; nf < 2; nf++) {
                int gc = kt * 64 + nslot * 16 + nf * 8 + tig * 2;
                *(__half2*)&scH[r * SCPH + gc]       = z;
                *(__half2*)&scH[(r + 8) * SCPH + gc] = z;
            }
        }
    }
    rs0 += __shfl_xor_sync(0xffffffffu, rs0, 1);
    rs0 += __shfl_xor_sync(0xffffffffu, rs0, 2);
    rs1 += __shfl_xor_sync(0xffffffffu, rs1, 1);
    rs1 += __shfl_xor_sync(0xffffffffu, rs1, 2);
    if (tig == 0) {
        part[(mw * 16 + g) * 4 + nslot]     = rs0;
        part[(mw * 16 + g + 8) * 4 + nslot] = rs1;
    }

    // V prologue: chunks 0..2
    #pragma unroll
    for (int p = 0; p < 3; p++) {
        #pragma unroll
        for (int i = 0; i < 2; i++) {
            int f = tid + 256 * i;
            int row = f >> 3, c8 = f & 7;
            CP16(uKV[p] + row * 144 + c8 * 16,
                 Vh + ((size_t)(p * 64 + row)) * 64 + c8 * 8);
        }
        CP_COMMIT();
    }
    __syncthreads();   // panel + part visible

    // ---- w pass: w = fp16(p) * inv; compute invS ----
    {
        int row = tid >> 3, l = tid & 7;
        const float* pr = part + row * 4;
        float sum = pr[0] + pr[1] + pr[2] + pr[3];
        float inv = g_mask[bS + q0 + row] ? (1.0f / sum) : 0.f;
        if (l == 0) invS[row] = inv;
        float* wrow = w_out + ((size_t)bh * SS + q0 + row) * SS;
        const char* prow = (const char*)scH + row * (SCPH * 2);
        #pragma unroll
        for (int j = 0; j < 16; j++) {
            int e = l + 8 * j;
            uint4 u = *(const uint4*)(prow + e * 16);
            const __half2* hp = (const __half2*)&u;
            float2 f0 = __half22float2(hp[0]);
            float2 f1 = __half22float2(hp[1]);
            float2 f2 = __half22float2(hp[2]);
            float2 f3 = __half22float2(hp[3]);
            float4 o0 = make_float4(f0.x * inv, f0.y * inv, f1.x * inv, f1.y * inv);
            float4 o1 = make_float4(f2.x * inv, f2.y * inv, f3.x * inv, f3.y * inv);
            *(float4*)(wrow + e * 8)     = o0;
            *(float4*)(wrow + e * 8 + 4) = o1;
        }
    }

    // ---- attnV: 16 chunks; dead chunks skip mma ----
    int nsl2 = wid & 3, mw2 = wid >> 2;
    unsigned paA = uSC + (unsigned)((mw2 * 16 + r8 + kh2 * 8) * (SCPH * 2) + kh4 * 16);
    unsigned pbN = (unsigned)((nsl2 * 16 + kh4 * 8) * 2);
    int rowVk = r8 + kh2 * 8;

    float acc[2][4];
    #pragma unroll
    for (int nf = 0; nf < 2; nf++)
        #pragma unroll
        for (int j = 0; j < 4; j++) acc[nf][j] = 0.f;

    for (int vt = 0; vt < 16; vt++) {
        CP_WAIT2();
        __syncthreads();
        if (vt + 3 < 16) {
            unsigned nxt = uKV[(vt + 3) & 3];
            #pragma unroll
            for (int i = 0; i < 2; i++) {
                int f = tid + 256 * i;
                int row = f >> 3, c8 = f & 7;
                CP16(nxt + row * 144 + c8 * 16,
                     Vh + ((size_t)((vt + 3) * 64 + row)) * 64 + c8 * 8);
            }
        }
        CP_COMMIT();

        if (ckvS[vt]) {
            unsigned uKVf = uKV[vt & 3];
            #pragma unroll
            for (int ks = 0; ks < 4; ks++) {
                unsigned a0, a1, a2, a3, b0, b1, b2, b3;
                ldsm4(paA + vt * 128 + ks * 32, a0, a1, a2, a3);
                ldsm4t(uKVf + (ks * 16 + rowVk) * 144 + pbN, b0, b1, b2, b3);
                mma_h16(acc[0], a0, a1, a2, a3, b0, b1);
                mma_h16(acc[1], a0, a1, a2, a3, b2, b3);
            }
        }
    }
    __syncthreads();

    // ---- store scaled attn into kvb, then epilogue ----
    {
        float* at = kvb;
        int r = mw2 * 16 + g;
        float i0 = invS[r], i1 = invS[r + 8];
        #pragma unroll
        for (int nf = 0; nf < 2; nf++) {
            int col = nsl2 * 16 + nf * 8 + tig * 2;
            *(float2*)&at[r * 68 + col]       = make_float2(acc[nf][0] * i0, acc[nf][1] * i0);
            *(float2*)&at[(r + 8) * 68 + col] = make_float2(acc[nf][2] * i1, acc[nf][3] * i1);
        }
    }
    __syncthreads();

    // ---- epilogue: attn_out = attn + Q; stats2 ----
    {
        float* at = kvb;
        float t1 = 0.f, t2 = 0.f;
        #pragma unroll
        for (int i = 0; i < 2; i++) {
            int f = tid + 256 * i;
            int r = f >> 4, c4 = f & 15;
            float4 a = *(const float4*)&at[r * 68 + c4 * 4];
            size_t gaddr = baseQ + (size_t)r * DD + c4 * 4;
            float4 q4 = *(const float4*)(Q + gaddr);
            float4 o = make_float4(a.x + q4.x, a.y + q4.y, a.z + q4.z, a.w + q4.w);
            *(float4*)(g_ao + gaddr) = o;
            t1 += o.x + o.y + o.z + o.w;
            t2 += o.x*o.x + o.y*o.y + o.z*o.z + o.w*o.w;
        }
        #pragma unroll
        for (int off = 16; off > 0; off >>= 1) {
            t1 += __shfl_xor_sync(0xffffffffu, t1, off);
            t2 += __shfl_xor_sync(0xffffffffu, t2, off);
        }
        if (lane == 0) { red[wid] = t1; red[8 + wid] = t2; }
    }
    __syncthreads();
    if (tid == 0) {
        float S1 = 0.f, S2 = 0.f;
        #pragma unroll
        for (int i = 0; i < 8; i++) { S1 += red[i]; S2 += red[8 + i]; }
        atomicAdd(&g_sum2[b], S1);
        atomicAdd(&g_sq2[b], S2);
    }
}

// ---------------- launch ----------------
extern "C" void kernel_launch(void* const* d_in, const int* in_sizes, int n_in,
                              void* d_out, int out_size) {
    const float* Q  = (const float*)d_in[0];
    const float* Wq = (const float*)d_in[1];
    const float* bq = (const float*)d_in[2];
    const float* Wk = (const float*)d_in[3];
    const float* bk = (const float*)d_in[4];
    const float* Wv = (const float*)d_in[5];
    const float* bv = (const float*)d_in[6];
    const float* Wo = (const float*)d_in[7];
    const float* bo = (const float*)d_in[8];

    float* out = (float*)d_out;
    float* w   = out + (size_t)BB * SS * DD;

    float*  g_ao_ptr;  cudaGetSymbolAddress((void**)&g_ao_ptr,  g_ao);
    __half* g_Qn_ptr;  cudaGetSymbolAddress((void**)&g_Qn_ptr,  g_Qn);
    __half* g_aon_ptr; cudaGetSymbolAddress((void**)&g_aon_ptr, g_aon);

    const int GEMM_SMEM = 8 * 10240;
    const int ATTN_SMEM = (16512 + 4 * KVW + 1152 + 16 + 128 + 32 + 16) * 4;  // 108224 B
    cudaFuncSetAttribute(k_qkv,  cudaFuncAttributeMaxDynamicSharedMemorySize, GEMM_SMEM);
    cudaFuncSetAttribute(k_out,  cudaFuncAttributeMaxDynamicSharedMemorySize, GEMM_SMEM);
    cudaFuncSetAttribute(k_attn, cudaFuncAttributeMaxDynamicSharedMemorySize, ATTN_SMEM);

    k_cvtW<<<dim3(16, 16, 4), 256>>>(Wq, Wk, Wv, Wo);
    k_maskstats<<<NROWS, 128>>>(Q);
    k_norm<<<NROWS, 128>>>(Q, g_Qn_ptr, 0);
    k_qkv<<<dim3(4, 64, 3), 256, GEMM_SMEM>>>(bq, bk, bv);
    k_attn<<<dim3(32, 64), 256, ATTN_SMEM>>>(Q, w);
    k_norm<<<NROWS, 128>>>(g_ao_ptr, g_aon_ptr, 1);
    k_out<<<dim3(4, 64), 256, GEMM_SMEM>>>(bo, out);
}